// round 1
// baseline (speedup 1.0000x reference)
#include <cuda_runtime.h>

// Problem constants (fixed shapes from the reference setup)
#define Bb 2
#define Ss 2304
#define Hh 24
#define HD 128
#define DM 3072           // HEADS*HEAD_DIM
#define N3 9216           // 3*DM
#define KD 3072           // GEMM K
#define MR (Bb*Ss)        // 4608 GEMM rows

// Scratch (static device globals: allocation-guard safe)
__device__ float g_qkv[(size_t)MR * N3];              // 170 MB
__device__ float g_q[(size_t)Bb * Hh * Ss * HD];      // 56.6 MB
__device__ float g_k[(size_t)Bb * Hh * Ss * HD];
__device__ float g_v[(size_t)Bb * Hh * Ss * HD];

// ---------- packed f32x2 helpers (Blackwell FFMA2) ----------
__device__ __forceinline__ unsigned long long pk2(float x) {
    unsigned long long r;
    asm("mov.b64 %0, {%1, %1};" : "=l"(r) : "f"(x));
    return r;
}
__device__ __forceinline__ unsigned long long f2fma(unsigned long long a,
                                                    unsigned long long b,
                                                    unsigned long long c) {
    unsigned long long d;
    asm("fma.rn.f32x2 %0, %1, %2, %3;" : "=l"(d) : "l"(a), "l"(b), "l"(c));
    return d;
}
__device__ __forceinline__ unsigned long long f2mul(unsigned long long a,
                                                    unsigned long long b) {
    unsigned long long d;
    asm("mul.rn.f32x2 %0, %1, %2;" : "=l"(d) : "l"(a), "l"(b));
    return d;
}
__device__ __forceinline__ float2 upk(unsigned long long a) {
    float lo, hi;
    asm("mov.b64 {%0, %1}, %2;" : "=f"(lo), "=f"(hi) : "l"(a));
    return make_float2(lo, hi);
}

// =====================================================================
// Kernel 1: QKV GEMM  C[m][n] = sum_k A[m][k]*W[n][k] + bias[n]
// BM=BN=128, BK=8, 256 threads, 8x8 microtile via f32x2
// =====================================================================
__global__ __launch_bounds__(256) void qkv_gemm(const float* __restrict__ A,
                                                const float* __restrict__ W,
                                                const float* __restrict__ bias) {
    __shared__ float As[8][132];
    __shared__ float Bs[8][132];
    int t = threadIdx.x;
    int tx = t & 15, ty = t >> 4;
    int n0 = blockIdx.x * 128, m0 = blockIdx.y * 128;

    int lrow = t >> 1;
    int lk = (t & 1) * 4;
    const float* Ap = A + (size_t)(m0 + lrow) * KD + lk;
    const float* Wp = W + (size_t)(n0 + lrow) * KD + lk;

    unsigned long long acc[8][4];
#pragma unroll
    for (int i = 0; i < 8; i++)
#pragma unroll
        for (int j = 0; j < 4; j++) acc[i][j] = 0ull;

    for (int k0 = 0; k0 < KD; k0 += 8) {
        float4 a4 = *(const float4*)(Ap + k0);
        float4 w4 = *(const float4*)(Wp + k0);
        As[lk + 0][lrow] = a4.x; As[lk + 1][lrow] = a4.y;
        As[lk + 2][lrow] = a4.z; As[lk + 3][lrow] = a4.w;
        Bs[lk + 0][lrow] = w4.x; Bs[lk + 1][lrow] = w4.y;
        Bs[lk + 2][lrow] = w4.z; Bs[lk + 3][lrow] = w4.w;
        __syncthreads();
#pragma unroll
        for (int kk = 0; kk < 8; kk++) {
            float4 alo = *(const float4*)(&As[kk][ty * 8]);
            float4 ahi = *(const float4*)(&As[kk][ty * 8 + 4]);
            ulonglong2 b0 = *(const ulonglong2*)(&Bs[kk][tx * 4]);
            ulonglong2 b1 = *(const ulonglong2*)(&Bs[kk][64 + tx * 4]);
            float ar[8] = {alo.x, alo.y, alo.z, alo.w, ahi.x, ahi.y, ahi.z, ahi.w};
#pragma unroll
            for (int i = 0; i < 8; i++) {
                unsigned long long a2 = pk2(ar[i]);
                acc[i][0] = f2fma(a2, b0.x, acc[i][0]);
                acc[i][1] = f2fma(a2, b0.y, acc[i][1]);
                acc[i][2] = f2fma(a2, b1.x, acc[i][2]);
                acc[i][3] = f2fma(a2, b1.y, acc[i][3]);
            }
        }
        __syncthreads();
    }

    float4 bia0 = *(const float4*)(bias + n0 + tx * 4);
    float4 bia1 = *(const float4*)(bias + n0 + 64 + tx * 4);
#pragma unroll
    for (int i = 0; i < 8; i++) {
        int m = m0 + ty * 8 + i;
        float2 c0 = upk(acc[i][0]), c1 = upk(acc[i][1]);
        float2 c2 = upk(acc[i][2]), c3 = upk(acc[i][3]);
        float4 o0 = make_float4(c0.x + bia0.x, c0.y + bia0.y, c1.x + bia0.z, c1.y + bia0.w);
        float4 o1 = make_float4(c2.x + bia1.x, c2.y + bia1.y, c3.x + bia1.z, c3.y + bia1.w);
        *(float4*)(g_qkv + (size_t)m * N3 + n0 + tx * 4) = o0;
        *(float4*)(g_qkv + (size_t)m * N3 + n0 + 64 + tx * 4) = o1;
    }
}

// =====================================================================
// Kernel 2: per-head RMSNorm (+ interleaved RoPE for s >= T) and
// transpose to [b][h][s][d]. One warp per (b,s,h,which) vector.
// which: 0=q (norm+rope), 1=k (norm+rope), 2=v (copy)
// =====================================================================
__global__ __launch_bounds__(256) void norm_rope(const float* __restrict__ wq,
                                                 const float* __restrict__ wk,
                                                 const float* __restrict__ cs,
                                                 const float* __restrict__ sn,
                                                 const int* __restrict__ tsl) {
    int warp = (blockIdx.x * 256 + threadIdx.x) >> 5;  // 0..331775
    int lane = threadIdx.x & 31;
    int which = warp % 3;
    int rem = warp / 3;
    int h = rem % Hh;
    int bs = rem / Hh;            // b*S + s
    int s = bs % Ss;
    int b = bs / Ss;

    const float4* src = (const float4*)(g_qkv + (size_t)bs * N3 + which * DM + h * HD);
    float4 x = src[lane];

    if (which < 2) {
        float ssq = x.x * x.x + x.y * x.y + x.z * x.z + x.w * x.w;
#pragma unroll
        for (int o = 16; o > 0; o >>= 1) ssq += __shfl_xor_sync(0xffffffffu, ssq, o);
        float r = rsqrtf(ssq * (1.0f / 128.0f) + 1e-6f);
        const float* w = (which == 0) ? wq : wk;
        float4 wv = ((const float4*)w)[lane];
        x.x *= r * wv.x; x.y *= r * wv.y; x.z *= r * wv.z; x.w *= r * wv.w;
        int T = tsl[0];
        if (s >= T) {
            int p = s - T;
            float c0 = cs[p * 64 + lane * 2],     s0 = sn[p * 64 + lane * 2];
            float c1 = cs[p * 64 + lane * 2 + 1], s1 = sn[p * 64 + lane * 2 + 1];
            float4 o;
            o.x = x.x * c0 - x.y * s0;
            o.y = x.y * c0 + x.x * s0;
            o.z = x.z * c1 - x.w * s1;
            o.w = x.w * c1 + x.z * s1;
            x = o;
        }
    }
    float* dst = (which == 0) ? g_q : (which == 1) ? g_k : g_v;
    ((float4*)(dst + ((size_t)(b * Hh + h) * Ss + s) * HD))[lane] = x;
}

// =====================================================================
// Kernel 3: flash attention, 64x64 tiles, fp32, online softmax.
// grid (S/64, H, B), 256 threads (16x16 microtile grid).
// =====================================================================
#define BM 64
#define BN 64
#define QSТ 132
#define QST 132
#define PST 68
#define ATT_SMEM ((3 * BM * QST + BM * PST + 3 * BM) * 4)

extern __shared__ float smf[];

__global__ __launch_bounds__(256) void attn(float* __restrict__ out) {
    float* Qs = smf;                   // [64][132]
    float* Ks = Qs + BM * QST;         // [64][132]
    float* Vs = Ks + BN * QST;         // [64][132]
    float* Pp = Vs + BN * QST;         // [64][68]
    float* m_s = Pp + BM * PST;
    float* l_s = m_s + BM;
    float* al_s = l_s + BM;

    int t = threadIdx.x;
    int tx = t & 15, ty = t >> 4;
    int q0 = blockIdx.x * BM;
    int h = blockIdx.y, b = blockIdx.z;

    const float* qp  = g_q + ((size_t)(b * Hh + h) * Ss + q0) * HD;
    const float* kpb = g_k + ((size_t)(b * Hh + h) * Ss) * HD;
    const float* vpb = g_v + ((size_t)(b * Hh + h) * Ss) * HD;
    const float scale = 0.08838834764831845f;  // 1/sqrt(128)

    // Load Q tile (pre-scaled)
#pragma unroll
    for (int it = 0; it < 8; it++) {
        int idx = t + it * 256;        // 0..2047
        int r = idx >> 5, d4 = idx & 31;
        float4 q = *(const float4*)(qp + r * HD + d4 * 4);
        q.x *= scale; q.y *= scale; q.z *= scale; q.w *= scale;
        *(float4*)(Qs + r * QST + d4 * 4) = q;
    }
    if (t < BM) { m_s[t] = -1e30f; l_s[t] = 0.0f; }

    unsigned long long acc[4][4];
#pragma unroll
    for (int i = 0; i < 4; i++)
#pragma unroll
        for (int j = 0; j < 4; j++) acc[i][j] = 0ull;

    int r0 = ty * 4, c0 = tx * 4;

    for (int kt = 0; kt < Ss; kt += BN) {
        __syncthreads();  // previous PV done before overwriting K/V/P
#pragma unroll
        for (int it = 0; it < 8; it++) {
            int idx = t + it * 256;
            int r = idx >> 5, d4 = idx & 31;
            *(float4*)(Ks + r * QST + d4 * 4) = *(const float4*)(kpb + (size_t)(kt + r) * HD + d4 * 4);
            *(float4*)(Vs + r * QST + d4 * 4) = *(const float4*)(vpb + (size_t)(kt + r) * HD + d4 * 4);
        }
        __syncthreads();

        // ---- scores: 4x4 per thread, f32x2 packed over d-pairs ----
        {
            unsigned long long sc[4][4];
#pragma unroll
            for (int i = 0; i < 4; i++)
#pragma unroll
                for (int j = 0; j < 4; j++) sc[i][j] = 0ull;
#pragma unroll 4
            for (int d4 = 0; d4 < 32; d4++) {
                ulonglong2 qv[4], kv[4];
#pragma unroll
                for (int i = 0; i < 4; i++)
                    qv[i] = *(const ulonglong2*)(Qs + (r0 + i) * QST + d4 * 4);
#pragma unroll
                for (int j = 0; j < 4; j++)
                    kv[j] = *(const ulonglong2*)(Ks + (c0 + j) * QST + d4 * 4);
#pragma unroll
                for (int i = 0; i < 4; i++)
#pragma unroll
                    for (int j = 0; j < 4; j++) {
                        sc[i][j] = f2fma(qv[i].x, kv[j].x, sc[i][j]);
                        sc[i][j] = f2fma(qv[i].y, kv[j].y, sc[i][j]);
                    }
            }
#pragma unroll
            for (int i = 0; i < 4; i++)
#pragma unroll
                for (int j = 0; j < 4; j++) {
                    float2 v = upk(sc[i][j]);
                    Pp[(r0 + i) * PST + c0 + j] = v.x + v.y;
                }
        }
        __syncthreads();

        // ---- online softmax: 4 threads per row ----
        {
            int row = t >> 2, part = t & 3;
            float* prow = Pp + row * PST + part * 16;
            float mx = -1e30f;
#pragma unroll
            for (int c = 0; c < 16; c++) mx = fmaxf(mx, prow[c]);
            mx = fmaxf(mx, __shfl_xor_sync(0xffffffffu, mx, 1));
            mx = fmaxf(mx, __shfl_xor_sync(0xffffffffu, mx, 2));
            float mprev = m_s[row];
            float mnew = fmaxf(mprev, mx);
            float alpha = __expf(mprev - mnew);
            float sum = 0.0f;
#pragma unroll
            for (int c = 0; c < 16; c++) {
                float p = __expf(prow[c] - mnew);
                prow[c] = p;
                sum += p;
            }
            sum += __shfl_xor_sync(0xffffffffu, sum, 1);
            sum += __shfl_xor_sync(0xffffffffu, sum, 2);
            if (part == 0) {
                m_s[row] = mnew;
                l_s[row] = l_s[row] * alpha + sum;
                al_s[row] = alpha;
            }
        }
        __syncthreads();

        // ---- rescale accumulators, then PV accumulate ----
        {
#pragma unroll
            for (int i = 0; i < 4; i++) {
                unsigned long long a2 = pk2(al_s[r0 + i]);
#pragma unroll
                for (int j = 0; j < 4; j++) acc[i][j] = f2mul(acc[i][j], a2);
            }
#pragma unroll 4
            for (int c = 0; c < BN; c++) {
                ulonglong2 va = *(const ulonglong2*)(Vs + c * QST + tx * 4);
                ulonglong2 vb2 = *(const ulonglong2*)(Vs + c * QST + 64 + tx * 4);
#pragma unroll
                for (int i = 0; i < 4; i++) {
                    unsigned long long p2 = pk2(Pp[(r0 + i) * PST + c]);
                    acc[i][0] = f2fma(p2, va.x, acc[i][0]);
                    acc[i][1] = f2fma(p2, va.y, acc[i][1]);
                    acc[i][2] = f2fma(p2, vb2.x, acc[i][2]);
                    acc[i][3] = f2fma(p2, vb2.y, acc[i][3]);
                }
            }
        }
    }

    // ---- epilogue: divide by l, write output [b][s][h*128+d] ----
#pragma unroll
    for (int i = 0; i < 4; i++) {
        float inv = 1.0f / l_s[r0 + i];
        float2 c0f = upk(acc[i][0]), c1f = upk(acc[i][1]);
        float2 c2f = upk(acc[i][2]), c3f = upk(acc[i][3]);
        float4 o0 = make_float4(c0f.x * inv, c0f.y * inv, c1f.x * inv, c1f.y * inv);
        float4 o1 = make_float4(c2f.x * inv, c2f.y * inv, c3f.x * inv, c3f.y * inv);
        size_t obase = ((size_t)b * Ss + q0 + r0 + i) * DM + h * HD;
        *(float4*)(out + obase + tx * 4) = o0;
        *(float4*)(out + obase + 64 + tx * 4) = o1;
    }
}

// =====================================================================
extern "C" void kernel_launch(void* const* d_in, const int* in_sizes, int n_in,
                              void* d_out, int out_size) {
    const float* hs  = (const float*)d_in[0];
    const float* w   = (const float*)d_in[1];
    const float* bqv = (const float*)d_in[2];
    const float* wqn = (const float*)d_in[3];
    const float* wkn = (const float*)d_in[4];
    const float* cs  = (const float*)d_in[5];
    const float* sn  = (const float*)d_in[6];
    const int*   tsl = (const int*)d_in[7];
    float* out = (float*)d_out;

    // QKV projection
    qkv_gemm<<<dim3(N3 / 128, MR / 128), 256>>>(hs, w, bqv);

    // RMSNorm + RoPE + transpose to [b][h][s][d]
    int total_warps = Bb * Ss * Hh * 3;           // 331776
    norm_rope<<<total_warps / 8, 256>>>(wqn, wkn, cs, sn, tsl);

    // Flash attention
    cudaFuncSetAttribute(attn, cudaFuncAttributeMaxDynamicSharedMemorySize, ATT_SMEM);
    attn<<<dim3(Ss / BM, Hh, Bb), 256, ATT_SMEM>>>(out);
}

// round 3
// speedup vs baseline: 1.5366x; 1.5366x over previous
#include <cuda_runtime.h>
#include <cuda_bf16.h>
#include <cstdint>

// Arch guard: tcgen05 only exists in the arch-specific (sm_103a) pass.
#if defined(__CUDA_ARCH_FEAT_SM103_ALL) || defined(__CUDA_ARCH_FEAT_SM100_ALL) || \
    (defined(__CUDA_ARCH_SPECIFIC__) && (__CUDA_ARCH_SPECIFIC__ >= 1000))
#define HAS_TCGEN05 1
#else
#define HAS_TCGEN05 0
#endif

// Problem constants (fixed shapes from the reference setup)
#define Bb 2
#define Ss 2304
#define Hh 24
#define HD 128
#define DM 3072           // HEADS*HEAD_DIM
#define N3 9216           // 3*DM
#define KD 3072           // GEMM K
#define MR (Bb*Ss)        // 4608 GEMM rows

// Scratch (static device globals: allocation-guard safe)
__device__ float g_qkv[(size_t)MR * N3];              // 170 MB
__device__ float g_q[(size_t)Bb * Hh * Ss * HD];      // 56.6 MB
__device__ float g_k[(size_t)Bb * Hh * Ss * HD];
__device__ float g_v[(size_t)Bb * Hh * Ss * HD];
// bf16 split operands
__device__ alignas(128) __nv_bfloat16 g_Ah[(size_t)MR * KD];
__device__ alignas(128) __nv_bfloat16 g_Al[(size_t)MR * KD];
__device__ alignas(128) __nv_bfloat16 g_Wh[(size_t)N3 * KD];
__device__ alignas(128) __nv_bfloat16 g_Wl[(size_t)N3 * KD];

// ---------- packed f32x2 helpers (Blackwell FFMA2) ----------
__device__ __forceinline__ unsigned long long pk2(float x) {
    unsigned long long r;
    asm("mov.b64 %0, {%1, %1};" : "=l"(r) : "f"(x));
    return r;
}
__device__ __forceinline__ unsigned long long f2fma(unsigned long long a,
                                                    unsigned long long b,
                                                    unsigned long long c) {
    unsigned long long d;
    asm("fma.rn.f32x2 %0, %1, %2, %3;" : "=l"(d) : "l"(a), "l"(b), "l"(c));
    return d;
}
__device__ __forceinline__ unsigned long long f2mul(unsigned long long a,
                                                    unsigned long long b) {
    unsigned long long d;
    asm("mul.rn.f32x2 %0, %1, %2;" : "=l"(d) : "l"(a), "l"(b));
    return d;
}
__device__ __forceinline__ float2 upk(unsigned long long a) {
    float lo, hi;
    asm("mov.b64 {%0, %1}, %2;" : "=f"(lo), "=f"(hi) : "l"(a));
    return make_float2(lo, hi);
}

// ---------- tcgen05 / mbarrier helpers ----------
__device__ __forceinline__ uint32_t smem_u32(const void* p) {
    uint32_t a;
    asm("{ .reg .u64 t; cvta.to.shared.u64 t, %1; cvt.u32.u64 %0, t; }" : "=r"(a) : "l"(p));
    return a;
}
#define SWZ(o) ((o) ^ (((o) >> 3) & 0x70))
#define MK_DESC(addr) ((uint64_t(2) << 61) | (uint64_t(1) << 46) | (uint64_t(64) << 32) | \
                       (uint64_t(1) << 16) | ((uint64_t)((addr) >> 4) & 0x3FFF))

#define MBAR_INIT(m, c) asm volatile("mbarrier.init.shared.b64 [%0], %1;" :: "r"(m), "r"(c) : "memory")
#define MBAR_WAIT(m, p) asm volatile( \
    "{\n\t.reg .pred P1;\n\t" \
    "WL%=:\n\tmbarrier.try_wait.parity.acquire.cta.shared::cta.b64 P1, [%0], %1, 0x989680;\n\t" \
    "@P1 bra.uni WD%=;\n\tbra.uni WL%=;\n\tWD%=:\n\t}" \
    :: "r"(m), "r"(p) : "memory")

#if HAS_TCGEN05
__device__ __forceinline__ void mma_bf16_ss(uint32_t d, uint64_t a, uint64_t b,
                                            uint32_t idesc, uint32_t en) {
    asm volatile(
        "{\n\t.reg .pred p;\n\tsetp.ne.u32 p, %4, 0;\n\t"
        "tcgen05.mma.cta_group::1.kind::f16 [%0], %1, %2, %3, {%5, %5, %5, %5}, p;\n\t}"
        :: "r"(d), "l"(a), "l"(b), "r"(idesc), "r"(en), "r"(0u) : "memory");
}
#define TC_COMMIT(m) asm volatile( \
    "tcgen05.commit.cta_group::1.mbarrier::arrive::one.shared::cluster.b64 [%0];" :: "r"(m) : "memory")
#define TC_ALLOC(sm, n)  asm volatile("tcgen05.alloc.cta_group::1.sync.aligned.shared::cta.b32 [%0], %1;" :: "r"(sm), "r"(n) : "memory")
#define TC_DEALLOC(t, n) asm volatile("tcgen05.dealloc.cta_group::1.sync.aligned.b32 %0, %1;" :: "r"(t), "r"(n))
#define TC_FENCE_AFTER() asm volatile("tcgen05.fence::after_thread_sync;" ::: "memory")
#define TC_WAIT_LD()     asm volatile("tcgen05.wait::ld.sync.aligned;" ::: "memory")
#define FENCE_ASYNC()    asm volatile("fence.proxy.async.shared::cta;" ::: "memory")

#define TC_LD_X32(r, a) asm volatile( \
    "tcgen05.ld.sync.aligned.32x32b.x32.b32 " \
    "{%0, %1, %2, %3, %4, %5, %6, %7, %8, %9, %10, %11, %12, %13, %14, %15, " \
    "%16, %17, %18, %19, %20, %21, %22, %23, %24, %25, %26, %27, %28, %29, %30, %31}, [%32];" \
    : "=r"((r)[0]), "=r"((r)[1]), "=r"((r)[2]), "=r"((r)[3]), "=r"((r)[4]), "=r"((r)[5]), \
      "=r"((r)[6]), "=r"((r)[7]), "=r"((r)[8]), "=r"((r)[9]), "=r"((r)[10]), "=r"((r)[11]), \
      "=r"((r)[12]), "=r"((r)[13]), "=r"((r)[14]), "=r"((r)[15]), "=r"((r)[16]), "=r"((r)[17]), \
      "=r"((r)[18]), "=r"((r)[19]), "=r"((r)[20]), "=r"((r)[21]), "=r"((r)[22]), "=r"((r)[23]), \
      "=r"((r)[24]), "=r"((r)[25]), "=r"((r)[26]), "=r"((r)[27]), "=r"((r)[28]), "=r"((r)[29]), \
      "=r"((r)[30]), "=r"((r)[31]) : "r"(a))
#endif  // HAS_TCGEN05

// =====================================================================
// Kernel 0: fp32 -> (hi, lo) bf16 split
// =====================================================================
__global__ __launch_bounds__(256) void cvt_split(const float* __restrict__ x,
                                                 __nv_bfloat16* __restrict__ hi,
                                                 __nv_bfloat16* __restrict__ lo,
                                                 int n4) {
    int i = blockIdx.x * 256 + threadIdx.x;
    if (i >= n4) return;
    float4 v = ((const float4*)x)[i];
    __nv_bfloat16 h0 = __float2bfloat16(v.x), h1 = __float2bfloat16(v.y);
    __nv_bfloat16 h2 = __float2bfloat16(v.z), h3 = __float2bfloat16(v.w);
    __nv_bfloat16 l0 = __float2bfloat16(v.x - __bfloat162float(h0));
    __nv_bfloat16 l1 = __float2bfloat16(v.y - __bfloat162float(h1));
    __nv_bfloat16 l2 = __float2bfloat16(v.z - __bfloat162float(h2));
    __nv_bfloat16 l3 = __float2bfloat16(v.w - __bfloat162float(h3));
    __nv_bfloat162* hp = (__nv_bfloat162*)hi;
    __nv_bfloat162* lp = (__nv_bfloat162*)lo;
    hp[2 * i] = __nv_bfloat162(h0, h1);
    hp[2 * i + 1] = __nv_bfloat162(h2, h3);
    lp[2 * i] = __nv_bfloat162(l0, l1);
    lp[2 * i + 1] = __nv_bfloat162(l2, l3);
}

// =====================================================================
// Kernel 1: tcgen05 bf16 3-term split GEMM.
// C[m][n] = sum_k A[m][k]*W[n][k] + bias[n], 128x256 tile/CTA,
// K-chunks of 64, 2-stage double buffer, D in TMEM (256 cols fp32).
// =====================================================================
#define ST_AH 0
#define ST_AL 16384
#define ST_WH 32768
#define ST_WL 65536
#define STG   98304
#define SM_BIAS  196608
#define SM_TMEMP 197632
#define SM_MB    197640
#define GEMM_SMEM 197760
#define IDESC_N128 0x8200490u
#define NCH 48   // KD / 64

extern __shared__ float smf[];

__global__ __launch_bounds__(256) void qkv_gemm_tc(const float* __restrict__ bias) {
#if HAS_TCGEN05
    char* sm = (char*)smf;
    uint32_t sb = smem_u32(sm);
    int t = threadIdx.x;
    int wid = t >> 5, lane = t & 31;
    int n0 = blockIdx.x * 256, m0 = blockIdx.y * 128;

    // TMEM alloc (warp 0, collective)
    if (wid == 0) TC_ALLOC(sb + SM_TMEMP, 256);
    if (t == 0) {
        MBAR_INIT(sb + SM_MB + 0, 1);
        MBAR_INIT(sb + SM_MB + 8, 1);
    }
    ((float*)(sm + SM_BIAS))[t] = bias[n0 + t];
    __syncthreads();
    uint32_t tmem;
    asm volatile("ld.shared.b32 %0, [%1];" : "=r"(tmem) : "r"(sb + SM_TMEMP));

    for (int i = 0; i < NCH; i++) {
        int s = i & 1;
        uint32_t mbar = sb + SM_MB + s * 8;
        if (i >= 2) MBAR_WAIT(mbar, ((i >> 1) + 1) & 1);

        int k0 = i * 64;
        char* stg = sm + s * STG;
        // A hi/lo tiles: 128 rows x 64 bf16 (128B rows, SW128)
#pragma unroll
        for (int it = 0; it < 4; it++) {
            int idx = t + it * 256;
            int r = idx >> 3, c = idx & 7;
            size_t g = (size_t)(m0 + r) * KD + k0 + c * 8;
            uint32_t so = SWZ(r * 128 + c * 16);
            *(uint4*)(stg + ST_AH + so) = *(const uint4*)(g_Ah + g);
            *(uint4*)(stg + ST_AL + so) = *(const uint4*)(g_Al + g);
        }
        // W hi/lo tiles: 256 rows x 64 bf16
#pragma unroll
        for (int it = 0; it < 8; it++) {
            int idx = t + it * 256;
            int r = idx >> 3, c = idx & 7;
            size_t g = (size_t)(n0 + r) * KD + k0 + c * 8;
            uint32_t so = SWZ(r * 128 + c * 16);
            *(uint4*)(stg + ST_WH + so) = *(const uint4*)(g_Wh + g);
            *(uint4*)(stg + ST_WL + so) = *(const uint4*)(g_Wl + g);
        }
        FENCE_ASYNC();
        __syncthreads();

        if (t == 0) {
            uint32_t base = sb + s * STG;
            uint64_t dA[2] = {MK_DESC(base + ST_AH), MK_DESC(base + ST_AL)};
            uint64_t dW0[2] = {MK_DESC(base + ST_WH), MK_DESC(base + ST_WL)};
            uint64_t dW1[2] = {MK_DESC(base + ST_WH + 16384), MK_DESC(base + ST_WL + 16384)};
            const int ca[3] = {0, 0, 1}, cw[3] = {0, 1, 0};
#pragma unroll
            for (int c3 = 0; c3 < 3; c3++) {
#pragma unroll
                for (int ks = 0; ks < 4; ks++) {
                    uint32_t en = (i | c3 | ks) ? 1u : 0u;
                    mma_bf16_ss(tmem, dA[ca[c3]] + ks * 2, dW0[cw[c3]] + ks * 2, IDESC_N128, en);
                    mma_bf16_ss(tmem + 128, dA[ca[c3]] + ks * 2, dW1[cw[c3]] + ks * 2, IDESC_N128, en);
                }
            }
            TC_COMMIT(mbar);
        }
    }

    // final completion waits (24 commits per stage -> last phase parity 1)
    MBAR_WAIT(sb + SM_MB + 0, 1);
    MBAR_WAIT(sb + SM_MB + 8, 1);
    TC_FENCE_AFTER();

    // epilogue: warps 0..3 read their M-subpartitions, add bias, store
    if (wid < 4) {
        const float* bs = (const float*)(sm + SM_BIAS);
        int m = m0 + wid * 32 + lane;
        float* dst = g_qkv + (size_t)m * N3 + n0;
#pragma unroll
        for (int cb = 0; cb < 8; cb++) {
            uint32_t rg[32];
            TC_LD_X32(rg, tmem + cb * 32);
            TC_WAIT_LD();
#pragma unroll
            for (int j = 0; j < 32; j += 4) {
                float4 o;
                o.x = __uint_as_float(rg[j + 0]) + bs[cb * 32 + j + 0];
                o.y = __uint_as_float(rg[j + 1]) + bs[cb * 32 + j + 1];
                o.z = __uint_as_float(rg[j + 2]) + bs[cb * 32 + j + 2];
                o.w = __uint_as_float(rg[j + 3]) + bs[cb * 32 + j + 3];
                *(float4*)(dst + cb * 32 + j) = o;
            }
        }
    }
    __syncthreads();
    if (wid == 0) TC_DEALLOC(tmem, 256);
#endif  // HAS_TCGEN05
}

// =====================================================================
// Kernel 2: per-head RMSNorm (+ interleaved RoPE for s >= T) and
// transpose to [b][h][s][d]. One warp per (b,s,h,which) vector.
// =====================================================================
__global__ __launch_bounds__(256) void norm_rope(const float* __restrict__ wq,
                                                 const float* __restrict__ wk,
                                                 const float* __restrict__ cs,
                                                 const float* __restrict__ sn,
                                                 const int* __restrict__ tsl) {
    int warp = (blockIdx.x * 256 + threadIdx.x) >> 5;
    int lane = threadIdx.x & 31;
    int which = warp % 3;
    int rem = warp / 3;
    int h = rem % Hh;
    int bs = rem / Hh;
    int s = bs % Ss;
    int b = bs / Ss;

    const float4* src = (const float4*)(g_qkv + (size_t)bs * N3 + which * DM + h * HD);
    float4 x = src[lane];

    if (which < 2) {
        float ssq = x.x * x.x + x.y * x.y + x.z * x.z + x.w * x.w;
#pragma unroll
        for (int o = 16; o > 0; o >>= 1) ssq += __shfl_xor_sync(0xffffffffu, ssq, o);
        float r = rsqrtf(ssq * (1.0f / 128.0f) + 1e-6f);
        const float* w = (which == 0) ? wq : wk;
        float4 wv = ((const float4*)w)[lane];
        x.x *= r * wv.x; x.y *= r * wv.y; x.z *= r * wv.z; x.w *= r * wv.w;
        int T = tsl[0];
        if (s >= T) {
            int p = s - T;
            float c0 = cs[p * 64 + lane * 2],     s0 = sn[p * 64 + lane * 2];
            float c1 = cs[p * 64 + lane * 2 + 1], s1 = sn[p * 64 + lane * 2 + 1];
            float4 o;
            o.x = x.x * c0 - x.y * s0;
            o.y = x.y * c0 + x.x * s0;
            o.z = x.z * c1 - x.w * s1;
            o.w = x.w * c1 + x.z * s1;
            x = o;
        }
    }
    float* dst = (which == 0) ? g_q : (which == 1) ? g_k : g_v;
    ((float4*)(dst + ((size_t)(b * Hh + h) * Ss + s) * HD))[lane] = x;
}

// =====================================================================
// Kernel 3: flash attention, 64x64 tiles, fp32, online softmax.
// =====================================================================
#define BM 64
#define BN 64
#define QST 132
#define PST 68
#define ATT_SMEM ((3 * BM * QST + BM * PST + 3 * BM) * 4)

__global__ __launch_bounds__(256) void attn(float* __restrict__ out) {
    float* Qs = smf;
    float* Ks = Qs + BM * QST;
    float* Vs = Ks + BN * QST;
    float* Pp = Vs + BN * QST;
    float* m_s = Pp + BM * PST;
    float* l_s = m_s + BM;
    float* al_s = l_s + BM;

    int t = threadIdx.x;
    int tx = t & 15, ty = t >> 4;
    int q0 = blockIdx.x * BM;
    int h = blockIdx.y, b = blockIdx.z;

    const float* qp  = g_q + ((size_t)(b * Hh + h) * Ss + q0) * HD;
    const float* kpb = g_k + ((size_t)(b * Hh + h) * Ss) * HD;
    const float* vpb = g_v + ((size_t)(b * Hh + h) * Ss) * HD;
    const float scale = 0.08838834764831845f;

#pragma unroll
    for (int it = 0; it < 8; it++) {
        int idx = t + it * 256;
        int r = idx >> 5, d4 = idx & 31;
        float4 q = *(const float4*)(qp + r * HD + d4 * 4);
        q.x *= scale; q.y *= scale; q.z *= scale; q.w *= scale;
        *(float4*)(Qs + r * QST + d4 * 4) = q;
    }
    if (t < BM) { m_s[t] = -1e30f; l_s[t] = 0.0f; }

    unsigned long long acc[4][4];
#pragma unroll
    for (int i = 0; i < 4; i++)
#pragma unroll
        for (int j = 0; j < 4; j++) acc[i][j] = 0ull;

    int r0 = ty * 4, c0 = tx * 4;

    for (int kt = 0; kt < Ss; kt += BN) {
        __syncthreads();
#pragma unroll
        for (int it = 0; it < 8; it++) {
            int idx = t + it * 256;
            int r = idx >> 5, d4 = idx & 31;
            *(float4*)(Ks + r * QST + d4 * 4) = *(const float4*)(kpb + (size_t)(kt + r) * HD + d4 * 4);
            *(float4*)(Vs + r * QST + d4 * 4) = *(const float4*)(vpb + (size_t)(kt + r) * HD + d4 * 4);
        }
        __syncthreads();

        {
            unsigned long long sc[4][4];
#pragma unroll
            for (int i = 0; i < 4; i++)
#pragma unroll
                for (int j = 0; j < 4; j++) sc[i][j] = 0ull;
#pragma unroll 4
            for (int d4 = 0; d4 < 32; d4++) {
                ulonglong2 qv[4], kv[4];
#pragma unroll
                for (int i = 0; i < 4; i++)
                    qv[i] = *(const ulonglong2*)(Qs + (r0 + i) * QST + d4 * 4);
#pragma unroll
                for (int j = 0; j < 4; j++)
                    kv[j] = *(const ulonglong2*)(Ks + (c0 + j) * QST + d4 * 4);
#pragma unroll
                for (int i = 0; i < 4; i++)
#pragma unroll
                    for (int j = 0; j < 4; j++) {
                        sc[i][j] = f2fma(qv[i].x, kv[j].x, sc[i][j]);
                        sc[i][j] = f2fma(qv[i].y, kv[j].y, sc[i][j]);
                    }
            }
#pragma unroll
            for (int i = 0; i < 4; i++)
#pragma unroll
                for (int j = 0; j < 4; j++) {
                    float2 v = upk(sc[i][j]);
                    Pp[(r0 + i) * PST + c0 + j] = v.x + v.y;
                }
        }
        __syncthreads();

        {
            int row = t >> 2, part = t & 3;
            float* prow = Pp + row * PST + part * 16;
            float mx = -1e30f;
#pragma unroll
            for (int c = 0; c < 16; c++) mx = fmaxf(mx, prow[c]);
            mx = fmaxf(mx, __shfl_xor_sync(0xffffffffu, mx, 1));
            mx = fmaxf(mx, __shfl_xor_sync(0xffffffffu, mx, 2));
            float mprev = m_s[row];
            float mnew = fmaxf(mprev, mx);
            float alpha = __expf(mprev - mnew);
            float sum = 0.0f;
#pragma unroll
            for (int c = 0; c < 16; c++) {
                float p = __expf(prow[c] - mnew);
                prow[c] = p;
                sum += p;
            }
            sum += __shfl_xor_sync(0xffffffffu, sum, 1);
            sum += __shfl_xor_sync(0xffffffffu, sum, 2);
            if (part == 0) {
                m_s[row] = mnew;
                l_s[row] = l_s[row] * alpha + sum;
                al_s[row] = alpha;
            }
        }
        __syncthreads();

        {
#pragma unroll
            for (int i = 0; i < 4; i++) {
                unsigned long long a2 = pk2(al_s[r0 + i]);
#pragma unroll
                for (int j = 0; j < 4; j++) acc[i][j] = f2mul(acc[i][j], a2);
            }
#pragma unroll 4
            for (int c = 0; c < BN; c++) {
                ulonglong2 va = *(const ulonglong2*)(Vs + c * QST + tx * 4);
                ulonglong2 vb2 = *(const ulonglong2*)(Vs + c * QST + 64 + tx * 4);
#pragma unroll
                for (int i = 0; i < 4; i++) {
                    unsigned long long p2 = pk2(Pp[(r0 + i) * PST + c]);
                    acc[i][0] = f2fma(p2, va.x, acc[i][0]);
                    acc[i][1] = f2fma(p2, va.y, acc[i][1]);
                    acc[i][2] = f2fma(p2, vb2.x, acc[i][2]);
                    acc[i][3] = f2fma(p2, vb2.y, acc[i][3]);
                }
            }
        }
    }

#pragma unroll
    for (int i = 0; i < 4; i++) {
        float inv = 1.0f / l_s[r0 + i];
        float2 c0f = upk(acc[i][0]), c1f = upk(acc[i][1]);
        float2 c2f = upk(acc[i][2]), c3f = upk(acc[i][3]);
        float4 o0 = make_float4(c0f.x * inv, c0f.y * inv, c1f.x * inv, c1f.y * inv);
        float4 o1 = make_float4(c2f.x * inv, c2f.y * inv, c3f.x * inv, c3f.y * inv);
        size_t obase = ((size_t)b * Ss + q0 + r0 + i) * DM + h * HD;
        *(float4*)(out + obase + tx * 4) = o0;
        *(float4*)(out + obase + 64 + tx * 4) = o1;
    }
}

// =====================================================================
extern "C" void kernel_launch(void* const* d_in, const int* in_sizes, int n_in,
                              void* d_out, int out_size) {
    const float* hs  = (const float*)d_in[0];
    const float* w   = (const float*)d_in[1];
    const float* bqv = (const float*)d_in[2];
    const float* wqn = (const float*)d_in[3];
    const float* wkn = (const float*)d_in[4];
    const float* cs  = (const float*)d_in[5];
    const float* sn  = (const float*)d_in[6];
    const int*   tsl = (const int*)d_in[7];
    float* out = (float*)d_out;

    __nv_bfloat16 *ah, *al, *wh, *wl;
    cudaGetSymbolAddress((void**)&ah, g_Ah);
    cudaGetSymbolAddress((void**)&al, g_Al);
    cudaGetSymbolAddress((void**)&wh, g_Wh);
    cudaGetSymbolAddress((void**)&wl, g_Wl);

    // fp32 -> (hi,lo) bf16 splits
    int na4 = MR * KD / 4;   // 3,538,944
    int nw4 = N3 * KD / 4;   // 7,077,888
    cvt_split<<<(na4 + 255) / 256, 256>>>(hs, ah, al, na4);
    cvt_split<<<(nw4 + 255) / 256, 256>>>(w, wh, wl, nw4);

    // QKV projection on tcgen05
    cudaFuncSetAttribute(qkv_gemm_tc, cudaFuncAttributeMaxDynamicSharedMemorySize, GEMM_SMEM);
    qkv_gemm_tc<<<dim3(N3 / 256, MR / 128), 256, GEMM_SMEM>>>(bqv);

    // RMSNorm + RoPE + transpose to [b][h][s][d]
    int total_warps = Bb * Ss * Hh * 3;
    norm_rope<<<total_warps / 8, 256>>>(wqn, wkn, cs, sn, tsl);

    // Flash attention
    cudaFuncSetAttribute(attn, cudaFuncAttributeMaxDynamicSharedMemorySize, ATT_SMEM);
    attn<<<dim3(Ss / BM, Hh, Bb), 256, ATT_SMEM>>>(out);
}

// round 5
// speedup vs baseline: 5.6961x; 3.7071x over previous
#include <cuda_runtime.h>
#include <cuda_bf16.h>
#include <cuda_fp16.h>
#include <cstdint>

// Arch guard: tcgen05 only exists in the arch-specific (sm_103a) pass.
#if defined(__CUDA_ARCH_FEAT_SM103_ALL) || defined(__CUDA_ARCH_FEAT_SM100_ALL) || \
    (defined(__CUDA_ARCH_SPECIFIC__) && (__CUDA_ARCH_SPECIFIC__ >= 1000))
#define HAS_TCGEN05 1
#else
#define HAS_TCGEN05 0
#endif

// Problem constants
#define Bb 2
#define Ss 2304
#define Hh 24
#define HD 128
#define DM 3072
#define N3 9216
#define KD 3072
#define MR (Bb*Ss)

// Scratch (static device globals)
__device__ float g_qkv[(size_t)MR * N3];
__device__ alignas(128) __nv_bfloat16 g_Ah[(size_t)MR * KD];
__device__ alignas(128) __nv_bfloat16 g_Al[(size_t)MR * KD];
__device__ alignas(128) __nv_bfloat16 g_Wh[(size_t)N3 * KD];
__device__ alignas(128) __nv_bfloat16 g_Wl[(size_t)N3 * KD];
// attention operands
#define NBH ((size_t)Bb * Hh * Ss * HD)
__device__ alignas(128) __nv_bfloat16 g_qh[NBH];
__device__ alignas(128) __nv_bfloat16 g_ql[NBH];
__device__ alignas(128) __nv_bfloat16 g_kh[NBH];
__device__ alignas(128) __nv_bfloat16 g_kl[NBH];
__device__ alignas(128) __half g_vh[NBH];   // [b,h,s,d]
__device__ alignas(128) __half g_vt[NBH];   // [b,h,d,s]

// ---------- helpers ----------
__device__ __forceinline__ uint32_t smem_u32(const void* p) {
    uint32_t a;
    asm("{ .reg .u64 t; cvta.to.shared.u64 t, %1; cvt.u32.u64 %0, t; }" : "=r"(a) : "l"(p));
    return a;
}
__device__ __forceinline__ uint32_t h2_as_u32(__half2 h) {
    uint32_t u;
    asm("mov.b32 %0, %1;" : "=r"(u) : "r"(*(uint32_t*)&h));
    return u;
}
#define SWZ(o) ((o) ^ (((o) >> 3) & 0x70))
#define MK_DESC(addr) ((uint64_t(2) << 61) | (uint64_t(1) << 46) | (uint64_t(64) << 32) | \
                       (uint64_t(1) << 16) | ((uint64_t)((addr) >> 4) & 0x3FFF))

#define MBAR_INIT(m, c) asm volatile("mbarrier.init.shared.b64 [%0], %1;" :: "r"(m), "r"(c) : "memory")
#define MBAR_WAIT(m, p) asm volatile( \
    "{\n\t.reg .pred P1;\n\t" \
    "WL%=:\n\tmbarrier.try_wait.parity.acquire.cta.shared::cta.b64 P1, [%0], %1, 0x989680;\n\t" \
    "@P1 bra.uni WD%=;\n\tbra.uni WL%=;\n\tWD%=:\n\t}" \
    :: "r"(m), "r"(p) : "memory")

#if HAS_TCGEN05
__device__ __forceinline__ void mma_ss(uint32_t d, uint64_t a, uint64_t b,
                                       uint32_t idesc, uint32_t en) {
    asm volatile(
        "{\n\t.reg .pred p;\n\tsetp.ne.u32 p, %4, 0;\n\t"
        "tcgen05.mma.cta_group::1.kind::f16 [%0], %1, %2, %3, {%5, %5, %5, %5}, p;\n\t}"
        :: "r"(d), "l"(a), "l"(b), "r"(idesc), "r"(en), "r"(0u) : "memory");
}
__device__ __forceinline__ void mma_ts(uint32_t d, uint32_t a, uint64_t b,
                                       uint32_t idesc, uint32_t en) {
    asm volatile(
        "{\n\t.reg .pred p;\n\tsetp.ne.u32 p, %4, 0;\n\t"
        "tcgen05.mma.cta_group::1.kind::f16 [%0], [%1], %2, %3, {%5, %5, %5, %5}, p;\n\t}"
        :: "r"(d), "r"(a), "l"(b), "r"(idesc), "r"(en), "r"(0u) : "memory");
}
#define TC_COMMIT(m) asm volatile( \
    "tcgen05.commit.cta_group::1.mbarrier::arrive::one.shared::cluster.b64 [%0];" :: "r"(m) : "memory")
#define TC_ALLOC(sm, n)  asm volatile("tcgen05.alloc.cta_group::1.sync.aligned.shared::cta.b32 [%0], %1;" :: "r"(sm), "r"(n) : "memory")
#define TC_DEALLOC(t, n) asm volatile("tcgen05.dealloc.cta_group::1.sync.aligned.b32 %0, %1;" :: "r"(t), "r"(n))
#define TC_FENCE_AFTER() asm volatile("tcgen05.fence::after_thread_sync;" ::: "memory")
#define TC_FENCE_BEFORE() asm volatile("tcgen05.fence::before_thread_sync;" ::: "memory")
#define TC_WAIT_LD()     asm volatile("tcgen05.wait::ld.sync.aligned;" ::: "memory")
#define TC_WAIT_ST()     asm volatile("tcgen05.wait::st.sync.aligned;" ::: "memory")
#define FENCE_ASYNC()    asm volatile("fence.proxy.async.shared::cta;" ::: "memory")

#define TC_LD_X32(r, a) asm volatile( \
    "tcgen05.ld.sync.aligned.32x32b.x32.b32 " \
    "{%0, %1, %2, %3, %4, %5, %6, %7, %8, %9, %10, %11, %12, %13, %14, %15, " \
    "%16, %17, %18, %19, %20, %21, %22, %23, %24, %25, %26, %27, %28, %29, %30, %31}, [%32];" \
    : "=r"((r)[0]), "=r"((r)[1]), "=r"((r)[2]), "=r"((r)[3]), "=r"((r)[4]), "=r"((r)[5]), \
      "=r"((r)[6]), "=r"((r)[7]), "=r"((r)[8]), "=r"((r)[9]), "=r"((r)[10]), "=r"((r)[11]), \
      "=r"((r)[12]), "=r"((r)[13]), "=r"((r)[14]), "=r"((r)[15]), "=r"((r)[16]), "=r"((r)[17]), \
      "=r"((r)[18]), "=r"((r)[19]), "=r"((r)[20]), "=r"((r)[21]), "=r"((r)[22]), "=r"((r)[23]), \
      "=r"((r)[24]), "=r"((r)[25]), "=r"((r)[26]), "=r"((r)[27]), "=r"((r)[28]), "=r"((r)[29]), \
      "=r"((r)[30]), "=r"((r)[31]) : "r"(a))

#define TC_ST_X32(a, r) asm volatile( \
    "tcgen05.st.sync.aligned.32x32b.x32.b32 [%0], " \
    "{%1, %2, %3, %4, %5, %6, %7, %8, %9, %10, %11, %12, %13, %14, %15, %16, " \
    "%17, %18, %19, %20, %21, %22, %23, %24, %25, %26, %27, %28, %29, %30, %31, %32};" \
    :: "r"(a), \
       "r"((r)[0]), "r"((r)[1]), "r"((r)[2]), "r"((r)[3]), "r"((r)[4]), "r"((r)[5]), \
       "r"((r)[6]), "r"((r)[7]), "r"((r)[8]), "r"((r)[9]), "r"((r)[10]), "r"((r)[11]), \
       "r"((r)[12]), "r"((r)[13]), "r"((r)[14]), "r"((r)[15]), "r"((r)[16]), "r"((r)[17]), \
       "r"((r)[18]), "r"((r)[19]), "r"((r)[20]), "r"((r)[21]), "r"((r)[22]), "r"((r)[23]), \
       "r"((r)[24]), "r"((r)[25]), "r"((r)[26]), "r"((r)[27]), "r"((r)[28]), "r"((r)[29]), \
       "r"((r)[30]), "r"((r)[31]) : "memory")
#endif  // HAS_TCGEN05

// =====================================================================
// Kernel 0: fp32 -> (hi, lo) bf16 split
// =====================================================================
__global__ __launch_bounds__(256) void cvt_split(const float* __restrict__ x,
                                                 __nv_bfloat16* __restrict__ hi,
                                                 __nv_bfloat16* __restrict__ lo,
                                                 int n4) {
    int i = blockIdx.x * 256 + threadIdx.x;
    if (i >= n4) return;
    float4 v = ((const float4*)x)[i];
    __nv_bfloat16 h0 = __float2bfloat16(v.x), h1 = __float2bfloat16(v.y);
    __nv_bfloat16 h2 = __float2bfloat16(v.z), h3 = __float2bfloat16(v.w);
    __nv_bfloat16 l0 = __float2bfloat16(v.x - __bfloat162float(h0));
    __nv_bfloat16 l1 = __float2bfloat16(v.y - __bfloat162float(h1));
    __nv_bfloat16 l2 = __float2bfloat16(v.z - __bfloat162float(h2));
    __nv_bfloat16 l3 = __float2bfloat16(v.w - __bfloat162float(h3));
    __nv_bfloat162* hp = (__nv_bfloat162*)hi;
    __nv_bfloat162* lp = (__nv_bfloat162*)lo;
    hp[2 * i] = __nv_bfloat162(h0, h1);
    hp[2 * i + 1] = __nv_bfloat162(h2, h3);
    lp[2 * i] = __nv_bfloat162(l0, l1);
    lp[2 * i + 1] = __nv_bfloat162(l2, l3);
}

// =====================================================================
// Kernel 1: tcgen05 bf16 3-term split GEMM (unchanged from R3).
// =====================================================================
#define ST_AH 0
#define ST_AL 16384
#define ST_WH 32768
#define ST_WL 65536
#define STG   98304
#define SM_BIAS  196608
#define SM_TMEMP 197632
#define SM_MB    197640
#define GEMM_SMEM 197760
#define IDESC_BF16 0x8200490u
#define IDESC_FP16 0x8200010u
#define NCH 48

extern __shared__ float smf[];

__global__ __launch_bounds__(256) void qkv_gemm_tc(const float* __restrict__ bias) {
#if HAS_TCGEN05
    char* sm = (char*)smf;
    uint32_t sb = smem_u32(sm);
    int t = threadIdx.x;
    int wid = t >> 5, lane = t & 31;
    int n0 = blockIdx.x * 256, m0 = blockIdx.y * 128;

    if (wid == 0) TC_ALLOC(sb + SM_TMEMP, 256);
    if (t == 0) {
        MBAR_INIT(sb + SM_MB + 0, 1);
        MBAR_INIT(sb + SM_MB + 8, 1);
    }
    ((float*)(sm + SM_BIAS))[t] = bias[n0 + t];
    __syncthreads();
    uint32_t tmem;
    asm volatile("ld.shared.b32 %0, [%1];" : "=r"(tmem) : "r"(sb + SM_TMEMP));

    for (int i = 0; i < NCH; i++) {
        int s = i & 1;
        uint32_t mbar = sb + SM_MB + s * 8;
        if (i >= 2) MBAR_WAIT(mbar, ((i >> 1) + 1) & 1);

        int k0 = i * 64;
        char* stg = sm + s * STG;
#pragma unroll
        for (int it = 0; it < 4; it++) {
            int idx = t + it * 256;
            int r = idx >> 3, c = idx & 7;
            size_t g = (size_t)(m0 + r) * KD + k0 + c * 8;
            uint32_t so = SWZ(r * 128 + c * 16);
            *(uint4*)(stg + ST_AH + so) = *(const uint4*)(g_Ah + g);
            *(uint4*)(stg + ST_AL + so) = *(const uint4*)(g_Al + g);
        }
#pragma unroll
        for (int it = 0; it < 8; it++) {
            int idx = t + it * 256;
            int r = idx >> 3, c = idx & 7;
            size_t g = (size_t)(n0 + r) * KD + k0 + c * 8;
            uint32_t so = SWZ(r * 128 + c * 16);
            *(uint4*)(stg + ST_WH + so) = *(const uint4*)(g_Wh + g);
            *(uint4*)(stg + ST_WL + so) = *(const uint4*)(g_Wl + g);
        }
        FENCE_ASYNC();
        __syncthreads();

        if (t == 0) {
            uint32_t base = sb + s * STG;
            uint64_t dA[2] = {MK_DESC(base + ST_AH), MK_DESC(base + ST_AL)};
            uint64_t dW0[2] = {MK_DESC(base + ST_WH), MK_DESC(base + ST_WL)};
            uint64_t dW1[2] = {MK_DESC(base + ST_WH + 16384), MK_DESC(base + ST_WL + 16384)};
            const int ca[3] = {0, 0, 1}, cw[3] = {0, 1, 0};
#pragma unroll
            for (int c3 = 0; c3 < 3; c3++) {
#pragma unroll
                for (int ks = 0; ks < 4; ks++) {
                    uint32_t en = (i | c3 | ks) ? 1u : 0u;
                    mma_ss(tmem, dA[ca[c3]] + ks * 2, dW0[cw[c3]] + ks * 2, IDESC_BF16, en);
                    mma_ss(tmem + 128, dA[ca[c3]] + ks * 2, dW1[cw[c3]] + ks * 2, IDESC_BF16, en);
                }
            }
            TC_COMMIT(mbar);
        }
    }

    MBAR_WAIT(sb + SM_MB + 0, 1);
    MBAR_WAIT(sb + SM_MB + 8, 1);
    TC_FENCE_AFTER();

    if (wid < 4) {
        const float* bs = (const float*)(sm + SM_BIAS);
        int m = m0 + wid * 32 + lane;
        float* dst = g_qkv + (size_t)m * N3 + n0;
#pragma unroll
        for (int cb = 0; cb < 8; cb++) {
            uint32_t rg[32];
            TC_LD_X32(rg, tmem + cb * 32);
            TC_WAIT_LD();
#pragma unroll
            for (int j = 0; j < 32; j += 4) {
                float4 o;
                o.x = __uint_as_float(rg[j + 0]) + bs[cb * 32 + j + 0];
                o.y = __uint_as_float(rg[j + 1]) + bs[cb * 32 + j + 1];
                o.z = __uint_as_float(rg[j + 2]) + bs[cb * 32 + j + 2];
                o.w = __uint_as_float(rg[j + 3]) + bs[cb * 32 + j + 3];
                *(float4*)(dst + cb * 32 + j) = o;
            }
        }
    }
    __syncthreads();
    if (wid == 0) TC_DEALLOC(tmem, 256);
#endif
}

// =====================================================================
// Kernel 2: RMSNorm + RoPE; emits bf16 hi/lo Q (pre-scaled) & K, fp16 V.
// =====================================================================
__global__ __launch_bounds__(256) void norm_rope(const float* __restrict__ wq,
                                                 const float* __restrict__ wk,
                                                 const float* __restrict__ cs,
                                                 const float* __restrict__ sn,
                                                 const int* __restrict__ tsl) {
    int warp = (blockIdx.x * 256 + threadIdx.x) >> 5;
    int lane = threadIdx.x & 31;
    int which = warp % 3;
    int rem = warp / 3;
    int h = rem % Hh;
    int bs = rem / Hh;
    int s = bs % Ss;
    int b = bs / Ss;

    const float4* src = (const float4*)(g_qkv + (size_t)bs * N3 + which * DM + h * HD);
    float4 x = src[lane];
    size_t base = ((size_t)(b * Hh + h) * Ss + s) * HD;

    if (which == 2) {
        __half2* vp = (__half2*)(g_vh + base);
        vp[lane * 2]     = __float22half2_rn(make_float2(x.x, x.y));
        vp[lane * 2 + 1] = __float22half2_rn(make_float2(x.z, x.w));
        return;
    }

    float ssq = x.x * x.x + x.y * x.y + x.z * x.z + x.w * x.w;
#pragma unroll
    for (int o = 16; o > 0; o >>= 1) ssq += __shfl_xor_sync(0xffffffffu, ssq, o);
    float r = rsqrtf(ssq * (1.0f / 128.0f) + 1e-6f);
    const float* w = (which == 0) ? wq : wk;
    float4 wv = ((const float4*)w)[lane];
    x.x *= r * wv.x; x.y *= r * wv.y; x.z *= r * wv.z; x.w *= r * wv.w;
    int T = tsl[0];
    if (s >= T) {
        int p = s - T;
        float c0 = cs[p * 64 + lane * 2],     s0 = sn[p * 64 + lane * 2];
        float c1 = cs[p * 64 + lane * 2 + 1], s1 = sn[p * 64 + lane * 2 + 1];
        float4 o;
        o.x = x.x * c0 - x.y * s0;
        o.y = x.y * c0 + x.x * s0;
        o.z = x.z * c1 - x.w * s1;
        o.w = x.w * c1 + x.z * s1;
        x = o;
    }
    __nv_bfloat16* dh;
    __nv_bfloat16* dl;
    if (which == 0) {
        const float scale = 0.08838834764831845f;  // 1/sqrt(128), folded into Q
        x.x *= scale; x.y *= scale; x.z *= scale; x.w *= scale;
        dh = g_qh + base; dl = g_ql + base;
    } else {
        dh = g_kh + base; dl = g_kl + base;
    }
    __nv_bfloat16 h0 = __float2bfloat16(x.x), h1 = __float2bfloat16(x.y);
    __nv_bfloat16 h2 = __float2bfloat16(x.z), h3 = __float2bfloat16(x.w);
    __nv_bfloat16 l0 = __float2bfloat16(x.x - __bfloat162float(h0));
    __nv_bfloat16 l1 = __float2bfloat16(x.y - __bfloat162float(h1));
    __nv_bfloat16 l2 = __float2bfloat16(x.z - __bfloat162float(h2));
    __nv_bfloat16 l3 = __float2bfloat16(x.w - __bfloat162float(h3));
    ((__nv_bfloat162*)dh)[lane * 2]     = __nv_bfloat162(h0, h1);
    ((__nv_bfloat162*)dh)[lane * 2 + 1] = __nv_bfloat162(h2, h3);
    ((__nv_bfloat162*)dl)[lane * 2]     = __nv_bfloat162(l0, l1);
    ((__nv_bfloat162*)dl)[lane * 2 + 1] = __nv_bfloat162(l2, l3);
}

// =====================================================================
// Kernel 2b: V transpose [b,h,s,d] -> [b,h,d,s] (fp16)
// =====================================================================
__global__ __launch_bounds__(256) void v_transpose() {
    __shared__ __half ts[128 * 129];
    int t = threadIdx.x;
    int s0 = blockIdx.x * 128;
    int bh = blockIdx.y;
    const __half* src = g_vh + ((size_t)bh * Ss + s0) * HD;
#pragma unroll
    for (int i = 0; i < 8; i++) {
        int idx = t + i * 256;
        int s = idx >> 4, c8 = idx & 15;
        uint4 v = *(const uint4*)(src + s * HD + c8 * 8);
        __half tmp[8];
        *(uint4*)tmp = v;
#pragma unroll
        for (int j = 0; j < 8; j++) ts[s * 129 + c8 * 8 + j] = tmp[j];
    }
    __syncthreads();
    __half* dst = g_vt + (size_t)bh * HD * Ss;
#pragma unroll
    for (int i = 0; i < 8; i++) {
        int idx = t + i * 256;
        int d = idx >> 4, s8 = idx & 15;
        __half o[8];
#pragma unroll
        for (int j = 0; j < 8; j++) o[j] = ts[(s8 * 8 + j) * 129 + d];
        *(uint4*)(dst + (size_t)d * Ss + s0 + s8 * 8) = *(uint4*)o;
    }
}

// =====================================================================
// Kernel 3: tcgen05 flash attention.
// Q (bf16 hi/lo) in TMEM, K (bf16 hi/lo) + V^T (fp16) in smem.
// S = Qh*Kh + Qh*Kl + Ql*Kh (fp32 in TMEM); softmax in regs;
// P fp16 -> TMEM; O += P*V (fp32 in TMEM).
// =====================================================================
#define A_KH 0
#define A_KL 32768
#define A_V  65536
#define A_PTR 98304
#define A_MBS 98312
#define A_MBO 98320
#define ATT_SMEM 98432
#define NT 18            // Ss / 128
// TMEM col offsets
#define TO_O  0
#define TO_S  128
#define TO_P  256
#define TO_QH 320
#define TO_QL 384

// blocked SW128 tile byte offset: 128 rows x 128 cols(2B), atom 8r x 128B
__device__ __forceinline__ uint32_t tile_off(int r, int c2) {
    uint32_t byte = (uint32_t)(((r >> 3) + (c2 >> 6) * 16) * 1024 + (r & 7) * 128 + (c2 & 63) * 2);
    return SWZ(byte);
}
__device__ __forceinline__ uint32_t dstep(int ks) {  // desc offset per 16-elem k-step
    return (uint32_t)((ks >> 2) * 1024 + (ks & 3) * 2);
}

__global__ __launch_bounds__(256, 1) void attn(float* __restrict__ out) {
#if HAS_TCGEN05
    char* sm = (char*)smf;
    uint32_t sb = smem_u32(sm);
    int t = threadIdx.x;
    int wid = t >> 5;
    int q0 = blockIdx.x * 128;
    int h = blockIdx.y, b = blockIdx.z;
    int bh = b * Hh + h;

    if (wid == 0) TC_ALLOC(sb + A_PTR, 512);
    if (t == 0) {
        MBAR_INIT(sb + A_MBS, 1);
        MBAR_INIT(sb + A_MBO, 1);
    }
    __syncthreads();
    uint32_t tmem;
    asm volatile("ld.shared.b32 %0, [%1];" : "=r"(tmem) : "r"(sb + A_PTR));

    // ---- prologue: Q tile into TMEM, bf16 hi/lo ----
    if (t < 128) {
        uint32_t tw = tmem + ((uint32_t)wid << 21);
        const uint32_t* qh = (const uint32_t*)(g_qh + ((size_t)bh * Ss + q0 + t) * HD);
        const uint32_t* ql = (const uint32_t*)(g_ql + ((size_t)bh * Ss + q0 + t) * HD);
        uint32_t rg[32];
#pragma unroll
        for (int half = 0; half < 2; half++) {
#pragma unroll
            for (int j = 0; j < 32; j++) rg[j] = qh[half * 32 + j];
            TC_ST_X32(tw + TO_QH + half * 32, rg);
#pragma unroll
            for (int j = 0; j < 32; j++) rg[j] = ql[half * 32 + j];
            TC_ST_X32(tw + TO_QL + half * 32, rg);
        }
        TC_WAIT_ST();
    }
    TC_FENCE_BEFORE();
    __syncthreads();

    const __nv_bfloat16* kh_b = g_kh + (size_t)bh * Ss * HD;
    const __nv_bfloat16* kl_b = g_kl + (size_t)bh * Ss * HD;
    const __half* vt_b = g_vt + (size_t)bh * HD * Ss;

    float m = -1e30f, l = 0.0f;

    for (int iter = 0; iter < NT; iter++) {
        if (iter > 0) {
            MBAR_WAIT(sb + A_MBO, (iter - 1) & 1);
            TC_FENCE_AFTER();
        }
        int kt = iter * 128;
#pragma unroll
        for (int i = 0; i < 8; i++) {
            int idx = t + i * 256;
            int r = idx >> 4, c8 = idx & 15;
            uint32_t so = tile_off(r, c8 * 8);
            *(uint4*)(sm + A_KH + so) = *(const uint4*)(kh_b + (size_t)(kt + r) * HD + c8 * 8);
            *(uint4*)(sm + A_KL + so) = *(const uint4*)(kl_b + (size_t)(kt + r) * HD + c8 * 8);
            *(uint4*)(sm + A_V + so)  = *(const uint4*)(vt_b + (size_t)r * Ss + kt + c8 * 8);
        }
        FENCE_ASYNC();
        __syncthreads();

        // ---- QK^T MMAs (3-term split) ----
        if (t == 0) {
            TC_FENCE_AFTER();
            uint64_t dKh = MK_DESC(sb + A_KH);
            uint64_t dKl = MK_DESC(sb + A_KL);
#pragma unroll
            for (int ks = 0; ks < 8; ks++)
                mma_ts(tmem + TO_S, tmem + TO_QH + ks * 8, dKh + dstep(ks), IDESC_BF16, ks > 0);
#pragma unroll
            for (int ks = 0; ks < 8; ks++)
                mma_ts(tmem + TO_S, tmem + TO_QH + ks * 8, dKl + dstep(ks), IDESC_BF16, 1);
#pragma unroll
            for (int ks = 0; ks < 8; ks++)
                mma_ts(tmem + TO_S, tmem + TO_QL + ks * 8, dKh + dstep(ks), IDESC_BF16, 1);
            TC_COMMIT(sb + A_MBS);
        }

        // ---- softmax (warps 0..3; thread t owns row t) ----
        if (t < 128) {
            uint32_t tw = tmem + ((uint32_t)wid << 21);
            MBAR_WAIT(sb + A_MBS, iter & 1);
            TC_FENCE_AFTER();
            float sc[128];
            uint32_t* scu = (uint32_t*)sc;
            TC_LD_X32(scu + 0,  tw + TO_S + 0);
            TC_LD_X32(scu + 32, tw + TO_S + 32);
            TC_LD_X32(scu + 64, tw + TO_S + 64);
            TC_LD_X32(scu + 96, tw + TO_S + 96);
            TC_WAIT_LD();
            float mx = sc[0];
#pragma unroll
            for (int c = 1; c < 128; c++) mx = fmaxf(mx, sc[c]);
            float mnew = fmaxf(m, mx);
            float alpha = __expf(m - mnew);
            m = mnew;
            float sum = 0.0f;
            uint32_t pr[64];
#pragma unroll
            for (int c = 0; c < 64; c++) {
                float p0 = __expf(sc[2 * c] - mnew);
                float p1 = __expf(sc[2 * c + 1] - mnew);
                sum += p0 + p1;
                pr[c] = h2_as_u32(__float22half2_rn(make_float2(p0, p1)));
            }
            l = l * alpha + sum;
            if (iter > 0) {
#pragma unroll
                for (int cb = 0; cb < 4; cb++) {
                    uint32_t og[32];
                    TC_LD_X32(og, tw + TO_O + cb * 32);
                    TC_WAIT_LD();
                    float* of = (float*)og;
#pragma unroll
                    for (int j = 0; j < 32; j++) of[j] *= alpha;
                    TC_ST_X32(tw + TO_O + cb * 32, og);
                }
            }
            TC_ST_X32(tw + TO_P + 0, pr);
            TC_ST_X32(tw + TO_P + 32, pr + 32);
            TC_WAIT_ST();
            TC_FENCE_BEFORE();
        }
        __syncthreads();

        // ---- PV MMA: O += P * V ----
        if (t == 0) {
            TC_FENCE_AFTER();
            uint64_t dV = MK_DESC(sb + A_V);
#pragma unroll
            for (int ks = 0; ks < 8; ks++)
                mma_ts(tmem + TO_O, tmem + TO_P + ks * 8, dV + dstep(ks), IDESC_FP16,
                       (iter > 0) || (ks > 0));
            TC_COMMIT(sb + A_MBO);
        }
    }

    // ---- epilogue ----
    MBAR_WAIT(sb + A_MBO, (NT - 1) & 1);
    TC_FENCE_AFTER();
    if (t < 128) {
        uint32_t tw = tmem + ((uint32_t)wid << 21);
        float inv = 1.0f / l;
        float* dst = out + ((size_t)b * Ss + q0 + t) * DM + h * HD;
#pragma unroll
        for (int cb = 0; cb < 4; cb++) {
            uint32_t og[32];
            TC_LD_X32(og, tw + TO_O + cb * 32);
            TC_WAIT_LD();
            float* of = (float*)og;
#pragma unroll
            for (int j = 0; j < 32; j += 4) {
                float4 o = make_float4(of[j] * inv, of[j + 1] * inv,
                                       of[j + 2] * inv, of[j + 3] * inv);
                *(float4*)(dst + cb * 32 + j) = o;
            }
        }
    }
    __syncthreads();
    if (wid == 0) TC_DEALLOC(tmem, 512);
#endif
}

// =====================================================================
extern "C" void kernel_launch(void* const* d_in, const int* in_sizes, int n_in,
                              void* d_out, int out_size) {
    const float* hs  = (const float*)d_in[0];
    const float* w   = (const float*)d_in[1];
    const float* bqv = (const float*)d_in[2];
    const float* wqn = (const float*)d_in[3];
    const float* wkn = (const float*)d_in[4];
    const float* cs  = (const float*)d_in[5];
    const float* sn  = (const float*)d_in[6];
    const int*   tsl = (const int*)d_in[7];
    float* out = (float*)d_out;

    __nv_bfloat16 *ah, *al, *wh, *wl;
    cudaGetSymbolAddress((void**)&ah, g_Ah);
    cudaGetSymbolAddress((void**)&al, g_Al);
    cudaGetSymbolAddress((void**)&wh, g_Wh);
    cudaGetSymbolAddress((void**)&wl, g_Wl);

    int na4 = MR * KD / 4;
    int nw4 = N3 * KD / 4;
    cvt_split<<<(na4 + 255) / 256, 256>>>(hs, ah, al, na4);
    cvt_split<<<(nw4 + 255) / 256, 256>>>(w, wh, wl, nw4);

    cudaFuncSetAttribute(qkv_gemm_tc, cudaFuncAttributeMaxDynamicSharedMemorySize, GEMM_SMEM);
    qkv_gemm_tc<<<dim3(N3 / 256, MR / 128), 256, GEMM_SMEM>>>(bqv);

    int total_warps = Bb * Ss * Hh * 3;
    norm_rope<<<total_warps / 8, 256>>>(wqn, wkn, cs, sn, tsl);

    v_transpose<<<dim3(Ss / 128, Bb * Hh), 256>>>();

    cudaFuncSetAttribute(attn, cudaFuncAttributeMaxDynamicSharedMemorySize, ATT_SMEM);
    attn<<<dim3(Ss / 128, Hh, Bb), 256, ATT_SMEM>>>(out);
}

// round 6
// speedup vs baseline: 5.9063x; 1.0369x over previous
#include <cuda_runtime.h>
#include <cuda_bf16.h>
#include <cuda_fp16.h>
#include <cstdint>

// Arch guard: tcgen05 only exists in the arch-specific (sm_103a) pass.
#if defined(__CUDA_ARCH_FEAT_SM103_ALL) || defined(__CUDA_ARCH_FEAT_SM100_ALL) || \
    (defined(__CUDA_ARCH_SPECIFIC__) && (__CUDA_ARCH_SPECIFIC__ >= 1000))
#define HAS_TCGEN05 1
#else
#define HAS_TCGEN05 0
#endif

// Problem constants
#define Bb 2
#define Ss 2304
#define Hh 24
#define HD 128
#define DM 3072
#define N3 9216
#define KD 3072
#define MR (Bb*Ss)

// Scratch (static device globals)
__device__ float g_qkv[(size_t)MR * N3];
__device__ alignas(128) __nv_bfloat16 g_Ah[(size_t)MR * KD];
__device__ alignas(128) __nv_bfloat16 g_Al[(size_t)MR * KD];
__device__ alignas(128) __nv_bfloat16 g_Wh[(size_t)N3 * KD];
__device__ alignas(128) __nv_bfloat16 g_Wl[(size_t)N3 * KD];
// attention operands
#define NBH ((size_t)Bb * Hh * Ss * HD)
__device__ alignas(128) __nv_bfloat16 g_qh[NBH];
__device__ alignas(128) __nv_bfloat16 g_ql[NBH];
__device__ alignas(128) __nv_bfloat16 g_kh[NBH];
__device__ alignas(128) __nv_bfloat16 g_kl[NBH];
__device__ alignas(128) __half g_vh[NBH];   // [b,h,s,d]
__device__ alignas(128) __half g_vt[NBH];   // [b,h,d,s]

// ---------- helpers ----------
__device__ __forceinline__ uint32_t smem_u32(const void* p) {
    uint32_t a;
    asm("{ .reg .u64 t; cvta.to.shared.u64 t, %1; cvt.u32.u64 %0, t; }" : "=r"(a) : "l"(p));
    return a;
}
__device__ __forceinline__ uint32_t h2_as_u32(__half2 h) {
    uint32_t u;
    asm("mov.b32 %0, %1;" : "=r"(u) : "r"(*(uint32_t*)&h));
    return u;
}
#define SWZ(o) ((o) ^ (((o) >> 3) & 0x70))
#define MK_DESC(addr) ((uint64_t(2) << 61) | (uint64_t(1) << 46) | (uint64_t(64) << 32) | \
                       (uint64_t(1) << 16) | ((uint64_t)((addr) >> 4) & 0x3FFF))

#define MBAR_INIT(m, c) asm volatile("mbarrier.init.shared.b64 [%0], %1;" :: "r"(m), "r"(c) : "memory")
#define MBAR_WAIT(m, p) asm volatile( \
    "{\n\t.reg .pred P1;\n\t" \
    "WL%=:\n\tmbarrier.try_wait.parity.acquire.cta.shared::cta.b64 P1, [%0], %1, 0x989680;\n\t" \
    "@P1 bra.uni WD%=;\n\tbra.uni WL%=;\n\tWD%=:\n\t}" \
    :: "r"(m), "r"(p) : "memory")

#if HAS_TCGEN05
__device__ __forceinline__ void mma_ss(uint32_t d, uint64_t a, uint64_t b,
                                       uint32_t idesc, uint32_t en) {
    asm volatile(
        "{\n\t.reg .pred p;\n\tsetp.ne.u32 p, %4, 0;\n\t"
        "tcgen05.mma.cta_group::1.kind::f16 [%0], %1, %2, %3, {%5, %5, %5, %5}, p;\n\t}"
        :: "r"(d), "l"(a), "l"(b), "r"(idesc), "r"(en), "r"(0u) : "memory");
}
__device__ __forceinline__ void mma_ts(uint32_t d, uint32_t a, uint64_t b,
                                       uint32_t idesc, uint32_t en) {
    asm volatile(
        "{\n\t.reg .pred p;\n\tsetp.ne.u32 p, %4, 0;\n\t"
        "tcgen05.mma.cta_group::1.kind::f16 [%0], [%1], %2, %3, {%5, %5, %5, %5}, p;\n\t}"
        :: "r"(d), "r"(a), "l"(b), "r"(idesc), "r"(en), "r"(0u) : "memory");
}
#define TC_COMMIT(m) asm volatile( \
    "tcgen05.commit.cta_group::1.mbarrier::arrive::one.shared::cluster.b64 [%0];" :: "r"(m) : "memory")
#define TC_ALLOC(sm, n)  asm volatile("tcgen05.alloc.cta_group::1.sync.aligned.shared::cta.b32 [%0], %1;" :: "r"(sm), "r"(n) : "memory")
#define TC_DEALLOC(t, n) asm volatile("tcgen05.dealloc.cta_group::1.sync.aligned.b32 %0, %1;" :: "r"(t), "r"(n))
#define TC_FENCE_AFTER() asm volatile("tcgen05.fence::after_thread_sync;" ::: "memory")
#define TC_FENCE_BEFORE() asm volatile("tcgen05.fence::before_thread_sync;" ::: "memory")
#define TC_WAIT_LD()     asm volatile("tcgen05.wait::ld.sync.aligned;" ::: "memory")
#define TC_WAIT_ST()     asm volatile("tcgen05.wait::st.sync.aligned;" ::: "memory")
#define FENCE_ASYNC()    asm volatile("fence.proxy.async.shared::cta;" ::: "memory")

#define TC_LD_X32(r, a) asm volatile( \
    "tcgen05.ld.sync.aligned.32x32b.x32.b32 " \
    "{%0, %1, %2, %3, %4, %5, %6, %7, %8, %9, %10, %11, %12, %13, %14, %15, " \
    "%16, %17, %18, %19, %20, %21, %22, %23, %24, %25, %26, %27, %28, %29, %30, %31}, [%32];" \
    : "=r"((r)[0]), "=r"((r)[1]), "=r"((r)[2]), "=r"((r)[3]), "=r"((r)[4]), "=r"((r)[5]), \
      "=r"((r)[6]), "=r"((r)[7]), "=r"((r)[8]), "=r"((r)[9]), "=r"((r)[10]), "=r"((r)[11]), \
      "=r"((r)[12]), "=r"((r)[13]), "=r"((r)[14]), "=r"((r)[15]), "=r"((r)[16]), "=r"((r)[17]), \
      "=r"((r)[18]), "=r"((r)[19]), "=r"((r)[20]), "=r"((r)[21]), "=r"((r)[22]), "=r"((r)[23]), \
      "=r"((r)[24]), "=r"((r)[25]), "=r"((r)[26]), "=r"((r)[27]), "=r"((r)[28]), "=r"((r)[29]), \
      "=r"((r)[30]), "=r"((r)[31]) : "r"(a))

#define TC_ST_X32(a, r) asm volatile( \
    "tcgen05.st.sync.aligned.32x32b.x32.b32 [%0], " \
    "{%1, %2, %3, %4, %5, %6, %7, %8, %9, %10, %11, %12, %13, %14, %15, %16, " \
    "%17, %18, %19, %20, %21, %22, %23, %24, %25, %26, %27, %28, %29, %30, %31, %32};" \
    :: "r"(a), \
       "r"((r)[0]), "r"((r)[1]), "r"((r)[2]), "r"((r)[3]), "r"((r)[4]), "r"((r)[5]), \
       "r"((r)[6]), "r"((r)[7]), "r"((r)[8]), "r"((r)[9]), "r"((r)[10]), "r"((r)[11]), \
       "r"((r)[12]), "r"((r)[13]), "r"((r)[14]), "r"((r)[15]), "r"((r)[16]), "r"((r)[17]), \
       "r"((r)[18]), "r"((r)[19]), "r"((r)[20]), "r"((r)[21]), "r"((r)[22]), "r"((r)[23]), \
       "r"((r)[24]), "r"((r)[25]), "r"((r)[26]), "r"((r)[27]), "r"((r)[28]), "r"((r)[29]), \
       "r"((r)[30]), "r"((r)[31]) : "memory")
#endif  // HAS_TCGEN05

// =====================================================================
// Kernel 0: fp32 -> (hi, lo) bf16 split
// =====================================================================
__global__ __launch_bounds__(256) void cvt_split(const float* __restrict__ x,
                                                 __nv_bfloat16* __restrict__ hi,
                                                 __nv_bfloat16* __restrict__ lo,
                                                 int n4) {
    int i = blockIdx.x * 256 + threadIdx.x;
    if (i >= n4) return;
    float4 v = ((const float4*)x)[i];
    __nv_bfloat16 h0 = __float2bfloat16(v.x), h1 = __float2bfloat16(v.y);
    __nv_bfloat16 h2 = __float2bfloat16(v.z), h3 = __float2bfloat16(v.w);
    __nv_bfloat16 l0 = __float2bfloat16(v.x - __bfloat162float(h0));
    __nv_bfloat16 l1 = __float2bfloat16(v.y - __bfloat162float(h1));
    __nv_bfloat16 l2 = __float2bfloat16(v.z - __bfloat162float(h2));
    __nv_bfloat16 l3 = __float2bfloat16(v.w - __bfloat162float(h3));
    __nv_bfloat162* hp = (__nv_bfloat162*)hi;
    __nv_bfloat162* lp = (__nv_bfloat162*)lo;
    hp[2 * i] = __nv_bfloat162(h0, h1);
    hp[2 * i + 1] = __nv_bfloat162(h2, h3);
    lp[2 * i] = __nv_bfloat162(l0, l1);
    lp[2 * i + 1] = __nv_bfloat162(l2, l3);
}

// =====================================================================
// Kernel 1: tcgen05 bf16 3-term split GEMM (unchanged).
// =====================================================================
#define ST_AH 0
#define ST_AL 16384
#define ST_WH 32768
#define ST_WL 65536
#define STG   98304
#define SM_BIAS  196608
#define SM_TMEMP 197632
#define SM_MB    197640
#define GEMM_SMEM 197760
#define IDESC_BF16 0x8200490u
#define IDESC_FP16 0x8200010u
#define NCH 48

extern __shared__ float smf[];

__global__ __launch_bounds__(256) void qkv_gemm_tc(const float* __restrict__ bias) {
#if HAS_TCGEN05
    char* sm = (char*)smf;
    uint32_t sb = smem_u32(sm);
    int t = threadIdx.x;
    int wid = t >> 5, lane = t & 31;
    int n0 = blockIdx.x * 256, m0 = blockIdx.y * 128;

    if (wid == 0) TC_ALLOC(sb + SM_TMEMP, 256);
    if (t == 0) {
        MBAR_INIT(sb + SM_MB + 0, 1);
        MBAR_INIT(sb + SM_MB + 8, 1);
    }
    ((float*)(sm + SM_BIAS))[t] = bias[n0 + t];
    __syncthreads();
    uint32_t tmem;
    asm volatile("ld.shared.b32 %0, [%1];" : "=r"(tmem) : "r"(sb + SM_TMEMP));

    for (int i = 0; i < NCH; i++) {
        int s = i & 1;
        uint32_t mbar = sb + SM_MB + s * 8;
        if (i >= 2) MBAR_WAIT(mbar, ((i >> 1) + 1) & 1);

        int k0 = i * 64;
        char* stg = sm + s * STG;
#pragma unroll
        for (int it = 0; it < 4; it++) {
            int idx = t + it * 256;
            int r = idx >> 3, c = idx & 7;
            size_t g = (size_t)(m0 + r) * KD + k0 + c * 8;
            uint32_t so = SWZ(r * 128 + c * 16);
            *(uint4*)(stg + ST_AH + so) = *(const uint4*)(g_Ah + g);
            *(uint4*)(stg + ST_AL + so) = *(const uint4*)(g_Al + g);
        }
#pragma unroll
        for (int it = 0; it < 8; it++) {
            int idx = t + it * 256;
            int r = idx >> 3, c = idx & 7;
            size_t g = (size_t)(n0 + r) * KD + k0 + c * 8;
            uint32_t so = SWZ(r * 128 + c * 16);
            *(uint4*)(stg + ST_WH + so) = *(const uint4*)(g_Wh + g);
            *(uint4*)(stg + ST_WL + so) = *(const uint4*)(g_Wl + g);
        }
        FENCE_ASYNC();
        __syncthreads();

        if (t == 0) {
            uint32_t base = sb + s * STG;
            uint64_t dA[2] = {MK_DESC(base + ST_AH), MK_DESC(base + ST_AL)};
            uint64_t dW0[2] = {MK_DESC(base + ST_WH), MK_DESC(base + ST_WL)};
            uint64_t dW1[2] = {MK_DESC(base + ST_WH + 16384), MK_DESC(base + ST_WL + 16384)};
            const int ca[3] = {0, 0, 1}, cw[3] = {0, 1, 0};
#pragma unroll
            for (int c3 = 0; c3 < 3; c3++) {
#pragma unroll
                for (int ks = 0; ks < 4; ks++) {
                    uint32_t en = (i | c3 | ks) ? 1u : 0u;
                    mma_ss(tmem, dA[ca[c3]] + ks * 2, dW0[cw[c3]] + ks * 2, IDESC_BF16, en);
                    mma_ss(tmem + 128, dA[ca[c3]] + ks * 2, dW1[cw[c3]] + ks * 2, IDESC_BF16, en);
                }
            }
            TC_COMMIT(mbar);
        }
    }

    MBAR_WAIT(sb + SM_MB + 0, 1);
    MBAR_WAIT(sb + SM_MB + 8, 1);
    TC_FENCE_AFTER();

    if (wid < 4) {
        const float* bs = (const float*)(sm + SM_BIAS);
        int m = m0 + wid * 32 + lane;
        float* dst = g_qkv + (size_t)m * N3 + n0;
#pragma unroll
        for (int cb = 0; cb < 8; cb++) {
            uint32_t rg[32];
            TC_LD_X32(rg, tmem + cb * 32);
            TC_WAIT_LD();
#pragma unroll
            for (int j = 0; j < 32; j += 4) {
                float4 o;
                o.x = __uint_as_float(rg[j + 0]) + bs[cb * 32 + j + 0];
                o.y = __uint_as_float(rg[j + 1]) + bs[cb * 32 + j + 1];
                o.z = __uint_as_float(rg[j + 2]) + bs[cb * 32 + j + 2];
                o.w = __uint_as_float(rg[j + 3]) + bs[cb * 32 + j + 3];
                *(float4*)(dst + cb * 32 + j) = o;
            }
        }
    }
    __syncthreads();
    if (wid == 0) TC_DEALLOC(tmem, 256);
#endif
}

// =====================================================================
// Kernel 2: RMSNorm + RoPE; emits bf16 hi/lo Q (pre-scaled) & K, fp16 V.
// =====================================================================
__global__ __launch_bounds__(256) void norm_rope(const float* __restrict__ wq,
                                                 const float* __restrict__ wk,
                                                 const float* __restrict__ cs,
                                                 const float* __restrict__ sn,
                                                 const int* __restrict__ tsl) {
    int warp = (blockIdx.x * 256 + threadIdx.x) >> 5;
    int lane = threadIdx.x & 31;
    int which = warp % 3;
    int rem = warp / 3;
    int h = rem % Hh;
    int bs = rem / Hh;
    int s = bs % Ss;
    int b = bs / Ss;

    const float4* src = (const float4*)(g_qkv + (size_t)bs * N3 + which * DM + h * HD);
    float4 x = src[lane];
    size_t base = ((size_t)(b * Hh + h) * Ss + s) * HD;

    if (which == 2) {
        __half2* vp = (__half2*)(g_vh + base);
        vp[lane * 2]     = __float22half2_rn(make_float2(x.x, x.y));
        vp[lane * 2 + 1] = __float22half2_rn(make_float2(x.z, x.w));
        return;
    }

    float ssq = x.x * x.x + x.y * x.y + x.z * x.z + x.w * x.w;
#pragma unroll
    for (int o = 16; o > 0; o >>= 1) ssq += __shfl_xor_sync(0xffffffffu, ssq, o);
    float r = rsqrtf(ssq * (1.0f / 128.0f) + 1e-6f);
    const float* w = (which == 0) ? wq : wk;
    float4 wv = ((const float4*)w)[lane];
    x.x *= r * wv.x; x.y *= r * wv.y; x.z *= r * wv.z; x.w *= r * wv.w;
    int T = tsl[0];
    if (s >= T) {
        int p = s - T;
        float c0 = cs[p * 64 + lane * 2],     s0 = sn[p * 64 + lane * 2];
        float c1 = cs[p * 64 + lane * 2 + 1], s1 = sn[p * 64 + lane * 2 + 1];
        float4 o;
        o.x = x.x * c0 - x.y * s0;
        o.y = x.y * c0 + x.x * s0;
        o.z = x.z * c1 - x.w * s1;
        o.w = x.w * c1 + x.z * s1;
        x = o;
    }
    __nv_bfloat16* dh;
    __nv_bfloat16* dl;
    if (which == 0) {
        const float scale = 0.08838834764831845f;  // 1/sqrt(128), folded into Q
        x.x *= scale; x.y *= scale; x.z *= scale; x.w *= scale;
        dh = g_qh + base; dl = g_ql + base;
    } else {
        dh = g_kh + base; dl = g_kl + base;
    }
    __nv_bfloat16 h0 = __float2bfloat16(x.x), h1 = __float2bfloat16(x.y);
    __nv_bfloat16 h2 = __float2bfloat16(x.z), h3 = __float2bfloat16(x.w);
    __nv_bfloat16 l0 = __float2bfloat16(x.x - __bfloat162float(h0));
    __nv_bfloat16 l1 = __float2bfloat16(x.y - __bfloat162float(h1));
    __nv_bfloat16 l2 = __float2bfloat16(x.z - __bfloat162float(h2));
    __nv_bfloat16 l3 = __float2bfloat16(x.w - __bfloat162float(h3));
    ((__nv_bfloat162*)dh)[lane * 2]     = __nv_bfloat162(h0, h1);
    ((__nv_bfloat162*)dh)[lane * 2 + 1] = __nv_bfloat162(h2, h3);
    ((__nv_bfloat162*)dl)[lane * 2]     = __nv_bfloat162(l0, l1);
    ((__nv_bfloat162*)dl)[lane * 2 + 1] = __nv_bfloat162(l2, l3);
}

// =====================================================================
// Kernel 2b: V transpose [b,h,s,d] -> [b,h,d,s] (fp16)
// =====================================================================
__global__ __launch_bounds__(256) void v_transpose() {
    __shared__ __half ts[128 * 129];
    int t = threadIdx.x;
    int s0 = blockIdx.x * 128;
    int bh = blockIdx.y;
    const __half* src = g_vh + ((size_t)bh * Ss + s0) * HD;
#pragma unroll
    for (int i = 0; i < 8; i++) {
        int idx = t + i * 256;
        int s = idx >> 4, c8 = idx & 15;
        uint4 v = *(const uint4*)(src + s * HD + c8 * 8);
        __half tmp[8];
        *(uint4*)tmp = v;
#pragma unroll
        for (int j = 0; j < 8; j++) ts[s * 129 + c8 * 8 + j] = tmp[j];
    }
    __syncthreads();
    __half* dst = g_vt + (size_t)bh * HD * Ss;
#pragma unroll
    for (int i = 0; i < 8; i++) {
        int idx = t + i * 256;
        int d = idx >> 4, s8 = idx & 15;
        __half o[8];
#pragma unroll
        for (int j = 0; j < 8; j++) o[j] = ts[(s8 * 8 + j) * 129 + d];
        *(uint4*)(dst + (size_t)d * Ss + s0 + s8 * 8) = *(uint4*)o;
    }
}

// =====================================================================
// Kernel 3: tcgen05 flash attention — pipelined.
// Double-buffered K/V smem, 8-warp softmax, S-MMA overlapped with loads.
// =====================================================================
#define A_STG 98304          // bytes per smem stage (KH 32K + KL 32K + V 32K)
#define AS_KH 0
#define AS_KL 32768
#define AS_V  65536
#define A_SMAX 196608        // float[256]
#define A_SSUM 197632        // float[256]
#define A_PTR  198656
#define A_MBS  198664
#define A_MBO  198672
#define ATT_SMEM 198784
#define NT 18                // Ss / 128
// TMEM col offsets
#define TO_O  0
#define TO_S  128
#define TO_P  256
#define TO_QH 320
#define TO_QL 384

// blocked SW128 tile byte offset: 128 rows x 128 cols(2B), atom 8r x 128B
__device__ __forceinline__ uint32_t tile_off(int r, int c2) {
    uint32_t byte = (uint32_t)(((r >> 3) + (c2 >> 6) * 16) * 1024 + (r & 7) * 128 + (c2 & 63) * 2);
    return SWZ(byte);
}
__device__ __forceinline__ uint32_t dstep(int ks) {  // desc offset per 16-elem k-step
    return (uint32_t)((ks >> 2) * 1024 + (ks & 3) * 2);
}

__global__ __launch_bounds__(256, 1) void attn(float* __restrict__ out) {
#if HAS_TCGEN05
    char* sm = (char*)smf;
    uint32_t sb = smem_u32(sm);
    int t = threadIdx.x;
    int wid = t >> 5;
    int row = t & 127;          // S/O row owned by this thread
    int half = t >> 7;          // 0: cols 0-63, 1: cols 64-127
    int q0 = blockIdx.x * 128;
    int h = blockIdx.y, b = blockIdx.z;
    int bh = b * Hh + h;

    if (wid == 0) TC_ALLOC(sb + A_PTR, 512);
    if (t == 0) {
        MBAR_INIT(sb + A_MBS, 1);
        MBAR_INIT(sb + A_MBO, 1);
    }
    __syncthreads();
    uint32_t tmem;
    asm volatile("ld.shared.b32 %0, [%1];" : "=r"(tmem) : "r"(sb + A_PTR));
    uint32_t tw = tmem + ((uint32_t)(wid & 3) << 21);

    const __nv_bfloat16* kh_b = g_kh + (size_t)bh * Ss * HD;
    const __nv_bfloat16* kl_b = g_kl + (size_t)bh * Ss * HD;
    const __half* vt_b = g_vt + (size_t)bh * HD * Ss;

    // ---- prologue: Q tile into TMEM (8 warps: t<128 QH, t>=128 QL) ----
    {
        const uint32_t* qsrc = (const uint32_t*)((half == 0 ? g_qh : g_ql) +
                                ((size_t)bh * Ss + q0 + row) * HD);
        uint32_t dstc = (half == 0) ? (tw + TO_QH) : (tw + TO_QL);
        uint32_t rg[32];
#pragma unroll
        for (int hb = 0; hb < 2; hb++) {
#pragma unroll
            for (int j = 0; j < 32; j++) rg[j] = qsrc[hb * 32 + j];
            TC_ST_X32(dstc + hb * 32, rg);
        }
        TC_WAIT_ST();
    }
    // ---- prologue: load tile 0 into stage 0 ----
#pragma unroll
    for (int i = 0; i < 8; i++) {
        int idx = t + i * 256;
        int r = idx >> 4, c8 = idx & 15;
        uint32_t so = tile_off(r, c8 * 8);
        *(uint4*)(sm + AS_KH + so) = *(const uint4*)(kh_b + (size_t)r * HD + c8 * 8);
        *(uint4*)(sm + AS_KL + so) = *(const uint4*)(kl_b + (size_t)r * HD + c8 * 8);
        *(uint4*)(sm + AS_V + so)  = *(const uint4*)(vt_b + (size_t)r * Ss + c8 * 8);
    }
    FENCE_ASYNC();
    TC_FENCE_BEFORE();
    __syncthreads();

    float m = -1e30f, l = 0.0f;

    for (int iter = 0; iter < NT; iter++) {
        int s = iter & 1;
        uint32_t stg = sb + s * A_STG;

        // (a) issue S-MMA for this tile (overlaps next-tile loads below)
        if (t == 0) {
            TC_FENCE_AFTER();
            uint64_t dKh = MK_DESC(stg + AS_KH);
            uint64_t dKl = MK_DESC(stg + AS_KL);
#pragma unroll
            for (int ks = 0; ks < 8; ks++)
                mma_ts(tmem + TO_S, tmem + TO_QH + ks * 8, dKh + dstep(ks), IDESC_BF16, ks > 0);
#pragma unroll
            for (int ks = 0; ks < 8; ks++)
                mma_ts(tmem + TO_S, tmem + TO_QH + ks * 8, dKl + dstep(ks), IDESC_BF16, 1);
#pragma unroll
            for (int ks = 0; ks < 8; ks++)
                mma_ts(tmem + TO_S, tmem + TO_QL + ks * 8, dKh + dstep(ks), IDESC_BF16, 1);
            TC_COMMIT(sb + A_MBS);
        }

        // (b) wait PV(iter-1): frees other smem stage + makes O safe to rescale
        if (iter > 0) MBAR_WAIT(sb + A_MBO, (iter - 1) & 1);

        // (c) load tile iter+1 into the other stage (overlaps S-MMA)
        if (iter + 1 < NT) {
            int kt = (iter + 1) * 128;
            char* nst = sm + ((iter + 1) & 1) * A_STG;
#pragma unroll
            for (int i = 0; i < 8; i++) {
                int idx = t + i * 256;
                int r = idx >> 4, c8 = idx & 15;
                uint32_t so = tile_off(r, c8 * 8);
                *(uint4*)(nst + AS_KH + so) = *(const uint4*)(kh_b + (size_t)(kt + r) * HD + c8 * 8);
                *(uint4*)(nst + AS_KL + so) = *(const uint4*)(kl_b + (size_t)(kt + r) * HD + c8 * 8);
                *(uint4*)(nst + AS_V + so)  = *(const uint4*)(vt_b + (size_t)r * Ss + kt + c8 * 8);
            }
            FENCE_ASYNC();
        }

        // (d) softmax — all 256 threads; thread owns 64 cols of row `row`
        {
            MBAR_WAIT(sb + A_MBS, iter & 1);
            TC_FENCE_AFTER();
            float sc[64];
            uint32_t* scu = (uint32_t*)sc;
            uint32_t scol = tw + TO_S + half * 64;
            TC_LD_X32(scu + 0,  scol + 0);
            TC_LD_X32(scu + 32, scol + 32);
            TC_WAIT_LD();
            float pmax = sc[0];
#pragma unroll
            for (int c = 1; c < 64; c++) pmax = fmaxf(pmax, sc[c]);
            ((float*)(sm + A_SMAX))[t] = pmax;
            __syncthreads();
            float omax = ((float*)(sm + A_SMAX))[t ^ 128];
            float mnew = fmaxf(m, fmaxf(pmax, omax));
            float alpha = __expf(m - mnew);
            m = mnew;
            float psum = 0.0f;
            uint32_t pr[32];
#pragma unroll
            for (int c = 0; c < 32; c++) {
                float p0 = __expf(sc[2 * c] - mnew);
                float p1 = __expf(sc[2 * c + 1] - mnew);
                psum += p0 + p1;
                pr[c] = h2_as_u32(__float22half2_rn(make_float2(p0, p1)));
            }
            ((float*)(sm + A_SSUM))[t] = psum;
            // P store: this thread's 64 scores -> 32 half2 TMEM cols
            TC_ST_X32(tw + TO_P + half * 32, pr);
            // O rescale (this half's 64 cols)
            if (iter > 0) {
#pragma unroll
                for (int cb = 0; cb < 2; cb++) {
                    uint32_t og[32];
                    TC_LD_X32(og, tw + TO_O + half * 64 + cb * 32);
                    TC_WAIT_LD();
                    float* of = (float*)og;
#pragma unroll
                    for (int j = 0; j < 32; j++) of[j] *= alpha;
                    TC_ST_X32(tw + TO_O + half * 64 + cb * 32, og);
                }
            }
            TC_WAIT_ST();
            TC_FENCE_BEFORE();
            __syncthreads();
            l = l * alpha + psum + ((float*)(sm + A_SSUM))[t ^ 128];
        }

        // (e) PV MMA: O += P * V
        if (t == 0) {
            TC_FENCE_AFTER();
            uint64_t dV = MK_DESC(stg + AS_V);
#pragma unroll
            for (int ks = 0; ks < 8; ks++)
                mma_ts(tmem + TO_O, tmem + TO_P + ks * 8, dV + dstep(ks), IDESC_FP16,
                       (iter > 0) || (ks > 0));
            TC_COMMIT(sb + A_MBO);
        }
    }

    // ---- epilogue: 8 warps, each thread writes its half-row ----
    MBAR_WAIT(sb + A_MBO, (NT - 1) & 1);
    TC_FENCE_AFTER();
    {
        float inv = 1.0f / l;
        float* dst = out + ((size_t)b * Ss + q0 + row) * DM + h * HD + half * 64;
#pragma unroll
        for (int cb = 0; cb < 2; cb++) {
            uint32_t og[32];
            TC_LD_X32(og, tw + TO_O + half * 64 + cb * 32);
            TC_WAIT_LD();
            float* of = (float*)og;
#pragma unroll
            for (int j = 0; j < 32; j += 4) {
                float4 o = make_float4(of[j] * inv, of[j + 1] * inv,
                                       of[j + 2] * inv, of[j + 3] * inv);
                *(float4*)(dst + cb * 32 + j) = o;
            }
        }
    }
    __syncthreads();
    if (wid == 0) TC_DEALLOC(tmem, 512);
#endif
}

// =====================================================================
extern "C" void kernel_launch(void* const* d_in, const int* in_sizes, int n_in,
                              void* d_out, int out_size) {
    const float* hs  = (const float*)d_in[0];
    const float* w   = (const float*)d_in[1];
    const float* bqv = (const float*)d_in[2];
    const float* wqn = (const float*)d_in[3];
    const float* wkn = (const float*)d_in[4];
    const float* cs  = (const float*)d_in[5];
    const float* sn  = (const float*)d_in[6];
    const int*   tsl = (const int*)d_in[7];
    float* out = (float*)d_out;

    __nv_bfloat16 *ah, *al, *wh, *wl;
    cudaGetSymbolAddress((void**)&ah, g_Ah);
    cudaGetSymbolAddress((void**)&al, g_Al);
    cudaGetSymbolAddress((void**)&wh, g_Wh);
    cudaGetSymbolAddress((void**)&wl, g_Wl);

    int na4 = MR * KD / 4;
    int nw4 = N3 * KD / 4;
    cvt_split<<<(na4 + 255) / 256, 256>>>(hs, ah, al, na4);
    cvt_split<<<(nw4 + 255) / 256, 256>>>(w, wh, wl, nw4);

    cudaFuncSetAttribute(qkv_gemm_tc, cudaFuncAttributeMaxDynamicSharedMemorySize, GEMM_SMEM);
    qkv_gemm_tc<<<dim3(N3 / 256, MR / 128), 256, GEMM_SMEM>>>(bqv);

    int total_warps = Bb * Ss * Hh * 3;
    norm_rope<<<total_warps / 8, 256>>>(wqn, wkn, cs, sn, tsl);

    v_transpose<<<dim3(Ss / 128, Bb * Hh), 256>>>();

    cudaFuncSetAttribute(attn, cudaFuncAttributeMaxDynamicSharedMemorySize, ATT_SMEM);
    attn<<<dim3(Ss / 128, Hh, Bb), 256, ATT_SMEM>>>(out);
}

// round 7
// speedup vs baseline: 8.7770x; 1.4860x over previous
#include <cuda_runtime.h>
#include <cuda.h>
#include <cuda_bf16.h>
#include <cuda_fp16.h>
#include <cstdint>

// Arch guard: tcgen05 only exists in the arch-specific (sm_103a) pass.
#if defined(__CUDA_ARCH_FEAT_SM103_ALL) || defined(__CUDA_ARCH_FEAT_SM100_ALL) || \
    (defined(__CUDA_ARCH_SPECIFIC__) && (__CUDA_ARCH_SPECIFIC__ >= 1000))
#define HAS_TCGEN05 1
#else
#define HAS_TCGEN05 0
#endif

// Problem constants
#define Bb 2
#define Ss 2304
#define Hh 24
#define HD 128
#define DM 3072
#define N3 9216
#define KD 3072
#define MR (Bb*Ss)

// Scratch (static device globals)
__device__ float g_qkv[(size_t)MR * N3];
__device__ alignas(128) __nv_bfloat16 g_Ah[(size_t)MR * KD];
__device__ alignas(128) __nv_bfloat16 g_Al[(size_t)MR * KD];
__device__ alignas(128) __nv_bfloat16 g_Wh[(size_t)N3 * KD];
__device__ alignas(128) __nv_bfloat16 g_Wl[(size_t)N3 * KD];
#define NBH ((size_t)Bb * Hh * Ss * HD)
__device__ alignas(128) __nv_bfloat16 g_qh[NBH];
__device__ alignas(128) __nv_bfloat16 g_ql[NBH];
__device__ alignas(128) __nv_bfloat16 g_kh[NBH];
__device__ alignas(128) __nv_bfloat16 g_kl[NBH];
__device__ alignas(128) __half g_vh[NBH];   // [b,h,s,d]
__device__ alignas(128) __half g_vt[NBH];   // [b,h,d,s]

// ---------- helpers ----------
__device__ __forceinline__ uint32_t smem_u32(const void* p) {
    uint32_t a;
    asm("{ .reg .u64 t; cvta.to.shared.u64 t, %1; cvt.u32.u64 %0, t; }" : "=r"(a) : "l"(p));
    return a;
}
__device__ __forceinline__ uint32_t h2_as_u32(__half2 h) {
    uint32_t u;
    asm("mov.b32 %0, %1;" : "=r"(u) : "r"(*(uint32_t*)&h));
    return u;
}
#define SWZ(o) ((o) ^ (((o) >> 3) & 0x70))
#define MK_DESC(addr) ((uint64_t(2) << 61) | (uint64_t(1) << 46) | (uint64_t(64) << 32) | \
                       (uint64_t(1) << 16) | ((uint64_t)((addr) >> 4) & 0x3FFF))

#define MBAR_INIT(m, c) asm volatile("mbarrier.init.shared.b64 [%0], %1;" :: "r"(m), "r"(c) : "memory")
#define MBAR_WAIT(m, p) asm volatile( \
    "{\n\t.reg .pred P1;\n\t" \
    "WL%=:\n\tmbarrier.try_wait.parity.acquire.cta.shared::cta.b64 P1, [%0], %1, 0x989680;\n\t" \
    "@P1 bra.uni WD%=;\n\tbra.uni WL%=;\n\tWD%=:\n\t}" \
    :: "r"(m), "r"(p) : "memory")
#define MBAR_EXPECT_TX(m, n) asm volatile( \
    "mbarrier.arrive.expect_tx.shared.b64 _, [%0], %1;" :: "r"(m), "r"(n) : "memory")

#define TMA_2D(dst, map, x, y, mb) asm volatile( \
    "cp.async.bulk.tensor.2d.shared::cta.global.tile.mbarrier::complete_tx::bytes " \
    "[%0], [%1, {%2, %3}], [%4];" \
    :: "r"(dst), "l"(map), "r"(x), "r"(y), "r"(mb) : "memory")
#define TMA_3D(dst, map, x, y, z, mb) asm volatile( \
    "cp.async.bulk.tensor.3d.shared::cta.global.tile.mbarrier::complete_tx::bytes " \
    "[%0], [%1, {%2, %3, %4}], [%5];" \
    :: "r"(dst), "l"(map), "r"(x), "r"(y), "r"(z), "r"(mb) : "memory")

#if HAS_TCGEN05
__device__ __forceinline__ void mma_ss(uint32_t d, uint64_t a, uint64_t b,
                                       uint32_t idesc, uint32_t en) {
    asm volatile(
        "{\n\t.reg .pred p;\n\tsetp.ne.u32 p, %4, 0;\n\t"
        "tcgen05.mma.cta_group::1.kind::f16 [%0], %1, %2, %3, {%5, %5, %5, %5}, p;\n\t}"
        :: "r"(d), "l"(a), "l"(b), "r"(idesc), "r"(en), "r"(0u) : "memory");
}
__device__ __forceinline__ void mma_ts(uint32_t d, uint32_t a, uint64_t b,
                                       uint32_t idesc, uint32_t en) {
    asm volatile(
        "{\n\t.reg .pred p;\n\tsetp.ne.u32 p, %4, 0;\n\t"
        "tcgen05.mma.cta_group::1.kind::f16 [%0], [%1], %2, %3, {%5, %5, %5, %5}, p;\n\t}"
        :: "r"(d), "r"(a), "l"(b), "r"(idesc), "r"(en), "r"(0u) : "memory");
}
#define TC_COMMIT(m) asm volatile( \
    "tcgen05.commit.cta_group::1.mbarrier::arrive::one.shared::cluster.b64 [%0];" :: "r"(m) : "memory")
#define TC_ALLOC(sm, n)  asm volatile("tcgen05.alloc.cta_group::1.sync.aligned.shared::cta.b32 [%0], %1;" :: "r"(sm), "r"(n) : "memory")
#define TC_DEALLOC(t, n) asm volatile("tcgen05.dealloc.cta_group::1.sync.aligned.b32 %0, %1;" :: "r"(t), "r"(n))
#define TC_FENCE_AFTER() asm volatile("tcgen05.fence::after_thread_sync;" ::: "memory")
#define TC_FENCE_BEFORE() asm volatile("tcgen05.fence::before_thread_sync;" ::: "memory")
#define TC_WAIT_LD()     asm volatile("tcgen05.wait::ld.sync.aligned;" ::: "memory")
#define TC_WAIT_ST()     asm volatile("tcgen05.wait::st.sync.aligned;" ::: "memory")
#define FENCE_ASYNC()    asm volatile("fence.proxy.async.shared::cta;" ::: "memory")

#define TC_LD_X32(r, a) asm volatile( \
    "tcgen05.ld.sync.aligned.32x32b.x32.b32 " \
    "{%0, %1, %2, %3, %4, %5, %6, %7, %8, %9, %10, %11, %12, %13, %14, %15, " \
    "%16, %17, %18, %19, %20, %21, %22, %23, %24, %25, %26, %27, %28, %29, %30, %31}, [%32];" \
    : "=r"((r)[0]), "=r"((r)[1]), "=r"((r)[2]), "=r"((r)[3]), "=r"((r)[4]), "=r"((r)[5]), \
      "=r"((r)[6]), "=r"((r)[7]), "=r"((r)[8]), "=r"((r)[9]), "=r"((r)[10]), "=r"((r)[11]), \
      "=r"((r)[12]), "=r"((r)[13]), "=r"((r)[14]), "=r"((r)[15]), "=r"((r)[16]), "=r"((r)[17]), \
      "=r"((r)[18]), "=r"((r)[19]), "=r"((r)[20]), "=r"((r)[21]), "=r"((r)[22]), "=r"((r)[23]), \
      "=r"((r)[24]), "=r"((r)[25]), "=r"((r)[26]), "=r"((r)[27]), "=r"((r)[28]), "=r"((r)[29]), \
      "=r"((r)[30]), "=r"((r)[31]) : "r"(a))

#define TC_ST_X32(a, r) asm volatile( \
    "tcgen05.st.sync.aligned.32x32b.x32.b32 [%0], " \
    "{%1, %2, %3, %4, %5, %6, %7, %8, %9, %10, %11, %12, %13, %14, %15, %16, " \
    "%17, %18, %19, %20, %21, %22, %23, %24, %25, %26, %27, %28, %29, %30, %31, %32};" \
    :: "r"(a), \
       "r"((r)[0]), "r"((r)[1]), "r"((r)[2]), "r"((r)[3]), "r"((r)[4]), "r"((r)[5]), \
       "r"((r)[6]), "r"((r)[7]), "r"((r)[8]), "r"((r)[9]), "r"((r)[10]), "r"((r)[11]), \
       "r"((r)[12]), "r"((r)[13]), "r"((r)[14]), "r"((r)[15]), "r"((r)[16]), "r"((r)[17]), \
       "r"((r)[18]), "r"((r)[19]), "r"((r)[20]), "r"((r)[21]), "r"((r)[22]), "r"((r)[23]), \
       "r"((r)[24]), "r"((r)[25]), "r"((r)[26]), "r"((r)[27]), "r"((r)[28]), "r"((r)[29]), \
       "r"((r)[30]), "r"((r)[31]) : "memory")
#endif  // HAS_TCGEN05

// =====================================================================
// Kernel 0: fp32 -> (hi, lo) bf16 split
// =====================================================================
__global__ __launch_bounds__(256) void cvt_split(const float* __restrict__ x,
                                                 __nv_bfloat16* __restrict__ hi,
                                                 __nv_bfloat16* __restrict__ lo,
                                                 int n4) {
    int i = blockIdx.x * 256 + threadIdx.x;
    if (i >= n4) return;
    float4 v = ((const float4*)x)[i];
    __nv_bfloat16 h0 = __float2bfloat16(v.x), h1 = __float2bfloat16(v.y);
    __nv_bfloat16 h2 = __float2bfloat16(v.z), h3 = __float2bfloat16(v.w);
    __nv_bfloat16 l0 = __float2bfloat16(v.x - __bfloat162float(h0));
    __nv_bfloat16 l1 = __float2bfloat16(v.y - __bfloat162float(h1));
    __nv_bfloat16 l2 = __float2bfloat16(v.z - __bfloat162float(h2));
    __nv_bfloat16 l3 = __float2bfloat16(v.w - __bfloat162float(h3));
    __nv_bfloat162* hp = (__nv_bfloat162*)hi;
    __nv_bfloat162* lp = (__nv_bfloat162*)lo;
    hp[2 * i] = __nv_bfloat162(h0, h1);
    hp[2 * i + 1] = __nv_bfloat162(h2, h3);
    lp[2 * i] = __nv_bfloat162(l0, l1);
    lp[2 * i + 1] = __nv_bfloat162(l2, l3);
}

// =====================================================================
// Kernel 1: tcgen05 bf16 3-term split GEMM — TMA feed, t0-driven mainloop.
// =====================================================================
#define ST_AH 0
#define ST_AL 16384
#define ST_WH 32768
#define ST_WL 65536
#define STG   98304
#define SM_BIAS  196608
#define SM_TMEMP 197632
#define SM_MB    197640   // mbM[2]
#define SM_KF    197656   // kfull[2]
#define GEMM_SMEM 197760
#define IDESC_BF16 0x8200490u
#define IDESC_FP16 0x8200010u
#define NCH 48

extern __shared__ float smf[];

__global__ __launch_bounds__(256) void qkv_gemm_tc(
        const float* __restrict__ bias,
        const __grid_constant__ CUtensorMap mAh,
        const __grid_constant__ CUtensorMap mAl,
        const __grid_constant__ CUtensorMap mWh,
        const __grid_constant__ CUtensorMap mWl) {
#if HAS_TCGEN05
    char* sm = (char*)smf;
    uint32_t sb = smem_u32(sm);
    int t = threadIdx.x;
    int wid = t >> 5, lane = t & 31;
    int n0 = blockIdx.x * 256, m0 = blockIdx.y * 128;

    if (wid == 0) TC_ALLOC(sb + SM_TMEMP, 256);
    if (t == 0) {
        MBAR_INIT(sb + SM_MB + 0, 1);
        MBAR_INIT(sb + SM_MB + 8, 1);
        MBAR_INIT(sb + SM_KF + 0, 1);
        MBAR_INIT(sb + SM_KF + 8, 1);
        FENCE_ASYNC();
        // prologue: TMA chunk 0 into stage 0
        MBAR_EXPECT_TX(sb + SM_KF, 98304u);
        TMA_2D(sb + ST_AH, &mAh, 0, m0, sb + SM_KF);
        TMA_2D(sb + ST_AL, &mAl, 0, m0, sb + SM_KF);
        TMA_2D(sb + ST_WH, &mWh, 0, n0, sb + SM_KF);
        TMA_2D(sb + ST_WL, &mWl, 0, n0, sb + SM_KF);
    }
    ((float*)(sm + SM_BIAS))[t] = bias[n0 + t];
    __syncthreads();
    uint32_t tmem;
    asm volatile("ld.shared.b32 %0, [%1];" : "=r"(tmem) : "r"(sb + SM_TMEMP));

    if (t == 0) {
        const int ca[3] = {0, 0, 1}, cw[3] = {0, 1, 0};
        for (int i = 0; i < NCH; i++) {
            int s = i & 1;
            uint32_t stg = sb + s * STG;
            MBAR_WAIT(sb + SM_KF + s * 8, (i >> 1) & 1);
            uint64_t dA[2] = {MK_DESC(stg + ST_AH), MK_DESC(stg + ST_AL)};
            uint64_t dW0[2] = {MK_DESC(stg + ST_WH), MK_DESC(stg + ST_WL)};
            uint64_t dW1[2] = {MK_DESC(stg + ST_WH + 16384), MK_DESC(stg + ST_WL + 16384)};
#pragma unroll
            for (int c3 = 0; c3 < 3; c3++) {
#pragma unroll
                for (int ks = 0; ks < 4; ks++) {
                    uint32_t en = (i | c3 | ks) ? 1u : 0u;
                    mma_ss(tmem, dA[ca[c3]] + ks * 2, dW0[cw[c3]] + ks * 2, IDESC_BF16, en);
                    mma_ss(tmem + 128, dA[ca[c3]] + ks * 2, dW1[cw[c3]] + ks * 2, IDESC_BF16, en);
                }
            }
            TC_COMMIT(sb + SM_MB + s * 8);
            if (i + 1 < NCH) {
                int s2 = (i + 1) & 1;
                // stage s2 smem last read by MMA chunk i-1
                if (i >= 1) MBAR_WAIT(sb + SM_MB + s2 * 8, ((i - 1) >> 1) & 1);
                uint32_t st2 = sb + s2 * STG;
                int k0 = (i + 1) * 64;
                MBAR_EXPECT_TX(sb + SM_KF + s2 * 8, 98304u);
                TMA_2D(st2 + ST_AH, &mAh, k0, m0, sb + SM_KF + s2 * 8);
                TMA_2D(st2 + ST_AL, &mAl, k0, m0, sb + SM_KF + s2 * 8);
                TMA_2D(st2 + ST_WH, &mWh, k0, n0, sb + SM_KF + s2 * 8);
                TMA_2D(st2 + ST_WL, &mWl, k0, n0, sb + SM_KF + s2 * 8);
            }
        }
        // final MMA completion (t0 has consumed phases; one outstanding each)
        MBAR_WAIT(sb + SM_MB + 0, 1);
        MBAR_WAIT(sb + SM_MB + 8, 1);
    }
    __syncthreads();
    TC_FENCE_AFTER();

    if (wid < 4) {
        const float* bs = (const float*)(sm + SM_BIAS);
        int m = m0 + wid * 32 + lane;
        float* dst = g_qkv + (size_t)m * N3 + n0;
#pragma unroll
        for (int cb = 0; cb < 8; cb++) {
            uint32_t rg[32];
            TC_LD_X32(rg, tmem + cb * 32);
            TC_WAIT_LD();
#pragma unroll
            for (int j = 0; j < 32; j += 4) {
                float4 o;
                o.x = __uint_as_float(rg[j + 0]) + bs[cb * 32 + j + 0];
                o.y = __uint_as_float(rg[j + 1]) + bs[cb * 32 + j + 1];
                o.z = __uint_as_float(rg[j + 2]) + bs[cb * 32 + j + 2];
                o.w = __uint_as_float(rg[j + 3]) + bs[cb * 32 + j + 3];
                *(float4*)(dst + cb * 32 + j) = o;
            }
        }
    }
    __syncthreads();
    if (wid == 0) TC_DEALLOC(tmem, 256);
#endif
}

// =====================================================================
// Kernel 2: RMSNorm + RoPE; emits bf16 hi/lo Q (pre-scaled) & K, fp16 V.
// =====================================================================
__global__ __launch_bounds__(256) void norm_rope(const float* __restrict__ wq,
                                                 const float* __restrict__ wk,
                                                 const float* __restrict__ cs,
                                                 const float* __restrict__ sn,
                                                 const int* __restrict__ tsl) {
    int warp = (blockIdx.x * 256 + threadIdx.x) >> 5;
    int lane = threadIdx.x & 31;
    int which = warp % 3;
    int rem = warp / 3;
    int h = rem % Hh;
    int bs = rem / Hh;
    int s = bs % Ss;
    int b = bs / Ss;

    const float4* src = (const float4*)(g_qkv + (size_t)bs * N3 + which * DM + h * HD);
    float4 x = src[lane];
    size_t base = ((size_t)(b * Hh + h) * Ss + s) * HD;

    if (which == 2) {
        __half2* vp = (__half2*)(g_vh + base);
        vp[lane * 2]     = __float22half2_rn(make_float2(x.x, x.y));
        vp[lane * 2 + 1] = __float22half2_rn(make_float2(x.z, x.w));
        return;
    }

    float ssq = x.x * x.x + x.y * x.y + x.z * x.z + x.w * x.w;
#pragma unroll
    for (int o = 16; o > 0; o >>= 1) ssq += __shfl_xor_sync(0xffffffffu, ssq, o);
    float r = rsqrtf(ssq * (1.0f / 128.0f) + 1e-6f);
    const float* w = (which == 0) ? wq : wk;
    float4 wv = ((const float4*)w)[lane];
    x.x *= r * wv.x; x.y *= r * wv.y; x.z *= r * wv.z; x.w *= r * wv.w;
    int T = tsl[0];
    if (s >= T) {
        int p = s - T;
        float c0 = cs[p * 64 + lane * 2],     s0 = sn[p * 64 + lane * 2];
        float c1 = cs[p * 64 + lane * 2 + 1], s1 = sn[p * 64 + lane * 2 + 1];
        float4 o;
        o.x = x.x * c0 - x.y * s0;
        o.y = x.y * c0 + x.x * s0;
        o.z = x.z * c1 - x.w * s1;
        o.w = x.w * c1 + x.z * s1;
        x = o;
    }
    __nv_bfloat16* dh;
    __nv_bfloat16* dl;
    if (which == 0) {
        const float scale = 0.08838834764831845f;  // 1/sqrt(128), folded into Q
        x.x *= scale; x.y *= scale; x.z *= scale; x.w *= scale;
        dh = g_qh + base; dl = g_ql + base;
    } else {
        dh = g_kh + base; dl = g_kl + base;
    }
    __nv_bfloat16 h0 = __float2bfloat16(x.x), h1 = __float2bfloat16(x.y);
    __nv_bfloat16 h2 = __float2bfloat16(x.z), h3 = __float2bfloat16(x.w);
    __nv_bfloat16 l0 = __float2bfloat16(x.x - __bfloat162float(h0));
    __nv_bfloat16 l1 = __float2bfloat16(x.y - __bfloat162float(h1));
    __nv_bfloat16 l2 = __float2bfloat16(x.z - __bfloat162float(h2));
    __nv_bfloat16 l3 = __float2bfloat16(x.w - __bfloat162float(h3));
    ((__nv_bfloat162*)dh)[lane * 2]     = __nv_bfloat162(h0, h1);
    ((__nv_bfloat162*)dh)[lane * 2 + 1] = __nv_bfloat162(h2, h3);
    ((__nv_bfloat162*)dl)[lane * 2]     = __nv_bfloat162(l0, l1);
    ((__nv_bfloat162*)dl)[lane * 2 + 1] = __nv_bfloat162(l2, l3);
}

// =====================================================================
// Kernel 2b: V transpose [b,h,s,d] -> [b,h,d,s] (fp16)
// =====================================================================
__global__ __launch_bounds__(256) void v_transpose() {
    __shared__ __half ts[128 * 129];
    int t = threadIdx.x;
    int s0 = blockIdx.x * 128;
    int bh = blockIdx.y;
    const __half* src = g_vh + ((size_t)bh * Ss + s0) * HD;
#pragma unroll
    for (int i = 0; i < 8; i++) {
        int idx = t + i * 256;
        int s = idx >> 4, c8 = idx & 15;
        uint4 v = *(const uint4*)(src + s * HD + c8 * 8);
        __half tmp[8];
        *(uint4*)tmp = v;
#pragma unroll
        for (int j = 0; j < 8; j++) ts[s * 129 + c8 * 8 + j] = tmp[j];
    }
    __syncthreads();
    __half* dst = g_vt + (size_t)bh * HD * Ss;
#pragma unroll
    for (int i = 0; i < 8; i++) {
        int idx = t + i * 256;
        int d = idx >> 4, s8 = idx & 15;
        __half o[8];
#pragma unroll
        for (int j = 0; j < 8; j++) o[j] = ts[(s8 * 8 + j) * 129 + d];
        *(uint4*)(dst + (size_t)d * Ss + s0 + s8 * 8) = *(uint4*)o;
    }
}

// =====================================================================
// Kernel 3: tcgen05 flash attention — TMA feed, pipelined, 8-warp softmax.
// =====================================================================
#define A_STG 98304
#define AS_KH 0
#define AS_KL 32768
#define AS_V  65536
#define A_SMAX 196608
#define A_SSUM 197632
#define A_PTR  198656
#define A_MBS  198664
#define A_MBO  198672
#define A_KF   198680   // kfull[2]
#define ATT_SMEM 198784
#define NT 18
#define TO_O  0
#define TO_S  128
#define TO_P  256
#define TO_QH 320
#define TO_QL 384

__device__ __forceinline__ uint32_t dstep(int ks) {  // desc offset per 16-elem k-step
    return (uint32_t)((ks >> 2) * 1024 + (ks & 3) * 2);
}

__global__ __launch_bounds__(256, 1) void attn(
        float* __restrict__ out,
        const __grid_constant__ CUtensorMap mKh,
        const __grid_constant__ CUtensorMap mKl,
        const __grid_constant__ CUtensorMap mVt) {
#if HAS_TCGEN05
    char* sm = (char*)smf;
    uint32_t sb = smem_u32(sm);
    int t = threadIdx.x;
    int wid = t >> 5;
    int row = t & 127;
    int half = t >> 7;
    int q0 = blockIdx.x * 128;
    int h = blockIdx.y, b = blockIdx.z;
    int bh = b * Hh + h;

    if (wid == 0) TC_ALLOC(sb + A_PTR, 512);
    if (t == 0) {
        MBAR_INIT(sb + A_MBS, 1);
        MBAR_INIT(sb + A_MBO, 1);
        MBAR_INIT(sb + A_KF + 0, 1);
        MBAR_INIT(sb + A_KF + 8, 1);
        FENCE_ASYNC();
        // prologue: TMA tile 0 into stage 0
        MBAR_EXPECT_TX(sb + A_KF, 98304u);
        TMA_3D(sb + AS_KH,         &mKh, 0,  0, bh, sb + A_KF);
        TMA_3D(sb + AS_KH + 16384, &mKh, 64, 0, bh, sb + A_KF);
        TMA_3D(sb + AS_KL,         &mKl, 0,  0, bh, sb + A_KF);
        TMA_3D(sb + AS_KL + 16384, &mKl, 64, 0, bh, sb + A_KF);
        TMA_3D(sb + AS_V,          &mVt, 0,  0, bh, sb + A_KF);
        TMA_3D(sb + AS_V + 16384,  &mVt, 64, 0, bh, sb + A_KF);
    }
    __syncthreads();
    uint32_t tmem;
    asm volatile("ld.shared.b32 %0, [%1];" : "=r"(tmem) : "r"(sb + A_PTR));
    uint32_t tw = tmem + ((uint32_t)(wid & 3) << 21);

    // ---- prologue: Q tile into TMEM (t<128 QH, t>=128 QL) ----
    {
        const uint32_t* qsrc = (const uint32_t*)((half == 0 ? g_qh : g_ql) +
                                ((size_t)bh * Ss + q0 + row) * HD);
        uint32_t dstc = (half == 0) ? (tw + TO_QH) : (tw + TO_QL);
        uint32_t rg[32];
#pragma unroll
        for (int hb = 0; hb < 2; hb++) {
#pragma unroll
            for (int j = 0; j < 32; j++) rg[j] = qsrc[hb * 32 + j];
            TC_ST_X32(dstc + hb * 32, rg);
        }
        TC_WAIT_ST();
    }
    TC_FENCE_BEFORE();
    __syncthreads();

    float m = -1e30f, l = 0.0f;

    for (int iter = 0; iter < NT; iter++) {
        int s = iter & 1;
        uint32_t stg = sb + s * A_STG;

        // (a) S-MMA for this tile (waits TMA full)
        if (t == 0) {
            TC_FENCE_AFTER();
            MBAR_WAIT(sb + A_KF + s * 8, (iter >> 1) & 1);
            uint64_t dKh = MK_DESC(stg + AS_KH);
            uint64_t dKl = MK_DESC(stg + AS_KL);
#pragma unroll
            for (int ks = 0; ks < 8; ks++)
                mma_ts(tmem + TO_S, tmem + TO_QH + ks * 8, dKh + dstep(ks), IDESC_BF16, ks > 0);
#pragma unroll
            for (int ks = 0; ks < 8; ks++)
                mma_ts(tmem + TO_S, tmem + TO_QH + ks * 8, dKl + dstep(ks), IDESC_BF16, 1);
#pragma unroll
            for (int ks = 0; ks < 8; ks++)
                mma_ts(tmem + TO_S, tmem + TO_QL + ks * 8, dKh + dstep(ks), IDESC_BF16, 1);
            TC_COMMIT(sb + A_MBS);
        }

        // (b) wait PV(iter-1): frees other smem stage + makes O safe
        if (iter > 0) MBAR_WAIT(sb + A_MBO, (iter - 1) & 1);

        // (c) TMA tile iter+1 into the other stage
        if (t == 0 && iter + 1 < NT) {
            int s2 = (iter + 1) & 1;
            uint32_t st2 = sb + s2 * A_STG;
            int kt = (iter + 1) * 128;
            MBAR_EXPECT_TX(sb + A_KF + s2 * 8, 98304u);
            TMA_3D(st2 + AS_KH,         &mKh, 0,  kt, bh, sb + A_KF + s2 * 8);
            TMA_3D(st2 + AS_KH + 16384, &mKh, 64, kt, bh, sb + A_KF + s2 * 8);
            TMA_3D(st2 + AS_KL,         &mKl, 0,  kt, bh, sb + A_KF + s2 * 8);
            TMA_3D(st2 + AS_KL + 16384, &mKl, 64, kt, bh, sb + A_KF + s2 * 8);
            TMA_3D(st2 + AS_V,          &mVt, kt,      0, bh, sb + A_KF + s2 * 8);
            TMA_3D(st2 + AS_V + 16384,  &mVt, kt + 64, 0, bh, sb + A_KF + s2 * 8);
        }

        // (d) softmax — all 256 threads; thread owns 64 cols of row `row`
        {
            MBAR_WAIT(sb + A_MBS, iter & 1);
            TC_FENCE_AFTER();
            float sc[64];
            uint32_t* scu = (uint32_t*)sc;
            uint32_t scol = tw + TO_S + half * 64;
            TC_LD_X32(scu + 0,  scol + 0);
            TC_LD_X32(scu + 32, scol + 32);
            TC_WAIT_LD();
            float pmax = sc[0];
#pragma unroll
            for (int c = 1; c < 64; c++) pmax = fmaxf(pmax, sc[c]);
            ((float*)(sm + A_SMAX))[t] = pmax;
            __syncthreads();
            float omax = ((float*)(sm + A_SMAX))[t ^ 128];
            float mnew = fmaxf(m, fmaxf(pmax, omax));
            float alpha = __expf(m - mnew);
            m = mnew;
            float psum = 0.0f;
            uint32_t pr[32];
#pragma unroll
            for (int c = 0; c < 32; c++) {
                float p0 = __expf(sc[2 * c] - mnew);
                float p1 = __expf(sc[2 * c + 1] - mnew);
                psum += p0 + p1;
                pr[c] = h2_as_u32(__float22half2_rn(make_float2(p0, p1)));
            }
            ((float*)(sm + A_SSUM))[t] = psum;
            TC_ST_X32(tw + TO_P + half * 32, pr);
            // O rescale — skip entirely when all alphas in warp are exactly 1
            if (iter > 0 && __any_sync(0xffffffffu, alpha != 1.0f)) {
#pragma unroll
                for (int cb = 0; cb < 2; cb++) {
                    uint32_t og[32];
                    TC_LD_X32(og, tw + TO_O + half * 64 + cb * 32);
                    TC_WAIT_LD();
                    float* of = (float*)og;
#pragma unroll
                    for (int j = 0; j < 32; j++) of[j] *= alpha;
                    TC_ST_X32(tw + TO_O + half * 64 + cb * 32, og);
                }
            }
            TC_WAIT_ST();
            TC_FENCE_BEFORE();
            __syncthreads();
            l = l * alpha + psum + ((float*)(sm + A_SSUM))[t ^ 128];
        }

        // (e) PV MMA: O += P * V
        if (t == 0) {
            TC_FENCE_AFTER();
            uint64_t dV = MK_DESC(stg + AS_V);
#pragma unroll
            for (int ks = 0; ks < 8; ks++)
                mma_ts(tmem + TO_O, tmem + TO_P + ks * 8, dV + dstep(ks), IDESC_FP16,
                       (iter > 0) || (ks > 0));
            TC_COMMIT(sb + A_MBO);
        }
    }

    // ---- epilogue ----
    MBAR_WAIT(sb + A_MBO, (NT - 1) & 1);
    TC_FENCE_AFTER();
    {
        float inv = 1.0f / l;
        float* dst = out + ((size_t)b * Ss + q0 + row) * DM + h * HD + half * 64;
#pragma unroll
        for (int cb = 0; cb < 2; cb++) {
            uint32_t og[32];
            TC_LD_X32(og, tw + TO_O + half * 64 + cb * 32);
            TC_WAIT_LD();
            float* of = (float*)og;
#pragma unroll
            for (int j = 0; j < 32; j += 4) {
                float4 o = make_float4(of[j] * inv, of[j + 1] * inv,
                                       of[j + 2] * inv, of[j + 3] * inv);
                *(float4*)(dst + cb * 32 + j) = o;
            }
        }
    }
    __syncthreads();
    if (wid == 0) TC_DEALLOC(tmem, 512);
#endif
}

// =====================================================================
// Host: tensormap encoding via runtime-resolved driver entry point
// =====================================================================
typedef CUresult (*PFN_encodeTiled)(CUtensorMap*, CUtensorMapDataType, cuuint32_t,
                                    void*, const cuuint64_t*, const cuuint64_t*,
                                    const cuuint32_t*, const cuuint32_t*,
                                    CUtensorMapInterleave, CUtensorMapSwizzle,
                                    CUtensorMapL2promotion, CUtensorMapFloatOOBfill);
static PFN_encodeTiled get_encoder() {
    static PFN_encodeTiled fn = nullptr;
    if (!fn) {
        cudaDriverEntryPointQueryResult qr;
        cudaGetDriverEntryPointByVersion("cuTensorMapEncodeTiled", (void**)&fn,
                                         12000, cudaEnableDefault, &qr);
    }
    return fn;
}
static void enc2d(CUtensorMap* m, void* base, uint64_t d0, uint64_t d1,
                  uint32_t b0, uint32_t b1, CUtensorMapDataType dt) {
    cuuint64_t dims[2] = {d0, d1};
    cuuint64_t strides[1] = {d0 * 2};
    cuuint32_t box[2] = {b0, b1};
    cuuint32_t es[2] = {1, 1};
    get_encoder()(m, dt, 2, base, dims, strides, box, es,
                  CU_TENSOR_MAP_INTERLEAVE_NONE, CU_TENSOR_MAP_SWIZZLE_128B,
                  CU_TENSOR_MAP_L2_PROMOTION_L2_128B, CU_TENSOR_MAP_FLOAT_OOB_FILL_NONE);
}
static void enc3d(CUtensorMap* m, void* base, uint64_t d0, uint64_t d1, uint64_t d2,
                  uint32_t b0, uint32_t b1, CUtensorMapDataType dt) {
    cuuint64_t dims[3] = {d0, d1, d2};
    cuuint64_t strides[2] = {d0 * 2, d0 * d1 * 2};
    cuuint32_t box[3] = {b0, b1, 1};
    cuuint32_t es[3] = {1, 1, 1};
    get_encoder()(m, dt, 3, base, dims, strides, box, es,
                  CU_TENSOR_MAP_INTERLEAVE_NONE, CU_TENSOR_MAP_SWIZZLE_128B,
                  CU_TENSOR_MAP_L2_PROMOTION_L2_128B, CU_TENSOR_MAP_FLOAT_OOB_FILL_NONE);
}

extern "C" void kernel_launch(void* const* d_in, const int* in_sizes, int n_in,
                              void* d_out, int out_size) {
    const float* hs  = (const float*)d_in[0];
    const float* w   = (const float*)d_in[1];
    const float* bqv = (const float*)d_in[2];
    const float* wqn = (const float*)d_in[3];
    const float* wkn = (const float*)d_in[4];
    const float* cs  = (const float*)d_in[5];
    const float* sn  = (const float*)d_in[6];
    const int*   tsl = (const int*)d_in[7];
    float* out = (float*)d_out;

    __nv_bfloat16 *ah, *al, *wh, *wl, *kh, *kl;
    __half *vt;
    cudaGetSymbolAddress((void**)&ah, g_Ah);
    cudaGetSymbolAddress((void**)&al, g_Al);
    cudaGetSymbolAddress((void**)&wh, g_Wh);
    cudaGetSymbolAddress((void**)&wl, g_Wl);
    cudaGetSymbolAddress((void**)&kh, g_kh);
    cudaGetSymbolAddress((void**)&kl, g_kl);
    cudaGetSymbolAddress((void**)&vt, g_vt);

    // tensormaps
    CUtensorMap mAh, mAl, mWh, mWl, mKh, mKl, mVt;
    enc2d(&mAh, ah, KD, MR, 64, 128, CU_TENSOR_MAP_DATA_TYPE_BFLOAT16);
    enc2d(&mAl, al, KD, MR, 64, 128, CU_TENSOR_MAP_DATA_TYPE_BFLOAT16);
    enc2d(&mWh, wh, KD, N3, 64, 256, CU_TENSOR_MAP_DATA_TYPE_BFLOAT16);
    enc2d(&mWl, wl, KD, N3, 64, 256, CU_TENSOR_MAP_DATA_TYPE_BFLOAT16);
    enc3d(&mKh, kh, HD, Ss, Bb * Hh, 64, 128, CU_TENSOR_MAP_DATA_TYPE_BFLOAT16);
    enc3d(&mKl, kl, HD, Ss, Bb * Hh, 64, 128, CU_TENSOR_MAP_DATA_TYPE_BFLOAT16);
    enc3d(&mVt, vt, Ss, HD, Bb * Hh, 64, 128, CU_TENSOR_MAP_DATA_TYPE_FLOAT16);

    int na4 = MR * KD / 4;
    int nw4 = N3 * KD / 4;
    cvt_split<<<(na4 + 255) / 256, 256>>>(hs, ah, al, na4);
    cvt_split<<<(nw4 + 255) / 256, 256>>>(w, wh, wl, nw4);

    cudaFuncSetAttribute(qkv_gemm_tc, cudaFuncAttributeMaxDynamicSharedMemorySize, GEMM_SMEM);
    qkv_gemm_tc<<<dim3(N3 / 256, MR / 128), 256, GEMM_SMEM>>>(bqv, mAh, mAl, mWh, mWl);

    int total_warps = Bb * Ss * Hh * 3;
    norm_rope<<<total_warps / 8, 256>>>(wqn, wkn, cs, sn, tsl);

    v_transpose<<<dim3(Ss / 128, Bb * Hh), 256>>>();

    cudaFuncSetAttribute(attn, cudaFuncAttributeMaxDynamicSharedMemorySize, ATT_SMEM);
    attn<<<dim3(Ss / 128, Hh, Bb), 256, ATT_SMEM>>>(out, mKh, mKl, mVt);
}

// round 8
// speedup vs baseline: 8.8286x; 1.0059x over previous
#include <cuda_runtime.h>
#include <cuda.h>
#include <cuda_bf16.h>
#include <cuda_fp16.h>
#include <cstdint>

// Arch guard: tcgen05 only exists in the arch-specific (sm_103a) pass.
#if defined(__CUDA_ARCH_FEAT_SM103_ALL) || defined(__CUDA_ARCH_FEAT_SM100_ALL) || \
    (defined(__CUDA_ARCH_SPECIFIC__) && (__CUDA_ARCH_SPECIFIC__ >= 1000))
#define HAS_TCGEN05 1
#else
#define HAS_TCGEN05 0
#endif

// Problem constants
#define Bb 2
#define Ss 2304
#define Hh 24
#define HD 128
#define DM 3072
#define N3 9216
#define KD 3072
#define MR (Bb*Ss)

// Scratch (static device globals)
__device__ float g_qkv[(size_t)MR * N3];
__device__ alignas(128) __nv_bfloat16 g_Ah[(size_t)MR * KD];
__device__ alignas(128) __nv_bfloat16 g_Al[(size_t)MR * KD];
__device__ alignas(128) __nv_bfloat16 g_Wh[(size_t)N3 * KD];
__device__ alignas(128) __nv_bfloat16 g_Wl[(size_t)N3 * KD];
#define NBH ((size_t)Bb * Hh * Ss * HD)
__device__ alignas(128) __nv_bfloat16 g_qh[NBH];
__device__ alignas(128) __nv_bfloat16 g_ql[NBH];
__device__ alignas(128) __nv_bfloat16 g_kh[NBH];
__device__ alignas(128) __nv_bfloat16 g_kl[NBH];
__device__ alignas(128) __half g_vh[NBH];   // [b,h,s,d]
__device__ alignas(128) __half g_vt[NBH];   // [b,h,d,s]

// ---------- helpers ----------
__device__ __forceinline__ uint32_t smem_u32(const void* p) {
    uint32_t a;
    asm("{ .reg .u64 t; cvta.to.shared.u64 t, %1; cvt.u32.u64 %0, t; }" : "=r"(a) : "l"(p));
    return a;
}
__device__ __forceinline__ uint32_t h2_as_u32(__half2 h) {
    uint32_t u;
    asm("mov.b32 %0, %1;" : "=r"(u) : "r"(*(uint32_t*)&h));
    return u;
}
#define SWZ(o) ((o) ^ (((o) >> 3) & 0x70))
#define MK_DESC(addr) ((uint64_t(2) << 61) | (uint64_t(1) << 46) | (uint64_t(64) << 32) | \
                       (uint64_t(1) << 16) | ((uint64_t)((addr) >> 4) & 0x3FFF))

#define MBAR_INIT(m, c) asm volatile("mbarrier.init.shared.b64 [%0], %1;" :: "r"(m), "r"(c) : "memory")
#define MBAR_WAIT(m, p) asm volatile( \
    "{\n\t.reg .pred P1;\n\t" \
    "WL%=:\n\tmbarrier.try_wait.parity.acquire.cta.shared::cta.b64 P1, [%0], %1, 0x989680;\n\t" \
    "@P1 bra.uni WD%=;\n\tbra.uni WL%=;\n\tWD%=:\n\t}" \
    :: "r"(m), "r"(p) : "memory")
#define MBAR_EXPECT_TX(m, n) asm volatile( \
    "mbarrier.arrive.expect_tx.shared.b64 _, [%0], %1;" :: "r"(m), "r"(n) : "memory")

#define TMA_2D(dst, map, x, y, mb) asm volatile( \
    "cp.async.bulk.tensor.2d.shared::cta.global.tile.mbarrier::complete_tx::bytes " \
    "[%0], [%1, {%2, %3}], [%4];" \
    :: "r"(dst), "l"(map), "r"(x), "r"(y), "r"(mb) : "memory")
#define TMA_3D(dst, map, x, y, z, mb) asm volatile( \
    "cp.async.bulk.tensor.3d.shared::cta.global.tile.mbarrier::complete_tx::bytes " \
    "[%0], [%1, {%2, %3, %4}], [%5];" \
    :: "r"(dst), "l"(map), "r"(x), "r"(y), "r"(z), "r"(mb) : "memory")

#if HAS_TCGEN05
__device__ __forceinline__ void mma_ss(uint32_t d, uint64_t a, uint64_t b,
                                       uint32_t idesc, uint32_t en) {
    asm volatile(
        "{\n\t.reg .pred p;\n\tsetp.ne.u32 p, %4, 0;\n\t"
        "tcgen05.mma.cta_group::1.kind::f16 [%0], %1, %2, %3, {%5, %5, %5, %5}, p;\n\t}"
        :: "r"(d), "l"(a), "l"(b), "r"(idesc), "r"(en), "r"(0u) : "memory");
}
__device__ __forceinline__ void mma_ts(uint32_t d, uint32_t a, uint64_t b,
                                       uint32_t idesc, uint32_t en) {
    asm volatile(
        "{\n\t.reg .pred p;\n\tsetp.ne.u32 p, %4, 0;\n\t"
        "tcgen05.mma.cta_group::1.kind::f16 [%0], [%1], %2, %3, {%5, %5, %5, %5}, p;\n\t}"
        :: "r"(d), "r"(a), "l"(b), "r"(idesc), "r"(en), "r"(0u) : "memory");
}
#define TC_COMMIT(m) asm volatile( \
    "tcgen05.commit.cta_group::1.mbarrier::arrive::one.shared::cluster.b64 [%0];" :: "r"(m) : "memory")
#define TC_ALLOC(sm, n)  asm volatile("tcgen05.alloc.cta_group::1.sync.aligned.shared::cta.b32 [%0], %1;" :: "r"(sm), "r"(n) : "memory")
#define TC_DEALLOC(t, n) asm volatile("tcgen05.dealloc.cta_group::1.sync.aligned.b32 %0, %1;" :: "r"(t), "r"(n))
#define TC_FENCE_AFTER() asm volatile("tcgen05.fence::after_thread_sync;" ::: "memory")
#define TC_FENCE_BEFORE() asm volatile("tcgen05.fence::before_thread_sync;" ::: "memory")
#define TC_WAIT_LD()     asm volatile("tcgen05.wait::ld.sync.aligned;" ::: "memory")
#define TC_WAIT_ST()     asm volatile("tcgen05.wait::st.sync.aligned;" ::: "memory")
#define FENCE_ASYNC()    asm volatile("fence.proxy.async.shared::cta;" ::: "memory")

#define TC_LD_X32(r, a) asm volatile( \
    "tcgen05.ld.sync.aligned.32x32b.x32.b32 " \
    "{%0, %1, %2, %3, %4, %5, %6, %7, %8, %9, %10, %11, %12, %13, %14, %15, " \
    "%16, %17, %18, %19, %20, %21, %22, %23, %24, %25, %26, %27, %28, %29, %30, %31}, [%32];" \
    : "=r"((r)[0]), "=r"((r)[1]), "=r"((r)[2]), "=r"((r)[3]), "=r"((r)[4]), "=r"((r)[5]), \
      "=r"((r)[6]), "=r"((r)[7]), "=r"((r)[8]), "=r"((r)[9]), "=r"((r)[10]), "=r"((r)[11]), \
      "=r"((r)[12]), "=r"((r)[13]), "=r"((r)[14]), "=r"((r)[15]), "=r"((r)[16]), "=r"((r)[17]), \
      "=r"((r)[18]), "=r"((r)[19]), "=r"((r)[20]), "=r"((r)[21]), "=r"((r)[22]), "=r"((r)[23]), \
      "=r"((r)[24]), "=r"((r)[25]), "=r"((r)[26]), "=r"((r)[27]), "=r"((r)[28]), "=r"((r)[29]), \
      "=r"((r)[30]), "=r"((r)[31]) : "r"(a))

#define TC_ST_X32(a, r) asm volatile( \
    "tcgen05.st.sync.aligned.32x32b.x32.b32 [%0], " \
    "{%1, %2, %3, %4, %5, %6, %7, %8, %9, %10, %11, %12, %13, %14, %15, %16, " \
    "%17, %18, %19, %20, %21, %22, %23, %24, %25, %26, %27, %28, %29, %30, %31, %32};" \
    :: "r"(a), \
       "r"((r)[0]), "r"((r)[1]), "r"((r)[2]), "r"((r)[3]), "r"((r)[4]), "r"((r)[5]), \
       "r"((r)[6]), "r"((r)[7]), "r"((r)[8]), "r"((r)[9]), "r"((r)[10]), "r"((r)[11]), \
       "r"((r)[12]), "r"((r)[13]), "r"((r)[14]), "r"((r)[15]), "r"((r)[16]), "r"((r)[17]), \
       "r"((r)[18]), "r"((r)[19]), "r"((r)[20]), "r"((r)[21]), "r"((r)[22]), "r"((r)[23]), \
       "r"((r)[24]), "r"((r)[25]), "r"((r)[26]), "r"((r)[27]), "r"((r)[28]), "r"((r)[29]), \
       "r"((r)[30]), "r"((r)[31]) : "memory")
#endif  // HAS_TCGEN05

// =====================================================================
// Kernel 0: fp32 -> (hi, lo) bf16 split
// =====================================================================
__global__ __launch_bounds__(256) void cvt_split(const float* __restrict__ x,
                                                 __nv_bfloat16* __restrict__ hi,
                                                 __nv_bfloat16* __restrict__ lo,
                                                 int n4) {
    int i = blockIdx.x * 256 + threadIdx.x;
    if (i >= n4) return;
    float4 v = ((const float4*)x)[i];
    __nv_bfloat16 h0 = __float2bfloat16(v.x), h1 = __float2bfloat16(v.y);
    __nv_bfloat16 h2 = __float2bfloat16(v.z), h3 = __float2bfloat16(v.w);
    __nv_bfloat16 l0 = __float2bfloat16(v.x - __bfloat162float(h0));
    __nv_bfloat16 l1 = __float2bfloat16(v.y - __bfloat162float(h1));
    __nv_bfloat16 l2 = __float2bfloat16(v.z - __bfloat162float(h2));
    __nv_bfloat16 l3 = __float2bfloat16(v.w - __bfloat162float(h3));
    __nv_bfloat162* hp = (__nv_bfloat162*)hi;
    __nv_bfloat162* lp = (__nv_bfloat162*)lo;
    hp[2 * i] = __nv_bfloat162(h0, h1);
    hp[2 * i + 1] = __nv_bfloat162(h2, h3);
    lp[2 * i] = __nv_bfloat162(l0, l1);
    lp[2 * i + 1] = __nv_bfloat162(l2, l3);
}

// =====================================================================
// Kernel 1: tcgen05 bf16 3-term split GEMM — TMA feed, t0-driven mainloop.
// =====================================================================
#define ST_AH 0
#define ST_AL 16384
#define ST_WH 32768
#define ST_WL 65536
#define STG   98304
#define SM_BIAS  196608
#define SM_TMEMP 197632
#define SM_MB    197640   // mbM[2]
#define SM_KF    197656   // kfull[2]
#define GEMM_SMEM 197760
#define IDESC_BF16 0x8200490u
#define IDESC_FP16 0x8200010u
#define NCH 48

extern __shared__ float smf[];

__global__ __launch_bounds__(256) void qkv_gemm_tc(
        const float* __restrict__ bias,
        const __grid_constant__ CUtensorMap mAh,
        const __grid_constant__ CUtensorMap mAl,
        const __grid_constant__ CUtensorMap mWh,
        const __grid_constant__ CUtensorMap mWl) {
#if HAS_TCGEN05
    char* sm = (char*)smf;
    uint32_t sb = smem_u32(sm);
    int t = threadIdx.x;
    int wid = t >> 5, lane = t & 31;
    int n0 = blockIdx.x * 256, m0 = blockIdx.y * 128;

    if (wid == 0) TC_ALLOC(sb + SM_TMEMP, 256);
    if (t == 0) {
        MBAR_INIT(sb + SM_MB + 0, 1);
        MBAR_INIT(sb + SM_MB + 8, 1);
        MBAR_INIT(sb + SM_KF + 0, 1);
        MBAR_INIT(sb + SM_KF + 8, 1);
        FENCE_ASYNC();
        // prologue: TMA chunk 0 into stage 0
        MBAR_EXPECT_TX(sb + SM_KF, 98304u);
        TMA_2D(sb + ST_AH, &mAh, 0, m0, sb + SM_KF);
        TMA_2D(sb + ST_AL, &mAl, 0, m0, sb + SM_KF);
        TMA_2D(sb + ST_WH, &mWh, 0, n0, sb + SM_KF);
        TMA_2D(sb + ST_WL, &mWl, 0, n0, sb + SM_KF);
    }
    ((float*)(sm + SM_BIAS))[t] = bias[n0 + t];
    __syncthreads();
    uint32_t tmem;
    asm volatile("ld.shared.b32 %0, [%1];" : "=r"(tmem) : "r"(sb + SM_TMEMP));

    if (t == 0) {
        const int ca[3] = {0, 0, 1}, cw[3] = {0, 1, 0};
        for (int i = 0; i < NCH; i++) {
            int s = i & 1;
            uint32_t stg = sb + s * STG;
            MBAR_WAIT(sb + SM_KF + s * 8, (i >> 1) & 1);
            uint64_t dA[2] = {MK_DESC(stg + ST_AH), MK_DESC(stg + ST_AL)};
            uint64_t dW0[2] = {MK_DESC(stg + ST_WH), MK_DESC(stg + ST_WL)};
            uint64_t dW1[2] = {MK_DESC(stg + ST_WH + 16384), MK_DESC(stg + ST_WL + 16384)};
#pragma unroll
            for (int c3 = 0; c3 < 3; c3++) {
#pragma unroll
                for (int ks = 0; ks < 4; ks++) {
                    uint32_t en = (i | c3 | ks) ? 1u : 0u;
                    mma_ss(tmem, dA[ca[c3]] + ks * 2, dW0[cw[c3]] + ks * 2, IDESC_BF16, en);
                    mma_ss(tmem + 128, dA[ca[c3]] + ks * 2, dW1[cw[c3]] + ks * 2, IDESC_BF16, en);
                }
            }
            TC_COMMIT(sb + SM_MB + s * 8);
            if (i + 1 < NCH) {
                int s2 = (i + 1) & 1;
                // stage s2 smem last read by MMA chunk i-1
                if (i >= 1) MBAR_WAIT(sb + SM_MB + s2 * 8, ((i - 1) >> 1) & 1);
                uint32_t st2 = sb + s2 * STG;
                int k0 = (i + 1) * 64;
                MBAR_EXPECT_TX(sb + SM_KF + s2 * 8, 98304u);
                TMA_2D(st2 + ST_AH, &mAh, k0, m0, sb + SM_KF + s2 * 8);
                TMA_2D(st2 + ST_AL, &mAl, k0, m0, sb + SM_KF + s2 * 8);
                TMA_2D(st2 + ST_WH, &mWh, k0, n0, sb + SM_KF + s2 * 8);
                TMA_2D(st2 + ST_WL, &mWl, k0, n0, sb + SM_KF + s2 * 8);
            }
        }
        // final MMA completion (t0 has consumed phases; one outstanding each)
        MBAR_WAIT(sb + SM_MB + 0, 1);
        MBAR_WAIT(sb + SM_MB + 8, 1);
    }
    __syncthreads();
    TC_FENCE_AFTER();

    if (wid < 4) {
        const float* bs = (const float*)(sm + SM_BIAS);
        int m = m0 + wid * 32 + lane;
        float* dst = g_qkv + (size_t)m * N3 + n0;
#pragma unroll
        for (int cb = 0; cb < 8; cb++) {
            uint32_t rg[32];
            TC_LD_X32(rg, tmem + cb * 32);
            TC_WAIT_LD();
#pragma unroll
            for (int j = 0; j < 32; j += 4) {
                float4 o;
                o.x = __uint_as_float(rg[j + 0]) + bs[cb * 32 + j + 0];
                o.y = __uint_as_float(rg[j + 1]) + bs[cb * 32 + j + 1];
                o.z = __uint_as_float(rg[j + 2]) + bs[cb * 32 + j + 2];
                o.w = __uint_as_float(rg[j + 3]) + bs[cb * 32 + j + 3];
                *(float4*)(dst + cb * 32 + j) = o;
            }
        }
    }
    __syncthreads();
    if (wid == 0) TC_DEALLOC(tmem, 256);
#endif
}

// =====================================================================
// Kernel 2: RMSNorm + RoPE; emits bf16 hi/lo Q (pre-scaled) & K, fp16 V.
// =====================================================================
__global__ __launch_bounds__(256) void norm_rope(const float* __restrict__ wq,
                                                 const float* __restrict__ wk,
                                                 const float* __restrict__ cs,
                                                 const float* __restrict__ sn,
                                                 const int* __restrict__ tsl) {
    int warp = (blockIdx.x * 256 + threadIdx.x) >> 5;
    int lane = threadIdx.x & 31;
    int which = warp % 3;
    int rem = warp / 3;
    int h = rem % Hh;
    int bs = rem / Hh;
    int s = bs % Ss;
    int b = bs / Ss;

    const float4* src = (const float4*)(g_qkv + (size_t)bs * N3 + which * DM + h * HD);
    float4 x = src[lane];
    size_t base = ((size_t)(b * Hh + h) * Ss + s) * HD;

    if (which == 2) {
        __half2* vp = (__half2*)(g_vh + base);
        vp[lane * 2]     = __float22half2_rn(make_float2(x.x, x.y));
        vp[lane * 2 + 1] = __float22half2_rn(make_float2(x.z, x.w));
        return;
    }

    float ssq = x.x * x.x + x.y * x.y + x.z * x.z + x.w * x.w;
#pragma unroll
    for (int o = 16; o > 0; o >>= 1) ssq += __shfl_xor_sync(0xffffffffu, ssq, o);
    float r = rsqrtf(ssq * (1.0f / 128.0f) + 1e-6f);
    const float* w = (which == 0) ? wq : wk;
    float4 wv = ((const float4*)w)[lane];
    x.x *= r * wv.x; x.y *= r * wv.y; x.z *= r * wv.z; x.w *= r * wv.w;
    int T = tsl[0];
    if (s >= T) {
        int p = s - T;
        float c0 = cs[p * 64 + lane * 2],     s0 = sn[p * 64 + lane * 2];
        float c1 = cs[p * 64 + lane * 2 + 1], s1 = sn[p * 64 + lane * 2 + 1];
        float4 o;
        o.x = x.x * c0 - x.y * s0;
        o.y = x.y * c0 + x.x * s0;
        o.z = x.z * c1 - x.w * s1;
        o.w = x.w * c1 + x.z * s1;
        x = o;
    }
    __nv_bfloat16* dh;
    __nv_bfloat16* dl;
    if (which == 0) {
        const float scale = 0.08838834764831845f;  // 1/sqrt(128), folded into Q
        x.x *= scale; x.y *= scale; x.z *= scale; x.w *= scale;
        dh = g_qh + base; dl = g_ql + base;
    } else {
        dh = g_kh + base; dl = g_kl + base;
    }
    __nv_bfloat16 h0 = __float2bfloat16(x.x), h1 = __float2bfloat16(x.y);
    __nv_bfloat16 h2 = __float2bfloat16(x.z), h3 = __float2bfloat16(x.w);
    __nv_bfloat16 l0 = __float2bfloat16(x.x - __bfloat162float(h0));
    __nv_bfloat16 l1 = __float2bfloat16(x.y - __bfloat162float(h1));
    __nv_bfloat16 l2 = __float2bfloat16(x.z - __bfloat162float(h2));
    __nv_bfloat16 l3 = __float2bfloat16(x.w - __bfloat162float(h3));
    ((__nv_bfloat162*)dh)[lane * 2]     = __nv_bfloat162(h0, h1);
    ((__nv_bfloat162*)dh)[lane * 2 + 1] = __nv_bfloat162(h2, h3);
    ((__nv_bfloat162*)dl)[lane * 2]     = __nv_bfloat162(l0, l1);
    ((__nv_bfloat162*)dl)[lane * 2 + 1] = __nv_bfloat162(l2, l3);
}

// =====================================================================
// Kernel 2b: V transpose [b,h,s,d] -> [b,h,d,s] (fp16)
// =====================================================================
__global__ __launch_bounds__(256) void v_transpose() {
    __shared__ __half ts[128 * 129];
    int t = threadIdx.x;
    int s0 = blockIdx.x * 128;
    int bh = blockIdx.y;
    const __half* src = g_vh + ((size_t)bh * Ss + s0) * HD;
#pragma unroll
    for (int i = 0; i < 8; i++) {
        int idx = t + i * 256;
        int s = idx >> 4, c8 = idx & 15;
        uint4 v = *(const uint4*)(src + s * HD + c8 * 8);
        __half tmp[8];
        *(uint4*)tmp = v;
#pragma unroll
        for (int j = 0; j < 8; j++) ts[s * 129 + c8 * 8 + j] = tmp[j];
    }
    __syncthreads();
    __half* dst = g_vt + (size_t)bh * HD * Ss;
#pragma unroll
    for (int i = 0; i < 8; i++) {
        int idx = t + i * 256;
        int d = idx >> 4, s8 = idx & 15;
        __half o[8];
#pragma unroll
        for (int j = 0; j < 8; j++) o[j] = ts[(s8 * 8 + j) * 129 + d];
        *(uint4*)(dst + (size_t)d * Ss + s0 + s8 * 8) = *(uint4*)o;
    }
}

// =====================================================================
// Kernel 3: tcgen05 flash attention — TMA feed, pipelined, 8-warp softmax.
// =====================================================================
#define A_STG 98304
#define AS_KH 0
#define AS_KL 32768
#define AS_V  65536
#define A_SMAX 196608
#define A_SSUM 197632
#define A_PTR  198656
#define A_MBS  198664
#define A_MBO  198672
#define A_KF   198680   // kfull[2]
#define ATT_SMEM 198784
#define NT 18
#define TO_O  0
#define TO_S  128
#define TO_P  256
#define TO_QH 320
#define TO_QL 384

__device__ __forceinline__ uint32_t dstep(int ks) {  // desc offset per 16-elem k-step
    return (uint32_t)((ks >> 2) * 1024 + (ks & 3) * 2);
}

__global__ __launch_bounds__(256, 1) void attn(
        float* __restrict__ out,
        const __grid_constant__ CUtensorMap mKh,
        const __grid_constant__ CUtensorMap mKl,
        const __grid_constant__ CUtensorMap mVt) {
#if HAS_TCGEN05
    char* sm = (char*)smf;
    uint32_t sb = smem_u32(sm);
    int t = threadIdx.x;
    int wid = t >> 5;
    int row = t & 127;
    int half = t >> 7;
    int q0 = blockIdx.x * 128;
    int h = blockIdx.y, b = blockIdx.z;
    int bh = b * Hh + h;

    if (wid == 0) TC_ALLOC(sb + A_PTR, 512);
    if (t == 0) {
        MBAR_INIT(sb + A_MBS, 1);
        MBAR_INIT(sb + A_MBO, 1);
        MBAR_INIT(sb + A_KF + 0, 1);
        MBAR_INIT(sb + A_KF + 8, 1);
        FENCE_ASYNC();
        // prologue: TMA tile 0 into stage 0
        MBAR_EXPECT_TX(sb + A_KF, 98304u);
        TMA_3D(sb + AS_KH,         &mKh, 0,  0, bh, sb + A_KF);
        TMA_3D(sb + AS_KH + 16384, &mKh, 64, 0, bh, sb + A_KF);
        TMA_3D(sb + AS_KL,         &mKl, 0,  0, bh, sb + A_KF);
        TMA_3D(sb + AS_KL + 16384, &mKl, 64, 0, bh, sb + A_KF);
        TMA_3D(sb + AS_V,          &mVt, 0,  0, bh, sb + A_KF);
        TMA_3D(sb + AS_V + 16384,  &mVt, 64, 0, bh, sb + A_KF);
    }
    __syncthreads();
    uint32_t tmem;
    asm volatile("ld.shared.b32 %0, [%1];" : "=r"(tmem) : "r"(sb + A_PTR));
    uint32_t tw = tmem + ((uint32_t)(wid & 3) << 21);

    // ---- prologue: Q tile into TMEM (t<128 QH, t>=128 QL) ----
    {
        const uint32_t* qsrc = (const uint32_t*)((half == 0 ? g_qh : g_ql) +
                                ((size_t)bh * Ss + q0 + row) * HD);
        uint32_t dstc = (half == 0) ? (tw + TO_QH) : (tw + TO_QL);
        uint32_t rg[32];
#pragma unroll
        for (int hb = 0; hb < 2; hb++) {
#pragma unroll
            for (int j = 0; j < 32; j++) rg[j] = qsrc[hb * 32 + j];
            TC_ST_X32(dstc + hb * 32, rg);
        }
        TC_WAIT_ST();
    }
    TC_FENCE_BEFORE();
    __syncthreads();

    float m = -1e30f, l = 0.0f;

    for (int iter = 0; iter < NT; iter++) {
        int s = iter & 1;
        uint32_t stg = sb + s * A_STG;

        // (a) S-MMA for this tile (waits TMA full)
        if (t == 0) {
            TC_FENCE_AFTER();
            MBAR_WAIT(sb + A_KF + s * 8, (iter >> 1) & 1);
            uint64_t dKh = MK_DESC(stg + AS_KH);
            uint64_t dKl = MK_DESC(stg + AS_KL);
#pragma unroll
            for (int ks = 0; ks < 8; ks++)
                mma_ts(tmem + TO_S, tmem + TO_QH + ks * 8, dKh + dstep(ks), IDESC_BF16, ks > 0);
#pragma unroll
            for (int ks = 0; ks < 8; ks++)
                mma_ts(tmem + TO_S, tmem + TO_QH + ks * 8, dKl + dstep(ks), IDESC_BF16, 1);
#pragma unroll
            for (int ks = 0; ks < 8; ks++)
                mma_ts(tmem + TO_S, tmem + TO_QL + ks * 8, dKh + dstep(ks), IDESC_BF16, 1);
            TC_COMMIT(sb + A_MBS);
        }

        // (b) wait PV(iter-1): frees other smem stage + makes O safe
        if (iter > 0) MBAR_WAIT(sb + A_MBO, (iter - 1) & 1);

        // (c) TMA tile iter+1 into the other stage
        if (t == 0 && iter + 1 < NT) {
            int s2 = (iter + 1) & 1;
            uint32_t st2 = sb + s2 * A_STG;
            int kt = (iter + 1) * 128;
            MBAR_EXPECT_TX(sb + A_KF + s2 * 8, 98304u);
            TMA_3D(st2 + AS_KH,         &mKh, 0,  kt, bh, sb + A_KF + s2 * 8);
            TMA_3D(st2 + AS_KH + 16384, &mKh, 64, kt, bh, sb + A_KF + s2 * 8);
            TMA_3D(st2 + AS_KL,         &mKl, 0,  kt, bh, sb + A_KF + s2 * 8);
            TMA_3D(st2 + AS_KL + 16384, &mKl, 64, kt, bh, sb + A_KF + s2 * 8);
            TMA_3D(st2 + AS_V,          &mVt, kt,      0, bh, sb + A_KF + s2 * 8);
            TMA_3D(st2 + AS_V + 16384,  &mVt, kt + 64, 0, bh, sb + A_KF + s2 * 8);
        }

        // (d) softmax — all 256 threads; thread owns 64 cols of row `row`
        {
            MBAR_WAIT(sb + A_MBS, iter & 1);
            TC_FENCE_AFTER();
            float sc[64];
            uint32_t* scu = (uint32_t*)sc;
            uint32_t scol = tw + TO_S + half * 64;
            TC_LD_X32(scu + 0,  scol + 0);
            TC_LD_X32(scu + 32, scol + 32);
            TC_WAIT_LD();
            float pmax = sc[0];
#pragma unroll
            for (int c = 1; c < 64; c++) pmax = fmaxf(pmax, sc[c]);
            ((float*)(sm + A_SMAX))[t] = pmax;
            __syncthreads();
            float omax = ((float*)(sm + A_SMAX))[t ^ 128];
            float mnew = fmaxf(m, fmaxf(pmax, omax));
            float alpha = __expf(m - mnew);
            m = mnew;
            float psum = 0.0f;
            uint32_t pr[32];
#pragma unroll
            for (int c = 0; c < 32; c++) {
                float p0 = __expf(sc[2 * c] - mnew);
                float p1 = __expf(sc[2 * c + 1] - mnew);
                psum += p0 + p1;
                pr[c] = h2_as_u32(__float22half2_rn(make_float2(p0, p1)));
            }
            ((float*)(sm + A_SSUM))[t] = psum;
            TC_ST_X32(tw + TO_P + half * 32, pr);
            // O rescale — skip entirely when all alphas in warp are exactly 1
            if (iter > 0 && __any_sync(0xffffffffu, alpha != 1.0f)) {
#pragma unroll
                for (int cb = 0; cb < 2; cb++) {
                    uint32_t og[32];
                    TC_LD_X32(og, tw + TO_O + half * 64 + cb * 32);
                    TC_WAIT_LD();
                    float* of = (float*)og;
#pragma unroll
                    for (int j = 0; j < 32; j++) of[j] *= alpha;
                    TC_ST_X32(tw + TO_O + half * 64 + cb * 32, og);
                }
            }
            TC_WAIT_ST();
            TC_FENCE_BEFORE();
            __syncthreads();
            l = l * alpha + psum + ((float*)(sm + A_SSUM))[t ^ 128];
        }

        // (e) PV MMA: O += P * V
        if (t == 0) {
            TC_FENCE_AFTER();
            uint64_t dV = MK_DESC(stg + AS_V);
#pragma unroll
            for (int ks = 0; ks < 8; ks++)
                mma_ts(tmem + TO_O, tmem + TO_P + ks * 8, dV + dstep(ks), IDESC_FP16,
                       (iter > 0) || (ks > 0));
            TC_COMMIT(sb + A_MBO);
        }
    }

    // ---- epilogue ----
    MBAR_WAIT(sb + A_MBO, (NT - 1) & 1);
    TC_FENCE_AFTER();
    {
        float inv = 1.0f / l;
        float* dst = out + ((size_t)b * Ss + q0 + row) * DM + h * HD + half * 64;
#pragma unroll
        for (int cb = 0; cb < 2; cb++) {
            uint32_t og[32];
            TC_LD_X32(og, tw + TO_O + half * 64 + cb * 32);
            TC_WAIT_LD();
            float* of = (float*)og;
#pragma unroll
            for (int j = 0; j < 32; j += 4) {
                float4 o = make_float4(of[j] * inv, of[j + 1] * inv,
                                       of[j + 2] * inv, of[j + 3] * inv);
                *(float4*)(dst + cb * 32 + j) = o;
            }
        }
    }
    __syncthreads();
    if (wid == 0) TC_DEALLOC(tmem, 512);
#endif
}

// =====================================================================
// Host: tensormap encoding via runtime-resolved driver entry point
// =====================================================================
typedef CUresult (*PFN_encodeTiled)(CUtensorMap*, CUtensorMapDataType, cuuint32_t,
                                    void*, const cuuint64_t*, const cuuint64_t*,
                                    const cuuint32_t*, const cuuint32_t*,
                                    CUtensorMapInterleave, CUtensorMapSwizzle,
                                    CUtensorMapL2promotion, CUtensorMapFloatOOBfill);
static PFN_encodeTiled get_encoder() {
    static PFN_encodeTiled fn = nullptr;
    if (!fn) {
        cudaDriverEntryPointQueryResult qr;
        cudaGetDriverEntryPointByVersion("cuTensorMapEncodeTiled", (void**)&fn,
                                         12000, cudaEnableDefault, &qr);
    }
    return fn;
}
static void enc2d(CUtensorMap* m, void* base, uint64_t d0, uint64_t d1,
                  uint32_t b0, uint32_t b1, CUtensorMapDataType dt) {
    cuuint64_t dims[2] = {d0, d1};
    cuuint64_t strides[1] = {d0 * 2};
    cuuint32_t box[2] = {b0, b1};
    cuuint32_t es[2] = {1, 1};
    get_encoder()(m, dt, 2, base, dims, strides, box, es,
                  CU_TENSOR_MAP_INTERLEAVE_NONE, CU_TENSOR_MAP_SWIZZLE_128B,
                  CU_TENSOR_MAP_L2_PROMOTION_L2_128B, CU_TENSOR_MAP_FLOAT_OOB_FILL_NONE);
}
static void enc3d(CUtensorMap* m, void* base, uint64_t d0, uint64_t d1, uint64_t d2,
                  uint32_t b0, uint32_t b1, CUtensorMapDataType dt) {
    cuuint64_t dims[3] = {d0, d1, d2};
    cuuint64_t strides[2] = {d0 * 2, d0 * d1 * 2};
    cuuint32_t box[3] = {b0, b1, 1};
    cuuint32_t es[3] = {1, 1, 1};
    get_encoder()(m, dt, 3, base, dims, strides, box, es,
                  CU_TENSOR_MAP_INTERLEAVE_NONE, CU_TENSOR_MAP_SWIZZLE_128B,
                  CU_TENSOR_MAP_L2_PROMOTION_L2_128B, CU_TENSOR_MAP_FLOAT_OOB_FILL_NONE);
}

extern "C" void kernel_launch(void* const* d_in, const int* in_sizes, int n_in,
                              void* d_out, int out_size) {
    const float* hs  = (const float*)d_in[0];
    const float* w   = (const float*)d_in[1];
    const float* bqv = (const float*)d_in[2];
    const float* wqn = (const float*)d_in[3];
    const float* wkn = (const float*)d_in[4];
    const float* cs  = (const float*)d_in[5];
    const float* sn  = (const float*)d_in[6];
    const int*   tsl = (const int*)d_in[7];
    float* out = (float*)d_out;

    __nv_bfloat16 *ah, *al, *wh, *wl, *kh, *kl;
    __half *vt;
    cudaGetSymbolAddress((void**)&ah, g_Ah);
    cudaGetSymbolAddress((void**)&al, g_Al);
    cudaGetSymbolAddress((void**)&wh, g_Wh);
    cudaGetSymbolAddress((void**)&wl, g_Wl);
    cudaGetSymbolAddress((void**)&kh, g_kh);
    cudaGetSymbolAddress((void**)&kl, g_kl);
    cudaGetSymbolAddress((void**)&vt, g_vt);

    // tensormaps
    CUtensorMap mAh, mAl, mWh, mWl, mKh, mKl, mVt;
    enc2d(&mAh, ah, KD, MR, 64, 128, CU_TENSOR_MAP_DATA_TYPE_BFLOAT16);
    enc2d(&mAl, al, KD, MR, 64, 128, CU_TENSOR_MAP_DATA_TYPE_BFLOAT16);
    enc2d(&mWh, wh, KD, N3, 64, 256, CU_TENSOR_MAP_DATA_TYPE_BFLOAT16);
    enc2d(&mWl, wl, KD, N3, 64, 256, CU_TENSOR_MAP_DATA_TYPE_BFLOAT16);
    enc3d(&mKh, kh, HD, Ss, Bb * Hh, 64, 128, CU_TENSOR_MAP_DATA_TYPE_BFLOAT16);
    enc3d(&mKl, kl, HD, Ss, Bb * Hh, 64, 128, CU_TENSOR_MAP_DATA_TYPE_BFLOAT16);
    enc3d(&mVt, vt, Ss, HD, Bb * Hh, 64, 128, CU_TENSOR_MAP_DATA_TYPE_FLOAT16);

    int na4 = MR * KD / 4;
    int nw4 = N3 * KD / 4;
    cvt_split<<<(na4 + 255) / 256, 256>>>(hs, ah, al, na4);
    cvt_split<<<(nw4 + 255) / 256, 256>>>(w, wh, wl, nw4);

    cudaFuncSetAttribute(qkv_gemm_tc, cudaFuncAttributeMaxDynamicSharedMemorySize, GEMM_SMEM);
    qkv_gemm_tc<<<dim3(N3 / 256, MR / 128), 256, GEMM_SMEM>>>(bqv, mAh, mAl, mWh, mWl);

    int total_warps = Bb * Ss * Hh * 3;
    norm_rope<<<total_warps / 8, 256>>>(wqn, wkn, cs, sn, tsl);

    v_transpose<<<dim3(Ss / 128, Bb * Hh), 256>>>();

    cudaFuncSetAttribute(attn, cudaFuncAttributeMaxDynamicSharedMemorySize, ATT_SMEM);
    attn<<<dim3(Ss / 128, Hh, Bb), 256, ATT_SMEM>>>(out, mKh, mKl, mVt);
}

// round 9
// speedup vs baseline: 9.9174x; 1.1233x over previous
#include <cuda_runtime.h>
#include <cuda.h>
#include <cuda_bf16.h>
#include <cuda_fp16.h>
#include <cstdint>

#if defined(__CUDA_ARCH_FEAT_SM103_ALL) || defined(__CUDA_ARCH_FEAT_SM100_ALL) || \
    (defined(__CUDA_ARCH_SPECIFIC__) && (__CUDA_ARCH_SPECIFIC__ >= 1000))
#define HAS_TCGEN05 1
#else
#define HAS_TCGEN05 0
#endif

#define Bb 2
#define Ss 2304
#define Hh 24
#define HD 128
#define DM 3072
#define N3 9216
#define KD 3072
#define MR (Bb*Ss)

__device__ alignas(128) __nv_bfloat16 g_Ah[(size_t)MR * KD];
__device__ alignas(128) __nv_bfloat16 g_Al[(size_t)MR * KD];
__device__ alignas(128) __nv_bfloat16 g_Wh[(size_t)N3 * KD];
__device__ alignas(128) __nv_bfloat16 g_Wl[(size_t)N3 * KD];
#define NBH ((size_t)Bb * Hh * Ss * HD)
__device__ alignas(128) __nv_bfloat16 g_qh[NBH];
__device__ alignas(128) __nv_bfloat16 g_ql[NBH];
__device__ alignas(128) __nv_bfloat16 g_kh[NBH];
__device__ alignas(128) __nv_bfloat16 g_kl[NBH];
__device__ alignas(128) __half g_vh[NBH];
__device__ alignas(128) __half g_vt[NBH];

__device__ __forceinline__ uint32_t smem_u32(const void* p) {
    uint32_t a;
    asm("{ .reg .u64 t; cvta.to.shared.u64 t, %1; cvt.u32.u64 %0, t; }" : "=r"(a) : "l"(p));
    return a;
}
__device__ __forceinline__ uint32_t h2_as_u32(__half2 h) {
    uint32_t u;
    asm("mov.b32 %0, %1;" : "=r"(u) : "r"(*(uint32_t*)&h));
    return u;
}
#define MK_DESC(addr) ((uint64_t(2) << 61) | (uint64_t(1) << 46) | (uint64_t(64) << 32) | \
                       (uint64_t(1) << 16) | ((uint64_t)((addr) >> 4) & 0x3FFF))
#define MBAR_INIT(m, c) asm volatile("mbarrier.init.shared.b64 [%0], %1;" :: "r"(m), "r"(c) : "memory")
#define MBAR_WAIT(m, p) asm volatile( \
    "{\n\t.reg .pred P1;\n\t" \
    "WL%=:\n\tmbarrier.try_wait.parity.acquire.cta.shared::cta.b64 P1, [%0], %1, 0x989680;\n\t" \
    "@P1 bra.uni WD%=;\n\tbra.uni WL%=;\n\tWD%=:\n\t}" \
    :: "r"(m), "r"(p) : "memory")
#define MBAR_EXPECT_TX(m, n) asm volatile( \
    "mbarrier.arrive.expect_tx.shared.b64 _, [%0], %1;" :: "r"(m), "r"(n) : "memory")
#define TMA_3D(dst, map, x, y, z, mb) asm volatile( \
    "cp.async.bulk.tensor.3d.shared::cta.global.tile.mbarrier::complete_tx::bytes " \
    "[%0], [%1, {%2, %3, %4}], [%5];" \
    :: "r"(dst), "l"(map), "r"(x), "r"(y), "r"(z), "r"(mb) : "memory")
#define TMA_2D_CG2(dst, map, x, y, mb) asm volatile( \
    "{\n\t.reg .b32 lb;\n\tand.b32 lb, %4, 0xFEFFFFFF;\n\t" \
    "cp.async.bulk.tensor.2d.cta_group::2.shared::cluster.global.tile." \
    "mbarrier::complete_tx::bytes [%0], [%1, {%2, %3}], [lb];\n\t}" \
    :: "r"(dst), "l"(map), "r"(x), "r"(y), "r"(mb) : "memory")
#define CLUSTER_SYNC() do { \
    asm volatile("barrier.cluster.arrive.aligned;" ::: "memory"); \
    asm volatile("barrier.cluster.wait.aligned;" ::: "memory"); } while (0)

#if HAS_TCGEN05
__device__ __forceinline__ void mma_ss_cg2(uint32_t d, uint64_t a, uint64_t b,
                                           uint32_t idesc, uint32_t en) {
    asm volatile(
        "{\n\t.reg .pred p;\n\tsetp.ne.u32 p, %4, 0;\n\t"
        "tcgen05.mma.cta_group::2.kind::f16 [%0], %1, %2, %3, "
        "{%5, %5, %5, %5, %5, %5, %5, %5}, p;\n\t}"
        :: "r"(d), "l"(a), "l"(b), "r"(idesc), "r"(en), "r"(0u) : "memory");
}
__device__ __forceinline__ void mma_ts(uint32_t d, uint32_t a, uint64_t b,
                                       uint32_t idesc, uint32_t en) {
    asm volatile(
        "{\n\t.reg .pred p;\n\tsetp.ne.u32 p, %4, 0;\n\t"
        "tcgen05.mma.cta_group::1.kind::f16 [%0], [%1], %2, %3, {%5, %5, %5, %5}, p;\n\t}"
        :: "r"(d), "r"(a), "l"(b), "r"(idesc), "r"(en), "r"(0u) : "memory");
}
#define TC_COMMIT(m) asm volatile( \
    "tcgen05.commit.cta_group::1.mbarrier::arrive::one.shared::cluster.b64 [%0];" :: "r"(m) : "memory")
#define TC_COMMIT_MC2(m) asm volatile( \
    "tcgen05.commit.cta_group::2.mbarrier::arrive::one.shared::cluster.multicast::cluster.b64 [%0], %1;" \
    :: "r"(m), "h"((uint16_t)0x3) : "memory")
#define TC_ALLOC(sm, n)  asm volatile("tcgen05.alloc.cta_group::1.sync.aligned.shared::cta.b32 [%0], %1;" :: "r"(sm), "r"(n) : "memory")
#define TC_DEALLOC(t, n) asm volatile("tcgen05.dealloc.cta_group::1.sync.aligned.b32 %0, %1;" :: "r"(t), "r"(n))
#define TC_ALLOC_CG2(sm, n)  asm volatile("tcgen05.alloc.cta_group::2.sync.aligned.shared::cta.b32 [%0], %1;" :: "r"(sm), "r"(n) : "memory")
#define TC_DEALLOC_CG2(t, n) asm volatile("tcgen05.dealloc.cta_group::2.sync.aligned.b32 %0, %1;" :: "r"(t), "r"(n))
#define TC_RELINQ_CG2() asm volatile("tcgen05.relinquish_alloc_permit.cta_group::2.sync.aligned;")
#define TC_FENCE_AFTER() asm volatile("tcgen05.fence::after_thread_sync;" ::: "memory")
#define TC_FENCE_BEFORE() asm volatile("tcgen05.fence::before_thread_sync;" ::: "memory")
#define TC_WAIT_LD()     asm volatile("tcgen05.wait::ld.sync.aligned;" ::: "memory")
#define TC_WAIT_ST()     asm volatile("tcgen05.wait::st.sync.aligned;" ::: "memory")
#define FENCE_ASYNC()    asm volatile("fence.proxy.async.shared::cta;" ::: "memory")

#define TC_LD_X32(r, a) asm volatile( \
    "tcgen05.ld.sync.aligned.32x32b.x32.b32 " \
    "{%0, %1, %2, %3, %4, %5, %6, %7, %8, %9, %10, %11, %12, %13, %14, %15, " \
    "%16, %17, %18, %19, %20, %21, %22, %23, %24, %25, %26, %27, %28, %29, %30, %31}, [%32];" \
    : "=r"((r)[0]), "=r"((r)[1]), "=r"((r)[2]), "=r"((r)[3]), "=r"((r)[4]), "=r"((r)[5]), \
      "=r"((r)[6]), "=r"((r)[7]), "=r"((r)[8]), "=r"((r)[9]), "=r"((r)[10]), "=r"((r)[11]), \
      "=r"((r)[12]), "=r"((r)[13]), "=r"((r)[14]), "=r"((r)[15]), "=r"((r)[16]), "=r"((r)[17]), \
      "=r"((r)[18]), "=r"((r)[19]), "=r"((r)[20]), "=r"((r)[21]), "=r"((r)[22]), "=r"((r)[23]), \
      "=r"((r)[24]), "=r"((r)[25]), "=r"((r)[26]), "=r"((r)[27]), "=r"((r)[28]), "=r"((r)[29]), \
      "=r"((r)[30]), "=r"((r)[31]) : "r"(a))

#define TC_ST_X32(a, r) asm volatile( \
    "tcgen05.st.sync.aligned.32x32b.x32.b32 [%0], " \
    "{%1, %2, %3, %4, %5, %6, %7, %8, %9, %10, %11, %12, %13, %14, %15, %16, " \
    "%17, %18, %19, %20, %21, %22, %23, %24, %25, %26, %27, %28, %29, %30, %31, %32};" \
    :: "r"(a), \
       "r"((r)[0]), "r"((r)[1]), "r"((r)[2]), "r"((r)[3]), "r"((r)[4]), "r"((r)[5]), \
       "r"((r)[6]), "r"((r)[7]), "r"((r)[8]), "r"((r)[9]), "r"((r)[10]), "r"((r)[11]), \
       "r"((r)[12]), "r"((r)[13]), "r"((r)[14]), "r"((r)[15]), "r"((r)[16]), "r"((r)[17]), \
       "r"((r)[18]), "r"((r)[19]), "r"((r)[20]), "r"((r)[21]), "r"((r)[22]), "r"((r)[23]), \
       "r"((r)[24]), "r"((r)[25]), "r"((r)[26]), "r"((r)[27]), "r"((r)[28]), "r"((r)[29]), \
       "r"((r)[30]), "r"((r)[31]) : "memory")
#endif

// ---- Kernel 0: fp32 -> (hi,lo) bf16 ----
__global__ __launch_bounds__(256) void cvt_split(const float* __restrict__ x,
                                                 __nv_bfloat16* __restrict__ hi,
                                                 __nv_bfloat16* __restrict__ lo,
                                                 int n4) {
    int i = blockIdx.x * 256 + threadIdx.x;
    if (i >= n4) return;
    float4 v = ((const float4*)x)[i];
    __nv_bfloat16 h0 = __float2bfloat16(v.x), h1 = __float2bfloat16(v.y);
    __nv_bfloat16 h2 = __float2bfloat16(v.z), h3 = __float2bfloat16(v.w);
    __nv_bfloat16 l0 = __float2bfloat16(v.x - __bfloat162float(h0));
    __nv_bfloat16 l1 = __float2bfloat16(v.y - __bfloat162float(h1));
    __nv_bfloat16 l2 = __float2bfloat16(v.z - __bfloat162float(h2));
    __nv_bfloat16 l3 = __float2bfloat16(v.w - __bfloat162float(h3));
    ((__nv_bfloat162*)hi)[2 * i] = __nv_bfloat162(h0, h1);
    ((__nv_bfloat162*)hi)[2 * i + 1] = __nv_bfloat162(h2, h3);
    ((__nv_bfloat162*)lo)[2 * i] = __nv_bfloat162(l0, l1);
    ((__nv_bfloat162*)lo)[2 * i + 1] = __nv_bfloat162(l2, l3);
}

// ---- Kernel 1: cg2 GEMM + fused norm/rope/split epilogue ----
#define GS_AH 0
#define GS_AL 16384
#define GS_WH 32768
#define GS_WL 49152
#define G_STG 65536
#define SM_BIAS  131072
#define SM_TMEMP 132096
#define SM_MB    132104
#define SM_KF    132120
#define GEMM_SMEM 132352
#define IDESC_CG2  0x10200490u
#define IDESC_BF16 0x8200490u
#define IDESC_FP16 0x8200010u
#define NCH 48

extern __shared__ float smf[];

__global__ __launch_bounds__(256) __cluster_dims__(2, 1, 1)
void qkv_gemm_tc(const float* __restrict__ bias,
                 const float* __restrict__ wq, const float* __restrict__ wk,
                 const float* __restrict__ cs, const float* __restrict__ sn,
                 const int* __restrict__ tsl,
                 const __grid_constant__ CUtensorMap mAh,
                 const __grid_constant__ CUtensorMap mAl,
                 const __grid_constant__ CUtensorMap mWh,
                 const __grid_constant__ CUtensorMap mWl) {
#if HAS_TCGEN05
    char* sm = (char*)smf;
    uint32_t sb = smem_u32(sm);
    int t = threadIdx.x;
    int wid = t >> 5;
    int rank = blockIdx.x & 1;
    int m0 = (blockIdx.x >> 1) * 256 + rank * 128;
    int n0 = blockIdx.y * 256;

    if (wid == 0) TC_ALLOC_CG2(sb + SM_TMEMP, 256);
    if (t == 0) {
        MBAR_INIT(sb + SM_MB + 0, 1);
        MBAR_INIT(sb + SM_MB + 8, 1);
        MBAR_INIT(sb + SM_KF + 0, 1);
        MBAR_INIT(sb + SM_KF + 8, 1);
        FENCE_ASYNC();
        if (rank == 0) {
            MBAR_EXPECT_TX(sb + SM_KF + 0, 131072u);
            MBAR_EXPECT_TX(sb + SM_KF + 8, 131072u);
        }
    }
    ((float*)(sm + SM_BIAS))[t] = bias[n0 + t];
    __syncthreads();
    CLUSTER_SYNC();
    uint32_t tmem;
    asm volatile("ld.shared.b32 %0, [%1];" : "=r"(tmem) : "r"(sb + SM_TMEMP));

    if (t == 0) {
#pragma unroll
        for (int c = 0; c < 2; c++) {   // prologue: chunks 0,1
            uint32_t stg = sb + c * G_STG, kfb = sb + SM_KF + c * 8;
            int k0 = c * 64;
            TMA_2D_CG2(stg + GS_AH, &mAh, k0, m0, kfb);
            TMA_2D_CG2(stg + GS_AL, &mAl, k0, m0, kfb);
            TMA_2D_CG2(stg + GS_WH,        &mWh, k0, n0 + rank * 64, kfb);
            TMA_2D_CG2(stg + GS_WH + 8192, &mWh, k0, n0 + 128 + rank * 64, kfb);
            TMA_2D_CG2(stg + GS_WL,        &mWl, k0, n0 + rank * 64, kfb);
            TMA_2D_CG2(stg + GS_WL + 8192, &mWl, k0, n0 + 128 + rank * 64, kfb);
        }
        const int ca[3] = {0, 0, 1}, cw[3] = {0, 1, 0};
        for (int i = 0; i < NCH; i++) {
            int s = i & 1;
            if (rank == 0) {
                MBAR_WAIT(sb + SM_KF + s * 8, (i >> 1) & 1);
                if (i + 2 < NCH) MBAR_EXPECT_TX(sb + SM_KF + s * 8, 131072u);
                uint32_t stg = sb + s * G_STG;
                uint64_t dA[2]  = {MK_DESC(stg + GS_AH), MK_DESC(stg + GS_AL)};
                uint64_t dWh[2] = {MK_DESC(stg + GS_WH), MK_DESC(stg + GS_WH + 8192)};
                uint64_t dWl[2] = {MK_DESC(stg + GS_WL), MK_DESC(stg + GS_WL + 8192)};
#pragma unroll
                for (int c3 = 0; c3 < 3; c3++)
#pragma unroll
                    for (int nh = 0; nh < 2; nh++) {
                        uint64_t bb = cw[c3] ? dWl[nh] : dWh[nh];
#pragma unroll
                        for (int ks = 0; ks < 4; ks++) {
                            uint32_t en = (i | c3 | ks) ? 1u : 0u;
                            mma_ss_cg2(tmem + nh * 128, dA[ca[c3]] + ks * 2,
                                       bb + ks * 2, IDESC_CG2, en);
                        }
                    }
                TC_COMMIT_MC2(sb + SM_MB + s * 8);
            }
            if (i >= 1 && i + 1 < NCH) {
                int s2 = (i + 1) & 1;
                MBAR_WAIT(sb + SM_MB + s2 * 8, ((i - 1) >> 1) & 1);
                uint32_t stg = sb + s2 * G_STG, kfb = sb + SM_KF + s2 * 8;
                int k0 = (i + 1) * 64;
                TMA_2D_CG2(stg + GS_AH, &mAh, k0, m0, kfb);
                TMA_2D_CG2(stg + GS_AL, &mAl, k0, m0, kfb);
                TMA_2D_CG2(stg + GS_WH,        &mWh, k0, n0 + rank * 64, kfb);
                TMA_2D_CG2(stg + GS_WH + 8192, &mWh, k0, n0 + 128 + rank * 64, kfb);
                TMA_2D_CG2(stg + GS_WL,        &mWl, k0, n0 + rank * 64, kfb);
                TMA_2D_CG2(stg + GS_WL + 8192, &mWl, k0, n0 + 128 + rank * 64, kfb);
            }
        }
        MBAR_WAIT(sb + SM_MB + 0, 1);
        MBAR_WAIT(sb + SM_MB + 8, 1);
    }
    __syncthreads();
    TC_FENCE_AFTER();

    // fused epilogue: thread = (row r=t&127, head hc=t>>7)
    {
        int r = t & 127, hc = t >> 7;
        int m = m0 + r;
        int b = m / Ss, s2 = m % Ss;
        int sec = n0 / DM;
        int h0 = (n0 % DM) / HD;
        uint32_t tw = tmem + ((uint32_t)(wid & 3) << 21);
        uint32_t cbase = tw + hc * 128;
        const float* bs = (const float*)(sm + SM_BIAS) + hc * 128;
        size_t obase = ((size_t)(b * Hh + h0 + hc) * Ss + s2) * (size_t)HD;

        if (sec == 2) {
            __half* dv = g_vh + obase;
#pragma unroll
            for (int cb = 0; cb < 4; cb++) {
                uint32_t rg[32];
                TC_LD_X32(rg, cbase + cb * 32);
                TC_WAIT_LD();
                __half hb[32];
#pragma unroll
                for (int j = 0; j < 32; j += 2) {
                    float a0 = __uint_as_float(rg[j]) + bs[cb * 32 + j];
                    float a1 = __uint_as_float(rg[j + 1]) + bs[cb * 32 + j + 1];
                    *(__half2*)(hb + j) = __float22half2_rn(make_float2(a0, a1));
                }
#pragma unroll
                for (int q4 = 0; q4 < 4; q4++)
                    *(uint4*)(dv + cb * 32 + q4 * 8) = *(uint4*)(hb + q4 * 8);
            }
        } else {
            const float* wn = (sec == 0) ? wq : wk;
            float ssq = 0.0f;
#pragma unroll
            for (int cb = 0; cb < 4; cb++) {
                uint32_t rg[32];
                TC_LD_X32(rg, cbase + cb * 32);
                TC_WAIT_LD();
#pragma unroll
                for (int j = 0; j < 32; j++) {
                    float a = __uint_as_float(rg[j]) + bs[cb * 32 + j];
                    ssq += a * a;
                }
            }
            float rms = rsqrtf(ssq * (1.0f / 128.0f) + 1e-6f);
            int T = tsl[0];
            bool rope = (s2 >= T);
            int p = s2 - T;
            float qscale = (sec == 0) ? 0.08838834764831845f : 1.0f;
            __nv_bfloat16* dh = ((sec == 0) ? g_qh : g_kh) + obase;
            __nv_bfloat16* dl = ((sec == 0) ? g_ql : g_kl) + obase;
#pragma unroll
            for (int cb = 0; cb < 4; cb++) {
                uint32_t rg[32];
                TC_LD_X32(rg, cbase + cb * 32);
                TC_WAIT_LD();
                float y[32];
#pragma unroll
                for (int j = 0; j < 32; j++)
                    y[j] = (__uint_as_float(rg[j]) + bs[cb * 32 + j]) * rms * wn[cb * 32 + j];
                if (rope) {
#pragma unroll
                    for (int jj = 0; jj < 16; jj++) {
                        float c = cs[p * 64 + cb * 16 + jj], sv = sn[p * 64 + cb * 16 + jj];
                        float x1 = y[2 * jj], x2 = y[2 * jj + 1];
                        y[2 * jj] = x1 * c - x2 * sv;
                        y[2 * jj + 1] = x2 * c + x1 * sv;
                    }
                }
                __nv_bfloat16 hb[32], lb[32];
#pragma unroll
                for (int j = 0; j < 32; j++) {
                    float v = y[j] * qscale;
                    __nv_bfloat16 hv = __float2bfloat16(v);
                    hb[j] = hv;
                    lb[j] = __float2bfloat16(v - __bfloat162float(hv));
                }
#pragma unroll
                for (int q4 = 0; q4 < 4; q4++) {
                    *(uint4*)(dh + cb * 32 + q4 * 8) = *(uint4*)(hb + q4 * 8);
                    *(uint4*)(dl + cb * 32 + q4 * 8) = *(uint4*)(lb + q4 * 8);
                }
            }
        }
    }
    __syncthreads();
    if (wid == 0) { TC_RELINQ_CG2(); TC_DEALLOC_CG2(tmem, 256); }
    CLUSTER_SYNC();
#endif
}

// ---- Kernel 2b: V transpose ----
__global__ __launch_bounds__(256) void v_transpose() {
    __shared__ __half ts[128 * 129];
    int t = threadIdx.x;
    int s0 = blockIdx.x * 128;
    int bh = blockIdx.y;
    const __half* src = g_vh + ((size_t)bh * Ss + s0) * HD;
#pragma unroll
    for (int i = 0; i < 8; i++) {
        int idx = t + i * 256;
        int s = idx >> 4, c8 = idx & 15;
        uint4 v = *(const uint4*)(src + s * HD + c8 * 8);
        __half tmp[8];
        *(uint4*)tmp = v;
#pragma unroll
        for (int j = 0; j < 8; j++) ts[s * 129 + c8 * 8 + j] = tmp[j];
    }
    __syncthreads();
    __half* dst = g_vt + (size_t)bh * HD * Ss;
#pragma unroll
    for (int i = 0; i < 8; i++) {
        int idx = t + i * 256;
        int d = idx >> 4, s8 = idx & 15;
        __half o[8];
#pragma unroll
        for (int j = 0; j < 8; j++) o[j] = ts[(s8 * 8 + j) * 129 + d];
        *(uint4*)(dst + (size_t)d * Ss + s0 + s8 * 8) = *(uint4*)o;
    }
}

// ---- Kernel 3: attention (unchanged from R7) ----
#define A_STG 98304
#define AS_KH 0
#define AS_KL 32768
#define AS_V  65536
#define A_SMAX 196608
#define A_SSUM 197632
#define A_PTR  198656
#define A_MBS  198664
#define A_MBO  198672
#define A_KF   198680
#define ATT_SMEM 198784
#define NT 18
#define TO_O  0
#define TO_S  128
#define TO_P  256
#define TO_QH 320
#define TO_QL 384

__device__ __forceinline__ uint32_t dstep(int ks) {
    return (uint32_t)((ks >> 2) * 1024 + (ks & 3) * 2);
}

__global__ __launch_bounds__(256, 1) void attn(
        float* __restrict__ out,
        const __grid_constant__ CUtensorMap mKh,
        const __grid_constant__ CUtensorMap mKl,
        const __grid_constant__ CUtensorMap mVt) {
#if HAS_TCGEN05
    char* sm = (char*)smf;
    uint32_t sb = smem_u32(sm);
    int t = threadIdx.x;
    int wid = t >> 5;
    int row = t & 127;
    int half = t >> 7;
    int q0 = blockIdx.x * 128;
    int h = blockIdx.y, b = blockIdx.z;
    int bh = b * Hh + h;

    if (wid == 0) TC_ALLOC(sb + A_PTR, 512);
    if (t == 0) {
        MBAR_INIT(sb + A_MBS, 1);
        MBAR_INIT(sb + A_MBO, 1);
        MBAR_INIT(sb + A_KF + 0, 1);
        MBAR_INIT(sb + A_KF + 8, 1);
        FENCE_ASYNC();
        MBAR_EXPECT_TX(sb + A_KF, 98304u);
        TMA_3D(sb + AS_KH,         &mKh, 0,  0, bh, sb + A_KF);
        TMA_3D(sb + AS_KH + 16384, &mKh, 64, 0, bh, sb + A_KF);
        TMA_3D(sb + AS_KL,         &mKl, 0,  0, bh, sb + A_KF);
        TMA_3D(sb + AS_KL + 16384, &mKl, 64, 0, bh, sb + A_KF);
        TMA_3D(sb + AS_V,          &mVt, 0,  0, bh, sb + A_KF);
        TMA_3D(sb + AS_V + 16384,  &mVt, 64, 0, bh, sb + A_KF);
    }
    __syncthreads();
    uint32_t tmem;
    asm volatile("ld.shared.b32 %0, [%1];" : "=r"(tmem) : "r"(sb + A_PTR));
    uint32_t tw = tmem + ((uint32_t)(wid & 3) << 21);

    {
        const uint32_t* qsrc = (const uint32_t*)((half == 0 ? g_qh : g_ql) +
                                ((size_t)bh * Ss + q0 + row) * HD);
        uint32_t dstc = (half == 0) ? (tw + TO_QH) : (tw + TO_QL);
        uint32_t rg[32];
#pragma unroll
        for (int hb = 0; hb < 2; hb++) {
#pragma unroll
            for (int j = 0; j < 32; j++) rg[j] = qsrc[hb * 32 + j];
            TC_ST_X32(dstc + hb * 32, rg);
        }
        TC_WAIT_ST();
    }
    TC_FENCE_BEFORE();
    __syncthreads();

    float m = -1e30f, l = 0.0f;

    for (int iter = 0; iter < NT; iter++) {
        int s = iter & 1;
        uint32_t stg = sb + s * A_STG;

        if (t == 0) {
            TC_FENCE_AFTER();
            MBAR_WAIT(sb + A_KF + s * 8, (iter >> 1) & 1);
            uint64_t dKh = MK_DESC(stg + AS_KH);
            uint64_t dKl = MK_DESC(stg + AS_KL);
#pragma unroll
            for (int ks = 0; ks < 8; ks++)
                mma_ts(tmem + TO_S, tmem + TO_QH + ks * 8, dKh + dstep(ks), IDESC_BF16, ks > 0);
#pragma unroll
            for (int ks = 0; ks < 8; ks++)
                mma_ts(tmem + TO_S, tmem + TO_QH + ks * 8, dKl + dstep(ks), IDESC_BF16, 1);
#pragma unroll
            for (int ks = 0; ks < 8; ks++)
                mma_ts(tmem + TO_S, tmem + TO_QL + ks * 8, dKh + dstep(ks), IDESC_BF16, 1);
            TC_COMMIT(sb + A_MBS);
        }

        if (iter > 0) MBAR_WAIT(sb + A_MBO, (iter - 1) & 1);

        if (t == 0 && iter + 1 < NT) {
            int s2 = (iter + 1) & 1;
            uint32_t st2 = sb + s2 * A_STG;
            int kt = (iter + 1) * 128;
            MBAR_EXPECT_TX(sb + A_KF + s2 * 8, 98304u);
            TMA_3D(st2 + AS_KH,         &mKh, 0,  kt, bh, sb + A_KF + s2 * 8);
            TMA_3D(st2 + AS_KH + 16384, &mKh, 64, kt, bh, sb + A_KF + s2 * 8);
            TMA_3D(st2 + AS_KL,         &mKl, 0,  kt, bh, sb + A_KF + s2 * 8);
            TMA_3D(st2 + AS_KL + 16384, &mKl, 64, kt, bh, sb + A_KF + s2 * 8);
            TMA_3D(st2 + AS_V,          &mVt, kt,      0, bh, sb + A_KF + s2 * 8);
            TMA_3D(st2 + AS_V + 16384,  &mVt, kt + 64, 0, bh, sb + A_KF + s2 * 8);
        }

        {
            MBAR_WAIT(sb + A_MBS, iter & 1);
            TC_FENCE_AFTER();
            float sc[64];
            uint32_t* scu = (uint32_t*)sc;
            uint32_t scol = tw + TO_S + half * 64;
            TC_LD_X32(scu + 0,  scol + 0);
            TC_LD_X32(scu + 32, scol + 32);
            TC_WAIT_LD();
            float pmax = sc[0];
#pragma unroll
            for (int c = 1; c < 64; c++) pmax = fmaxf(pmax, sc[c]);
            ((float*)(sm + A_SMAX))[t] = pmax;
            __syncthreads();
            float omax = ((float*)(sm + A_SMAX))[t ^ 128];
            float mnew = fmaxf(m, fmaxf(pmax, omax));
            float alpha = __expf(m - mnew);
            m = mnew;
            float psum = 0.0f;
            uint32_t pr[32];
#pragma unroll
            for (int c = 0; c < 32; c++) {
                float p0 = __expf(sc[2 * c] - mnew);
                float p1 = __expf(sc[2 * c + 1] - mnew);
                psum += p0 + p1;
                pr[c] = h2_as_u32(__float22half2_rn(make_float2(p0, p1)));
            }
            ((float*)(sm + A_SSUM))[t] = psum;
            TC_ST_X32(tw + TO_P + half * 32, pr);
            if (iter > 0 && __any_sync(0xffffffffu, alpha != 1.0f)) {
#pragma unroll
                for (int cb = 0; cb < 2; cb++) {
                    uint32_t og[32];
                    TC_LD_X32(og, tw + TO_O + half * 64 + cb * 32);
                    TC_WAIT_LD();
                    float* of = (float*)og;
#pragma unroll
                    for (int j = 0; j < 32; j++) of[j] *= alpha;
                    TC_ST_X32(tw + TO_O + half * 64 + cb * 32, og);
                }
            }
            TC_WAIT_ST();
            TC_FENCE_BEFORE();
            __syncthreads();
            l = l * alpha + psum + ((float*)(sm + A_SSUM))[t ^ 128];
        }

        if (t == 0) {
            TC_FENCE_AFTER();
            uint64_t dV = MK_DESC(stg + AS_V);
#pragma unroll
            for (int ks = 0; ks < 8; ks++)
                mma_ts(tmem + TO_O, tmem + TO_P + ks * 8, dV + dstep(ks), IDESC_FP16,
                       (iter > 0) || (ks > 0));
            TC_COMMIT(sb + A_MBO);
        }
    }

    MBAR_WAIT(sb + A_MBO, (NT - 1) & 1);
    TC_FENCE_AFTER();
    {
        float inv = 1.0f / l;
        float* dst = out + ((size_t)b * Ss + q0 + row) * DM + h * HD + half * 64;
#pragma unroll
        for (int cb = 0; cb < 2; cb++) {
            uint32_t og[32];
            TC_LD_X32(og, tw + TO_O + half * 64 + cb * 32);
            TC_WAIT_LD();
            float* of = (float*)og;
#pragma unroll
            for (int j = 0; j < 32; j += 4) {
                float4 o = make_float4(of[j] * inv, of[j + 1] * inv,
                                       of[j + 2] * inv, of[j + 3] * inv);
                *(float4*)(dst + cb * 32 + j) = o;
            }
        }
    }
    __syncthreads();
    if (wid == 0) TC_DEALLOC(tmem, 512);
#endif
}

// ---- Host ----
typedef CUresult (*PFN_encodeTiled)(CUtensorMap*, CUtensorMapDataType, cuuint32_t,
                                    void*, const cuuint64_t*, const cuuint64_t*,
                                    const cuuint32_t*, const cuuint32_t*,
                                    CUtensorMapInterleave, CUtensorMapSwizzle,
                                    CUtensorMapL2promotion, CUtensorMapFloatOOBfill);
static PFN_encodeTiled get_encoder() {
    static PFN_encodeTiled fn = nullptr;
    if (!fn) {
        cudaDriverEntryPointQueryResult qr;
        cudaGetDriverEntryPointByVersion("cuTensorMapEncodeTiled", (void**)&fn,
                                         12000, cudaEnableDefault, &qr);
    }
    return fn;
}
static void enc(CUtensorMap* m, void* base, int nd, uint64_t d0, uint64_t d1, uint64_t d2,
                uint32_t b0, uint32_t b1, CUtensorMapDataType dt) {
    cuuint64_t dims[3] = {d0, d1, d2};
    cuuint64_t strides[2] = {d0 * 2, d0 * d1 * 2};
    cuuint32_t box[3] = {b0, b1, 1};
    cuuint32_t es[3] = {1, 1, 1};
    get_encoder()(m, dt, nd, base, dims, strides, box, es,
                  CU_TENSOR_MAP_INTERLEAVE_NONE, CU_TENSOR_MAP_SWIZZLE_128B,
                  CU_TENSOR_MAP_L2_PROMOTION_L2_128B, CU_TENSOR_MAP_FLOAT_OOB_FILL_NONE);
}

extern "C" void kernel_launch(void* const* d_in, const int* in_sizes, int n_in,
                              void* d_out, int out_size) {
    const float* hs  = (const float*)d_in[0];
    const float* w   = (const float*)d_in[1];
    const float* bqv = (const float*)d_in[2];
    const float* wqn = (const float*)d_in[3];
    const float* wkn = (const float*)d_in[4];
    const float* cs  = (const float*)d_in[5];
    const float* sn  = (const float*)d_in[6];
    const int*   tsl = (const int*)d_in[7];
    float* out = (float*)d_out;

    __nv_bfloat16 *ah, *al, *wh, *wl, *kh, *kl;
    __half *vt;
    cudaGetSymbolAddress((void**)&ah, g_Ah);
    cudaGetSymbolAddress((void**)&al, g_Al);
    cudaGetSymbolAddress((void**)&wh, g_Wh);
    cudaGetSymbolAddress((void**)&wl, g_Wl);
    cudaGetSymbolAddress((void**)&kh, g_kh);
    cudaGetSymbolAddress((void**)&kl, g_kl);
    cudaGetSymbolAddress((void**)&vt, g_vt);

    CUtensorMap mAh, mAl, mWh, mWl, mKh, mKl, mVt;
    enc(&mAh, ah, 2, KD, MR, 1, 64, 128, CU_TENSOR_MAP_DATA_TYPE_BFLOAT16);
    enc(&mAl, al, 2, KD, MR, 1, 64, 128, CU_TENSOR_MAP_DATA_TYPE_BFLOAT16);
    enc(&mWh, wh, 2, KD, N3, 1, 64, 64, CU_TENSOR_MAP_DATA_TYPE_BFLOAT16);
    enc(&mWl, wl, 2, KD, N3, 1, 64, 64, CU_TENSOR_MAP_DATA_TYPE_BFLOAT16);
    enc(&mKh, kh, 3, HD, Ss, Bb * Hh, 64, 128, CU_TENSOR_MAP_DATA_TYPE_BFLOAT16);
    enc(&mKl, kl, 3, HD, Ss, Bb * Hh, 64, 128, CU_TENSOR_MAP_DATA_TYPE_BFLOAT16);
    enc(&mVt, vt, 3, Ss, HD, Bb * Hh, 64, 128, CU_TENSOR_MAP_DATA_TYPE_FLOAT16);

    int na4 = MR * KD / 4;
    int nw4 = N3 * KD / 4;
    cvt_split<<<(na4 + 255) / 256, 256>>>(hs, ah, al, na4);
    cvt_split<<<(nw4 + 255) / 256, 256>>>(w, wh, wl, nw4);

    cudaFuncSetAttribute(qkv_gemm_tc, cudaFuncAttributeMaxDynamicSharedMemorySize, GEMM_SMEM);
    qkv_gemm_tc<<<dim3(MR / 128, N3 / 256), 256, GEMM_SMEM>>>(bqv, wqn, wkn, cs, sn, tsl,
                                                              mAh, mAl, mWh, mWl);

    v_transpose<<<dim3(Ss / 128, Bb * Hh), 256>>>();

    cudaFuncSetAttribute(attn, cudaFuncAttributeMaxDynamicSharedMemorySize, ATT_SMEM);
    attn<<<dim3(Ss / 128, Hh, Bb), 256, ATT_SMEM>>>(out, mKh, mKl, mVt);
}